// round 10
// baseline (speedup 1.0000x reference)
#include <cuda_runtime.h>
#include <cuda_bf16.h>
#include <mma.h>
#include <math.h>
#include <stdint.h>

using namespace nvcuda;

// Problem constants: B=8, N=256, T=128, D=256, H=8, hd=32, TOPK=32
#define BATCH 8
#define NN    256
#define TT    128
#define DD    256
#define HH    8
#define HD    32
#define TOPK  32

#define BN    (BATCH*NN)            // 2048
#define M_BIG ((size_t)BATCH*NN*TT) // 262144

// Scratch (accessed ONLY from device code — never passed as kernel args)
__device__ float g_q[BN*DD];
__device__ float g_k[BN*DD];
__device__ float g_wt[2*DD*DD];                        // transposed Wq,Wk (qk gemm)
// bf16 hi/lo plane world:
__device__ __nv_bfloat16 g_w_h[2*DD*DD];               // Wv, Wo  [w][n][k]
__device__ __nv_bfloat16 g_w_l[2*DD*DD];
__device__ __nv_bfloat16 g_hv_h[M_BIG*DD];             // h_val   [m][k]
__device__ __nv_bfloat16 g_hv_l[M_BIG*DD];
__device__ __nv_bfloat16 g_attn_h[(size_t)BATCH*HH*NN*NN];
__device__ __nv_bfloat16 g_attn_l[(size_t)BATCH*HH*NN*NN];
__device__ __nv_bfloat16 g_v_h[M_BIG*DD];              // v       [b,j,t,d]
__device__ __nv_bfloat16 g_v_l[M_BIG*DD];
__device__ __nv_bfloat16 g_mix_h[M_BIG*DD];            // mixed   [m][k]
__device__ __nv_bfloat16 g_mix_l[M_BIG*DD];

typedef wmma::fragment<wmma::matrix_a, 16, 16, 16, __nv_bfloat16, wmma::row_major> FragA;
typedef wmma::fragment<wmma::matrix_b, 16, 16, 16, __nv_bfloat16, wmma::col_major> FragBc;
typedef wmma::fragment<wmma::matrix_b, 16, 16, 16, __nv_bfloat16, wmma::row_major> FragBr;
typedef wmma::fragment<wmma::accumulator, 16, 16, 16, float> FragC;

// ---------------------------------------------------------------------------
// helpers
// ---------------------------------------------------------------------------
__device__ __forceinline__ void cp16(void* dst, const void* src) {
    unsigned d = (unsigned)__cvta_generic_to_shared(dst);
    asm volatile("cp.async.cg.shared.global [%0], [%1], 16;\n" :: "r"(d), "l"(src));
}
__device__ __forceinline__ void cp_commit() { asm volatile("cp.async.commit_group;\n"); }
__device__ __forceinline__ void cp_wait1()  { asm volatile("cp.async.wait_group 1;\n"); }
__device__ __forceinline__ void cp_wait0()  { asm volatile("cp.async.wait_group 0;\n"); }

// split float4 into hi/lo bf16x2 pairs; store as two __nv_bfloat162 per plane
__device__ __forceinline__ void split_store_bf162(__nv_bfloat16* hp, __nv_bfloat16* lp,
                                                  float4 v) {
    __nv_bfloat16 h0 = __float2bfloat16_rn(v.x);
    __nv_bfloat16 h1 = __float2bfloat16_rn(v.y);
    __nv_bfloat16 h2 = __float2bfloat16_rn(v.z);
    __nv_bfloat16 h3 = __float2bfloat16_rn(v.w);
    __nv_bfloat162 ha; ha.x = h0; ha.y = h1;
    __nv_bfloat162 hb; hb.x = h2; hb.y = h3;
    *(__nv_bfloat162*)(hp)     = ha;
    *(__nv_bfloat162*)(hp + 2) = hb;
    __nv_bfloat162 la, lb;
    la.x = __float2bfloat16_rn(v.x - __bfloat162float(h0));
    la.y = __float2bfloat16_rn(v.y - __bfloat162float(h1));
    lb.x = __float2bfloat16_rn(v.z - __bfloat162float(h2));
    lb.y = __float2bfloat16_rn(v.w - __bfloat162float(h3));
    *(__nv_bfloat162*)(lp)     = la;
    *(__nv_bfloat162*)(lp + 2) = lb;
}

// ---------------------------------------------------------------------------
// K0a: transpose Wq, Wk -> g_wt.  grid (8,8,2), block (32,8)
// ---------------------------------------------------------------------------
__global__ void transpose_w_kernel(const float* __restrict__ Wq, const float* __restrict__ Wk) {
    __shared__ float t[32][33];
    const int w = blockIdx.z;
    const float* W = (w == 0) ? Wq : Wk;
    float* out = g_wt + (size_t)w * DD * DD;
    const int n0 = blockIdx.x * 32, k0 = blockIdx.y * 32;
    const int tx = threadIdx.x, ty = threadIdx.y;
#pragma unroll
    for (int i = 0; i < 4; i++)
        t[ty + 8*i][tx] = W[(size_t)(n0 + ty + 8*i)*DD + k0 + tx];
    __syncthreads();
#pragma unroll
    for (int i = 0; i < 4; i++)
        out[(size_t)(k0 + ty + 8*i)*DD + n0 + tx] = t[tx][ty + 8*i];
}

// K0b: Wv, Wo -> bf16 hi/lo planes.  grid (64, 2) x 256
__global__ void convert_w_kernel(const float* __restrict__ Wv, const float* __restrict__ Wo) {
    const int w = blockIdx.y;
    const float* W = w ? Wo : Wv;
    size_t f = ((size_t)blockIdx.x*256 + threadIdx.x) * 4;   // element index
    float4 v = *(const float4*)(W + f);
    split_store_bf162(g_w_h + (size_t)w*DD*DD + f, g_w_l + (size_t)w*DD*DD + f, v);
}

// K0c: h_val -> bf16 hi/lo planes.  grid 65536 x 256
__global__ void convert_hval_kernel(const float* __restrict__ hv) {
    size_t f = ((size_t)blockIdx.x*256 + threadIdx.x) * 4;
    float4 v = *(const float4*)(hv + f);
    split_store_bf162(g_hv_h + f, g_hv_l + f, v);
}

// ---------------------------------------------------------------------------
// SIMT GEMM macros (qk only)
// ---------------------------------------------------------------------------
#define GEMM_DECL \
    __shared__ float As[2][16][68];  \
    __shared__ float Bs[2][16][260]; \
    const int tid = threadIdx.x;     \
    const int tx = tid & 31, ty = tid >> 5; \
    const int ar = tid >> 2;         \
    const int ak = (tid & 3) << 2;   \
    float acc[8][8];                 \
    _Pragma("unroll") for (int r = 0; r < 8; r++) \
    _Pragma("unroll") for (int c = 0; c < 8; c++) acc[r][c] = 0.f;

#define GEMM_COMPUTE(buf) \
    _Pragma("unroll") \
    for (int kk = 0; kk < 16; kk++) { \
        float a[8], bb[8]; \
        *(float4*)&a[0]  = *(const float4*)&As[buf][kk][ty*8]; \
        *(float4*)&a[4]  = *(const float4*)&As[buf][kk][ty*8 + 4]; \
        *(float4*)&bb[0] = *(const float4*)&Bs[buf][kk][tx*8]; \
        *(float4*)&bb[4] = *(const float4*)&Bs[buf][kk][tx*8 + 4]; \
        _Pragma("unroll") for (int r = 0; r < 8; r++) \
        _Pragma("unroll") for (int c = 0; c < 8; c++) acc[r][c] += a[r]*bb[c]; \
    }

// ---------------------------------------------------------------------------
// K1: q/k projection GEMM.  grid (32, 2): y=0 -> q, y=1 -> k
// ---------------------------------------------------------------------------
__global__ void __launch_bounds__(256) gemm_qk_kernel(const float* __restrict__ Z) {
    GEMM_DECL
    const int wsel = blockIdx.y;
    const float* WT = g_wt + (size_t)wsel * DD * DD;
    float* out = wsel ? g_k : g_q;
    const size_t m0 = (size_t)blockIdx.x * 64;

#pragma unroll
    for (int u = 0; u < 4; u++) {
        int f = tid + u*256; int jj = f >> 6; int cc = (f & 63) << 2;
        cp16(&Bs[0][jj][cc], WT + (size_t)jj*DD + cc);
    }
    cp_commit();
    float4 av = *(const float4*)(Z + (m0 + ar)*DD + ak);
    As[0][ak+0][ar] = av.x; As[0][ak+1][ar] = av.y;
    As[0][ak+2][ar] = av.z; As[0][ak+3][ar] = av.w;

    for (int k = 0; k < 16; k++) {
        const int cur = k & 1;
        if (k < 15) {
            av = *(const float4*)(Z + (m0 + ar)*DD + (k+1)*16 + ak);
#pragma unroll
            for (int u = 0; u < 4; u++) {
                int f = tid + u*256; int jj = f >> 6; int cc = (f & 63) << 2;
                cp16(&Bs[cur^1][jj][cc], WT + (size_t)((k+1)*16 + jj)*DD + cc);
            }
            cp_commit(); cp_wait1();
        } else cp_wait0();
        __syncthreads();
        GEMM_COMPUTE(cur)
        __syncthreads();
        if (k < 15) {
            As[cur^1][ak+0][ar] = av.x; As[cur^1][ak+1][ar] = av.y;
            As[cur^1][ak+2][ar] = av.z; As[cur^1][ak+3][ar] = av.w;
        }
    }
#pragma unroll
    for (int r = 0; r < 8; r++) {
        size_t row = m0 + ty*8 + r;
#pragma unroll
        for (int c = 0; c < 8; c += 4) {
            float4 o = make_float4(acc[r][c], acc[r][c+1], acc[r][c+2], acc[r][c+3]);
            *(float4*)(out + row*DD + tx*8 + c) = o;
        }
    }
}

// ---------------------------------------------------------------------------
// K2: attention — warp h handles head h of row (b,i). Emits bf16 hi/lo planes.
// ---------------------------------------------------------------------------
#define SWAP_DESC(a, b) { float _hi = fmaxf(a, b); b = fminf(a, b); a = _hi; }

__global__ void __launch_bounds__(256) attn_kernel(const float* __restrict__ adj,
                                                   float* __restrict__ out_attn_mean,
                                                   float* __restrict__ out_raw_mean) {
    extern __shared__ float sm[];
    float* kss   = sm;
    float* logbs = kss + 64*257;
    float* qsh   = logbs + 256;
    float* asum  = qsh + 256;
    float* rsum  = asum + 8*256;

    const int bi = blockIdx.x, b = bi >> 8, i = bi & 255;
    const int tid = threadIdx.x, lane = tid & 31, h = tid >> 5;
    const float scale = 0.17677669529663687f;

    logbs[tid] = logf(fmaxf(adj[(size_t)bi*NN + tid], 1e-12f));
    qsh[tid]   = g_q[(size_t)bi*DD + tid];
    __syncthreads();

    float qreg[32];
#pragma unroll
    for (int e = 0; e < 32; e++) qreg[e] = qsh[h*HD + e];

    float sreg[8];
    for (int jt = 0; jt < 4; jt++) {
        if (jt) __syncthreads();
        const float* ksrc = g_k + ((size_t)(b*NN) + jt*64) * DD;
#pragma unroll
        for (int u = 0; u < 16; u++) {
            int f = tid + u*256;
            int r = f >> 6, c = (f & 63) << 2;
            float4 kv = *(const float4*)(ksrc + (size_t)f*4);
            kss[r*257 + c + 0] = kv.x; kss[r*257 + c + 1] = kv.y;
            kss[r*257 + c + 2] = kv.z; kss[r*257 + c + 3] = kv.w;
        }
        __syncthreads();
#pragma unroll
        for (int g = 0; g < 2; g++) {
            int jl = g*32 + lane;
            const float* kp = &kss[jl*257 + h*HD];
            float s = 0.f;
#pragma unroll
            for (int e = 0; e < 32; e++) s += qreg[e] * kp[e];
            sreg[jt*2 + g] = s * scale + logbs[jt*64 + jl];
        }
    }

    float m = sreg[0];
#pragma unroll
    for (int x = 1; x < 8; x++) m = fmaxf(m, sreg[x]);
#pragma unroll
    for (int o = 16; o; o >>= 1) m = fmaxf(m, __shfl_xor_sync(0xffffffffu, m, o));
    float preg[8], tsum = 0.f;
#pragma unroll
    for (int x = 0; x < 8; x++) { preg[x] = expf(sreg[x] - m); tsum += preg[x]; }
#pragma unroll
    for (int o = 16; o; o >>= 1) tsum += __shfl_xor_sync(0xffffffffu, tsum, o);

    float v0 = sreg[0], v1 = sreg[1], v2 = sreg[2], v3 = sreg[3];
    float v4 = sreg[4], v5 = sreg[5], v6 = sreg[6], v7 = sreg[7];
    SWAP_DESC(v0,v1) SWAP_DESC(v2,v3) SWAP_DESC(v4,v5) SWAP_DESC(v6,v7)
    SWAP_DESC(v0,v2) SWAP_DESC(v1,v3) SWAP_DESC(v4,v6) SWAP_DESC(v5,v7)
    SWAP_DESC(v1,v2) SWAP_DESC(v5,v6)
    SWAP_DESC(v0,v4) SWAP_DESC(v1,v5) SWAP_DESC(v2,v6) SWAP_DESC(v3,v7)
    SWAP_DESC(v2,v4) SWAP_DESC(v3,v5)
    SWAP_DESC(v1,v2) SWAP_DESC(v3,v4) SWAP_DESC(v5,v6)

    float kth = 0.f;
#pragma unroll 1
    for (int it = 0; it < TOPK; it++) {
        float mm = v0;
#pragma unroll
        for (int o = 16; o; o >>= 1) mm = fmaxf(mm, __shfl_xor_sync(0xffffffffu, mm, o));
        if (it == TOPK-1) { kth = mm; break; }
        unsigned bal = __ballot_sync(0xffffffffu, v0 == mm);
        if (lane == (__ffs(bal) - 1)) {
            v0 = v1; v1 = v2; v2 = v3; v3 = v4; v4 = v5; v5 = v6; v6 = v7;
            v7 = -3.402823466e38f;
        }
    }

    float pa[8], ts2 = 0.f;
#pragma unroll
    for (int x = 0; x < 8; x++) { pa[x] = (sreg[x] >= kth) ? preg[x] : 0.f; ts2 += pa[x]; }
#pragma unroll
    for (int o = 16; o; o >>= 1) ts2 += __shfl_xor_sync(0xffffffffu, ts2, o);

    const float inv2 = 1.f / ts2, inv1 = 1.f / tsum;
    const size_t arow = ((size_t)(b*HH + h)*NN + i)*NN;
#pragma unroll
    for (int x = 0; x < 8; x++) {
        int j = (x >> 1)*64 + (x & 1)*32 + lane;
        float a = pa[x] * inv2;
        __nv_bfloat16 ah = __float2bfloat16_rn(a);
        g_attn_h[arow + j] = ah;
        g_attn_l[arow + j] = __float2bfloat16_rn(a - __bfloat162float(ah));
        asum[h*256 + j] = a;
        rsum[h*256 + j] = preg[x] * inv1;
    }
    __syncthreads();
    float sa = 0.f, sr = 0.f;
#pragma unroll
    for (int hh = 0; hh < 8; hh++) { sa += asum[hh*256 + tid]; sr += rsum[hh*256 + tid]; }
    out_attn_mean[(size_t)bi*NN + tid] = sa * 0.125f;
    out_raw_mean[(size_t)bi*NN + tid]  = sr * 0.125f;
}

// ---------------------------------------------------------------------------
// K3/K5: pure-bf16 WMMA GEMM vs weights (cp.async planes, no in-loop convert).
// mode 0:  g_v planes[m,n] <- sum_k hv[m,k]*Wv[n,k]
// mode 1:  outExt[m,n] = resid[m,n] + sum_k mix[m,k]*Wo[n,k]
// grid (2 n-tiles, 2048 m-tiles), 256 thr, 2 CTAs/SM; tile 128x128x32.
// ---------------------------------------------------------------------------
#define WG_BUF 20480   // bf16 elems per buffer: 4 planes x 128 x 40

__global__ void __launch_bounds__(256, 2) wgemm_kernel(float* __restrict__ outExt,
                                                       const float* __restrict__ residExt,
                                                       int mode) {
    const __nv_bfloat16* Ah_g = mode ? g_mix_h : g_hv_h;
    const __nv_bfloat16* Al_g = mode ? g_mix_l : g_hv_l;
    const __nv_bfloat16* Bh_g = g_w_h + (size_t)mode*DD*DD;
    const __nv_bfloat16* Bl_g = g_w_l + (size_t)mode*DD*DD;

    extern __shared__ __nv_bfloat16 dsm[];   // 2 * WG_BUF

    const int tid = threadIdx.x, wid = tid >> 5;
    const size_t m0 = (size_t)blockIdx.y * 128;
    const int n0 = blockIdx.x * 128;
    const int m_base = (wid & 1) * 64;
    const int n_base = (wid >> 1) * 32;

    FragC acc[4][2];
#pragma unroll
    for (int mt = 0; mt < 4; mt++)
#pragma unroll
        for (int nt = 0; nt < 2; nt++) wmma::fill_fragment(acc[mt][nt], 0.0f);

    auto FILL = [&](int buf, int c) {
        __nv_bfloat16* base = dsm + buf*WG_BUF;
#pragma unroll
        for (int e = 0; e < 8; e++) {
            int id = e*256 + tid;          // 0..2047 chunks of 16B
            int plane = id >> 9;           // 0:Ah 1:Al 2:Bh 3:Bl
            int cid = id & 511;
            int row = cid >> 2;
            int cc = (cid & 3) * 8;        // bf16 elem offset in 32-wide k
            const __nv_bfloat16* src;
            if (plane == 0)      src = Ah_g + (m0 + row)*DD + c*32 + cc;
            else if (plane == 1) src = Al_g + (m0 + row)*DD + c*32 + cc;
            else if (plane == 2) src = Bh_g + (size_t)(n0 + row)*DD + c*32 + cc;
            else                 src = Bl_g + (size_t)(n0 + row)*DD + c*32 + cc;
            cp16(base + plane*5120 + row*40 + cc, src);
        }
        cp_commit();
    };
    auto COMPUTE = [&](int buf) {
        __nv_bfloat16* Ah = dsm + buf*WG_BUF;
        __nv_bfloat16* Al = Ah + 5120;
        __nv_bfloat16* Bh = Ah + 10240;
        __nv_bfloat16* Bl = Ah + 15360;
#pragma unroll
        for (int ks = 0; ks < 2; ks++) {
            FragA  af[4];
            FragBc bhf[2], blf[2];
#pragma unroll
            for (int mt = 0; mt < 4; mt++)
                wmma::load_matrix_sync(af[mt], Ah + (m_base + mt*16)*40 + ks*16, 40);
#pragma unroll
            for (int nt = 0; nt < 2; nt++) {
                wmma::load_matrix_sync(bhf[nt], Bh + (n_base + nt*16)*40 + ks*16, 40);
                wmma::load_matrix_sync(blf[nt], Bl + (n_base + nt*16)*40 + ks*16, 40);
            }
#pragma unroll
            for (int mt = 0; mt < 4; mt++)
#pragma unroll
                for (int nt = 0; nt < 2; nt++) {
                    wmma::mma_sync(acc[mt][nt], af[mt], bhf[nt], acc[mt][nt]);
                    wmma::mma_sync(acc[mt][nt], af[mt], blf[nt], acc[mt][nt]);
                }
#pragma unroll
            for (int mt = 0; mt < 4; mt++)
                wmma::load_matrix_sync(af[mt], Al + (m_base + mt*16)*40 + ks*16, 40);
#pragma unroll
            for (int mt = 0; mt < 4; mt++)
#pragma unroll
                for (int nt = 0; nt < 2; nt++)
                    wmma::mma_sync(acc[mt][nt], af[mt], bhf[nt], acc[mt][nt]);
        }
    };

    FILL(0, 0);
    for (int c = 0; c < 8; c++) {
        const int cur = c & 1;
        if (c < 7) { FILL(cur ^ 1, c + 1); cp_wait1(); }
        else cp_wait0();
        __syncthreads();
        COMPUTE(cur);
        __syncthreads();   // buf cur may be refilled next iteration
    }

    if (mode) {
        // direct fp32 epilogue with residual
#pragma unroll
        for (int mt = 0; mt < 4; mt++) {
            size_t roff = (m0 + m_base + mt*16) * DD;
#pragma unroll
            for (int nt = 0; nt < 2; nt++) {
                size_t off = roff + n0 + n_base + nt*16;
                FragC r;
                wmma::load_matrix_sync(r, residExt + off, DD, wmma::mem_row_major);
#pragma unroll
                for (int e = 0; e < r.num_elements; e++) acc[mt][nt].x[e] += r.x[e];
                wmma::store_matrix_sync(outExt + off, acc[mt][nt], DD, wmma::mem_row_major);
            }
        }
    } else {
        // stage fp32 tile in smem, convert to g_v bf16 planes
        float* cs = (float*)dsm;   // 128x128 fp32 = 64KB
#pragma unroll
        for (int mt = 0; mt < 4; mt++)
#pragma unroll
            for (int nt = 0; nt < 2; nt++)
                wmma::store_matrix_sync(cs + (m_base + mt*16)*128 + n_base + nt*16,
                                        acc[mt][nt], 128, wmma::mem_row_major);
        __syncthreads();
#pragma unroll
        for (int u = 0; u < 16; u++) {
            int f = u*256 + tid;           // 4096 float4
            int r = f >> 5, c4 = (f & 31) * 4;
            float4 v = *(const float4*)(cs + r*128 + c4);
            size_t go = (m0 + r)*DD + n0 + c4;
            split_store_bf162(g_v_h + go, g_v_l + go, v);
        }
    }
}

// ---------------------------------------------------------------------------
// K4: mix — per (b,h): C[i, td] = sum_j attn[b,h,i,j] * v[b,j,td'].
// Pure-bf16 cp.async planes; epilogue emits g_mix bf16 planes.
// grid (32 td, 2 i, 64 bh), 256 thr, 2 CTAs/SM; tile 128(i)x128(td)x32(j).
// ---------------------------------------------------------------------------
#define MX_BUF 18944   // Ph 5120 + Pl 5120 + Vh 4352 + Vl 4352

__global__ void __launch_bounds__(256, 2) mixgemm_kernel() {
    extern __shared__ __nv_bfloat16 dsm[];   // 2 * MX_BUF

    const int tid = threadIdx.x, wid = tid >> 5;
    const int bh = blockIdx.z, b = bh >> 3, h = bh & 7;
    const int td0 = blockIdx.x * 128;
    const int i0 = blockIdx.y * 128;
    const int m_base = (wid & 1) * 64;          // i
    const int n_base = (wid >> 1) * 32;         // td

    const __nv_bfloat16* Ph_g = g_attn_h + (size_t)bh * NN * NN;
    const __nv_bfloat16* Pl_g = g_attn_l + (size_t)bh * NN * NN;
    const __nv_bfloat16* Vh_g = g_v_h + (size_t)b * NN * TT * DD;
    const __nv_bfloat16* Vl_g = g_v_l + (size_t)b * NN * TT * DD;

    FragC acc[4][2];
#pragma unroll
    for (int mt = 0; mt < 4; mt++)
#pragma unroll
        for (int nt = 0; nt < 2; nt++) wmma::fill_fragment(acc[mt][nt], 0.0f);

    auto FILL = [&](int buf, int c) {
        __nv_bfloat16* base = dsm + buf*MX_BUF;
#pragma unroll
        for (int e = 0; e < 8; e++) {
            int id = e*256 + tid;
            int plane = id >> 9;           // 0:Ph 1:Pl 2:Vh 3:Vl
            int cid = id & 511;
            if (plane < 2) {
                int row = cid >> 2;            // i local
                int cc = (cid & 3) * 8;        // j offset
                const __nv_bfloat16* src = (plane ? Pl_g : Ph_g)
                                           + (size_t)(i0 + row)*NN + c*32 + cc;
                cp16(base + plane*5120 + row*40 + cc, src);
            } else {
                int j = cid >> 4;              // 32 rows of 16 chunks
                int cc = (cid & 15) * 8;       // td offset
                int tdg = td0 + cc;
                int ti = tdg >> 5, d = tdg & 31;
                const __nv_bfloat16* src = ((plane == 2) ? Vh_g : Vl_g)
                    + ((size_t)(c*32 + j)*TT + ti)*DD + h*32 + d;
                cp16(base + 10240 + (plane - 2)*4352 + j*136 + cc, src);
            }
        }
        cp_commit();
    };
    auto COMPUTE = [&](int buf) {
        __nv_bfloat16* Ph = dsm + buf*MX_BUF;
        __nv_bfloat16* Pl = Ph + 5120;
        __nv_bfloat16* Vh = Ph + 10240;
        __nv_bfloat16* Vl = Ph + 14592;
#pragma unroll
        for (int ks = 0; ks < 2; ks++) {
            FragA  af[4];
            FragBr bhf[2], blf[2];
#pragma unroll
            for (int mt = 0; mt < 4; mt++)
                wmma::load_matrix_sync(af[mt], Ph + (m_base + mt*16)*40 + ks*16, 40);
#pragma unroll
            for (int nt = 0; nt < 2; nt++) {
                wmma::load_matrix_sync(bhf[nt], Vh + ks*16*136 + n_base + nt*16, 136);
                wmma::load_matrix_sync(blf[nt], Vl + ks*16*136 + n_base + nt*16, 136);
            }
#pragma unroll
            for (int mt = 0; mt < 4; mt++)
#pragma unroll
                for (int nt = 0; nt < 2; nt++) {
                    wmma::mma_sync(acc[mt][nt], af[mt], bhf[nt], acc[mt][nt]);
                    wmma::mma_sync(acc[mt][nt], af[mt], blf[nt], acc[mt][nt]);
                }
#pragma unroll
            for (int mt = 0; mt < 4; mt++)
                wmma::load_matrix_sync(af[mt], Pl + (m_base + mt*16)*40 + ks*16, 40);
#pragma unroll
            for (int mt = 0; mt < 4; mt++)
#pragma unroll
                for (int nt = 0; nt < 2; nt++)
                    wmma::mma_sync(acc[mt][nt], af[mt], bhf[nt], acc[mt][nt]);
        }
    };

    FILL(0, 0);
    for (int c = 0; c < 8; c++) {
        const int cur = c & 1;
        if (c < 7) { FILL(cur ^ 1, c + 1); cp_wait1(); }
        else cp_wait0();
        __syncthreads();
        COMPUTE(cur);
        __syncthreads();
    }

    // epilogue: stage fp32 tile, emit g_mix bf16 planes
    float* cs = (float*)dsm;   // 128x128 fp32
#pragma unroll
    for (int mt = 0; mt < 4; mt++)
#pragma unroll
        for (int nt = 0; nt < 2; nt++)
            wmma::store_matrix_sync(cs + (m_base + mt*16)*128 + n_base + nt*16,
                                    acc[mt][nt], 128, wmma::mem_row_major);
    __syncthreads();
#pragma unroll
    for (int u = 0; u < 16; u++) {
        int f = u*256 + tid;
        int r = f >> 5, c4 = (f & 31) * 4;
        float4 v = *(const float4*)(cs + r*128 + c4);
        int tdg = td0 + c4;
        int ti = tdg >> 5, d = tdg & 31;
        size_t go = ((size_t)(b*NN + i0 + r)*TT + ti)*DD + h*32 + d;
        split_store_bf162(g_mix_h + go, g_mix_l + go, v);
    }
}

// ---------------------------------------------------------------------------
extern "C" void kernel_launch(void* const* d_in, const int* in_sizes, int n_in,
                              void* d_out, int out_size) {
    const float* h_val = (const float*)d_in[0];
    const float* z_map = (const float*)d_in[1];
    const float* adj   = (const float*)d_in[2];
    const float* Wq    = (const float*)d_in[3];
    const float* Wk    = (const float*)d_in[4];
    const float* Wv    = (const float*)d_in[5];
    const float* Wo    = (const float*)d_in[6];

    float* out       = (float*)d_out;
    float* attn_mean = out + (size_t)BATCH*NN*TT*DD;
    float* raw_mean  = attn_mean + (size_t)BATCH*NN*NN;

    const int attn_smem = (64*257 + 256 + 256 + 8*256 + 8*256) * (int)sizeof(float);
    const int wg_smem   = 2 * WG_BUF * (int)sizeof(__nv_bfloat16);   // 81920
    const int mx_smem   = 2 * MX_BUF * (int)sizeof(__nv_bfloat16);   // 75776
    cudaFuncSetAttribute(attn_kernel, cudaFuncAttributeMaxDynamicSharedMemorySize, attn_smem);
    cudaFuncSetAttribute(wgemm_kernel, cudaFuncAttributeMaxDynamicSharedMemorySize, wg_smem);
    cudaFuncSetAttribute(mixgemm_kernel, cudaFuncAttributeMaxDynamicSharedMemorySize, mx_smem);

    dim3 tgrid(8, 8, 2), tblk(32, 8);
    transpose_w_kernel<<<tgrid, tblk>>>(Wq, Wk);
    dim3 cwgrid(64, 2);
    convert_w_kernel<<<cwgrid, 256>>>(Wv, Wo);
    convert_hval_kernel<<<(int)(M_BIG*DD/1024), 256>>>(h_val);
    dim3 qkgrid(32, 2);
    gemm_qk_kernel<<<qkgrid, 256>>>(z_map);
    attn_kernel<<<BN, 256, attn_smem>>>(adj, attn_mean, raw_mean);
    dim3 wg(2, 2048);
    wgemm_kernel<<<wg, 256, wg_smem>>>(nullptr, nullptr, 0);
    dim3 gmix(32, 2, BATCH*HH);
    mixgemm_kernel<<<gmix, 256, mx_smem>>>();
    wgemm_kernel<<<wg, 256, wg_smem>>>(out, h_val, 1);
}

// round 11
// speedup vs baseline: 1.1565x; 1.1565x over previous
#include <cuda_runtime.h>
#include <cuda_bf16.h>
#include <mma.h>
#include <math.h>
#include <stdint.h>

using namespace nvcuda;

// Problem constants: B=8, N=256, T=128, D=256, H=8, hd=32, TOPK=32
#define BATCH 8
#define NN    256
#define TT    128
#define DD    256
#define HH    8
#define HD    32
#define TOPK  32

#define BN    (BATCH*NN)            // 2048
#define M_BIG ((size_t)BATCH*NN*TT) // 262144

// Scratch (accessed ONLY from device code — never passed as kernel args)
__device__ float g_q[BN*DD];
__device__ float g_k[BN*DD];
__device__ float g_wt[2*DD*DD];                    // transposed Wq,Wk
__device__ float g_attn[(size_t)BATCH*HH*NN*NN];   // 16 MB
__device__ float g_v[(size_t)BATCH*NN*TT*DD];      // 256 MB
__device__ float g_mixed[(size_t)BATCH*NN*TT*DD];  // 256 MB

typedef wmma::fragment<wmma::matrix_a, 16, 16, 16, __nv_bfloat16, wmma::row_major> FragA;
typedef wmma::fragment<wmma::matrix_b, 16, 16, 16, __nv_bfloat16, wmma::col_major> FragBc;
typedef wmma::fragment<wmma::matrix_b, 16, 16, 16, __nv_bfloat16, wmma::row_major> FragBr;
typedef wmma::fragment<wmma::accumulator, 16, 16, 16, float> FragC;

// ---------------------------------------------------------------------------
// helpers
// ---------------------------------------------------------------------------
__device__ __forceinline__ void cp16(void* dst, const void* src) {
    unsigned d = (unsigned)__cvta_generic_to_shared(dst);
    asm volatile("cp.async.cg.shared.global [%0], [%1], 16;\n" :: "r"(d), "l"(src));
}
__device__ __forceinline__ void cp_commit() { asm volatile("cp.async.commit_group;\n"); }
__device__ __forceinline__ void cp_wait1()  { asm volatile("cp.async.wait_group 1;\n"); }
__device__ __forceinline__ void cp_wait0()  { asm volatile("cp.async.wait_group 0;\n"); }

// fp32 -> (bf16 hi, bf16 lo) split, plain element stores (no punning).
__device__ __forceinline__ void bf_split_store4(__nv_bfloat16* hp, __nv_bfloat16* lp,
                                                float4 v) {
    float vv0 = v.x, vv1 = v.y, vv2 = v.z, vv3 = v.w;
    __nv_bfloat16 h0 = __float2bfloat16_rn(vv0);
    __nv_bfloat16 h1 = __float2bfloat16_rn(vv1);
    __nv_bfloat16 h2 = __float2bfloat16_rn(vv2);
    __nv_bfloat16 h3 = __float2bfloat16_rn(vv3);
    hp[0] = h0; hp[1] = h1; hp[2] = h2; hp[3] = h3;
    lp[0] = __float2bfloat16_rn(vv0 - __bfloat162float(h0));
    lp[1] = __float2bfloat16_rn(vv1 - __bfloat162float(h1));
    lp[2] = __float2bfloat16_rn(vv2 - __bfloat162float(h2));
    lp[3] = __float2bfloat16_rn(vv3 - __bfloat162float(h3));
}

// ---------------------------------------------------------------------------
// K0: transpose Wq, Wk  -> g_wt.  grid (8,8,2), block (32,8)
// ---------------------------------------------------------------------------
__global__ void transpose_w_kernel(const float* __restrict__ Wq, const float* __restrict__ Wk) {
    __shared__ float t[32][33];
    const int w = blockIdx.z;
    const float* W = (w == 0) ? Wq : Wk;
    float* out = g_wt + (size_t)w * DD * DD;
    const int n0 = blockIdx.x * 32, k0 = blockIdx.y * 32;
    const int tx = threadIdx.x, ty = threadIdx.y;
#pragma unroll
    for (int i = 0; i < 4; i++)
        t[ty + 8*i][tx] = W[(size_t)(n0 + ty + 8*i)*DD + k0 + tx];
    __syncthreads();
#pragma unroll
    for (int i = 0; i < 4; i++)
        out[(size_t)(k0 + ty + 8*i)*DD + n0 + tx] = t[tx][ty + 8*i];
}

// ---------------------------------------------------------------------------
// SIMT GEMM macros (qk only)
// ---------------------------------------------------------------------------
#define GEMM_DECL \
    __shared__ float As[2][16][68];  \
    __shared__ float Bs[2][16][260]; \
    const int tid = threadIdx.x;     \
    const int tx = tid & 31, ty = tid >> 5; \
    const int ar = tid >> 2;         \
    const int ak = (tid & 3) << 2;   \
    float acc[8][8];                 \
    _Pragma("unroll") for (int r = 0; r < 8; r++) \
    _Pragma("unroll") for (int c = 0; c < 8; c++) acc[r][c] = 0.f;

#define GEMM_COMPUTE(buf) \
    _Pragma("unroll") \
    for (int kk = 0; kk < 16; kk++) { \
        float a[8], bb[8]; \
        *(float4*)&a[0]  = *(const float4*)&As[buf][kk][ty*8]; \
        *(float4*)&a[4]  = *(const float4*)&As[buf][kk][ty*8 + 4]; \
        *(float4*)&bb[0] = *(const float4*)&Bs[buf][kk][tx*8]; \
        *(float4*)&bb[4] = *(const float4*)&Bs[buf][kk][tx*8 + 4]; \
        _Pragma("unroll") for (int r = 0; r < 8; r++) \
        _Pragma("unroll") for (int c = 0; c < 8; c++) acc[r][c] += a[r]*bb[c]; \
    }

// ---------------------------------------------------------------------------
// K1: q/k projection GEMM.  grid (32, 2): y=0 -> q, y=1 -> k
// ---------------------------------------------------------------------------
__global__ void __launch_bounds__(256) gemm_qk_kernel(const float* __restrict__ Z) {
    GEMM_DECL
    const int wsel = blockIdx.y;
    const float* WT = g_wt + (size_t)wsel * DD * DD;
    float* out = wsel ? g_k : g_q;
    const size_t m0 = (size_t)blockIdx.x * 64;

#pragma unroll
    for (int u = 0; u < 4; u++) {
        int f = tid + u*256; int jj = f >> 6; int cc = (f & 63) << 2;
        cp16(&Bs[0][jj][cc], WT + (size_t)jj*DD + cc);
    }
    cp_commit();
    float4 av = *(const float4*)(Z + (m0 + ar)*DD + ak);
    As[0][ak+0][ar] = av.x; As[0][ak+1][ar] = av.y;
    As[0][ak+2][ar] = av.z; As[0][ak+3][ar] = av.w;

    for (int k = 0; k < 16; k++) {
        const int cur = k & 1;
        if (k < 15) {
            av = *(const float4*)(Z + (m0 + ar)*DD + (k+1)*16 + ak);
#pragma unroll
            for (int u = 0; u < 4; u++) {
                int f = tid + u*256; int jj = f >> 6; int cc = (f & 63) << 2;
                cp16(&Bs[cur^1][jj][cc], WT + (size_t)((k+1)*16 + jj)*DD + cc);
            }
            cp_commit(); cp_wait1();
        } else cp_wait0();
        __syncthreads();
        GEMM_COMPUTE(cur)
        __syncthreads();
        if (k < 15) {
            As[cur^1][ak+0][ar] = av.x; As[cur^1][ak+1][ar] = av.y;
            As[cur^1][ak+2][ar] = av.z; As[cur^1][ak+3][ar] = av.w;
        }
    }
#pragma unroll
    for (int r = 0; r < 8; r++) {
        size_t row = m0 + ty*8 + r;
#pragma unroll
        for (int c = 0; c < 8; c += 4) {
            float4 o = make_float4(acc[r][c], acc[r][c+1], acc[r][c+2], acc[r][c+3]);
            *(float4*)(out + row*DD + tx*8 + c) = o;
        }
    }
}

// ---------------------------------------------------------------------------
// K2: attention — warp h handles head h of row (b,i).
// ---------------------------------------------------------------------------
#define SWAP_DESC(a, b) { float _hi = fmaxf(a, b); b = fminf(a, b); a = _hi; }

__global__ void __launch_bounds__(256) attn_kernel(const float* __restrict__ adj,
                                                   float* __restrict__ out_attn_mean,
                                                   float* __restrict__ out_raw_mean) {
    extern __shared__ float sm[];
    float* kss   = sm;
    float* logbs = kss + 64*257;
    float* qsh   = logbs + 256;
    float* asum  = qsh + 256;
    float* rsum  = asum + 8*256;

    const int bi = blockIdx.x, b = bi >> 8, i = bi & 255;
    const int tid = threadIdx.x, lane = tid & 31, h = tid >> 5;
    const float scale = 0.17677669529663687f;

    logbs[tid] = logf(fmaxf(adj[(size_t)bi*NN + tid], 1e-12f));
    qsh[tid]   = g_q[(size_t)bi*DD + tid];
    __syncthreads();

    float qreg[32];
#pragma unroll
    for (int e = 0; e < 32; e++) qreg[e] = qsh[h*HD + e];

    float sreg[8];
    for (int jt = 0; jt < 4; jt++) {
        if (jt) __syncthreads();
        const float* ksrc = g_k + ((size_t)(b*NN) + jt*64) * DD;
#pragma unroll
        for (int u = 0; u < 16; u++) {
            int f = tid + u*256;
            int r = f >> 6, c = (f & 63) << 2;
            float4 kv = *(const float4*)(ksrc + (size_t)f*4);
            kss[r*257 + c + 0] = kv.x; kss[r*257 + c + 1] = kv.y;
            kss[r*257 + c + 2] = kv.z; kss[r*257 + c + 3] = kv.w;
        }
        __syncthreads();
#pragma unroll
        for (int g = 0; g < 2; g++) {
            int jl = g*32 + lane;
            const float* kp = &kss[jl*257 + h*HD];
            float s = 0.f;
#pragma unroll
            for (int e = 0; e < 32; e++) s += qreg[e] * kp[e];
            sreg[jt*2 + g] = s * scale + logbs[jt*64 + jl];
        }
    }

    float m = sreg[0];
#pragma unroll
    for (int x = 1; x < 8; x++) m = fmaxf(m, sreg[x]);
#pragma unroll
    for (int o = 16; o; o >>= 1) m = fmaxf(m, __shfl_xor_sync(0xffffffffu, m, o));
    float preg[8], tsum = 0.f;
#pragma unroll
    for (int x = 0; x < 8; x++) { preg[x] = expf(sreg[x] - m); tsum += preg[x]; }
#pragma unroll
    for (int o = 16; o; o >>= 1) tsum += __shfl_xor_sync(0xffffffffu, tsum, o);

    float v0 = sreg[0], v1 = sreg[1], v2 = sreg[2], v3 = sreg[3];
    float v4 = sreg[4], v5 = sreg[5], v6 = sreg[6], v7 = sreg[7];
    SWAP_DESC(v0,v1) SWAP_DESC(v2,v3) SWAP_DESC(v4,v5) SWAP_DESC(v6,v7)
    SWAP_DESC(v0,v2) SWAP_DESC(v1,v3) SWAP_DESC(v4,v6) SWAP_DESC(v5,v7)
    SWAP_DESC(v1,v2) SWAP_DESC(v5,v6)
    SWAP_DESC(v0,v4) SWAP_DESC(v1,v5) SWAP_DESC(v2,v6) SWAP_DESC(v3,v7)
    SWAP_DESC(v2,v4) SWAP_DESC(v3,v5)
    SWAP_DESC(v1,v2) SWAP_DESC(v3,v4) SWAP_DESC(v5,v6)

    float kth = 0.f;
#pragma unroll 1
    for (int it = 0; it < TOPK; it++) {
        float mm = v0;
#pragma unroll
        for (int o = 16; o; o >>= 1) mm = fmaxf(mm, __shfl_xor_sync(0xffffffffu, mm, o));
        if (it == TOPK-1) { kth = mm; break; }
        unsigned bal = __ballot_sync(0xffffffffu, v0 == mm);
        if (lane == (__ffs(bal) - 1)) {
            v0 = v1; v1 = v2; v2 = v3; v3 = v4; v4 = v5; v5 = v6; v6 = v7;
            v7 = -3.402823466e38f;
        }
    }

    float pa[8], ts2 = 0.f;
#pragma unroll
    for (int x = 0; x < 8; x++) { pa[x] = (sreg[x] >= kth) ? preg[x] : 0.f; ts2 += pa[x]; }
#pragma unroll
    for (int o = 16; o; o >>= 1) ts2 += __shfl_xor_sync(0xffffffffu, ts2, o);

    const float inv2 = 1.f / ts2, inv1 = 1.f / tsum;
    float* arow = g_attn + ((size_t)(b*HH + h)*NN + i)*NN;
#pragma unroll
    for (int x = 0; x < 8; x++) {
        int j = (x >> 1)*64 + (x & 1)*32 + lane;
        float a = pa[x] * inv2;
        arow[j] = a;
        asum[h*256 + j] = a;
        rsum[h*256 + j] = preg[x] * inv1;
    }
    __syncthreads();
    float sa = 0.f, sr = 0.f;
#pragma unroll
    for (int hh = 0; hh < 8; hh++) { sa += asum[hh*256 + tid]; sr += rsum[hh*256 + tid]; }
    out_attn_mean[(size_t)bi*NN + tid] = sa * 0.125f;
    out_raw_mean[(size_t)bi*NN + tid]  = sr * 0.125f;
}

// ---------------------------------------------------------------------------
// K3/K5: bf16x3 WMMA GEMM vs weights, 512 threads (16 warps of 32x32 tiles),
// double-buffered staging.
// mode 0:  g_v[m,n]  = sum_k Aext[m,k]*W[n,k]           (Aext = h_val)
// mode 1:  outExt[m,n] = resid[m,n] + sum_k g_mixed[m,k]*W[n,k]
// grid (2048, 2); tile 128x128x32.
// ---------------------------------------------------------------------------
#define WG_BUF 20480   // bf16 elems per buffer: 4 planes x 128 rows x 40

__global__ void __launch_bounds__(512) wgemm_kernel(const float* __restrict__ Aext,
                                                    const float* __restrict__ W,
                                                    float* __restrict__ outExt,
                                                    const float* __restrict__ residExt,
                                                    int mode) {
    const float* A      = mode ? (const float*)g_mixed : Aext;
    float*       outp   = mode ? outExt : (float*)g_v;
    const float* resid  = mode ? residExt : nullptr;

    extern __shared__ __nv_bfloat16 dsm[];   // 2 * WG_BUF

    const int tid = threadIdx.x, wid = tid >> 5;
    const size_t m0 = (size_t)blockIdx.x * 128;
    const int n0 = blockIdx.y * 128;
    const int sr = tid >> 3, sk4 = (tid & 7) * 4;   // staging: row(0..63 per u), k elem
    const int m_base = (wid & 3) * 32;
    const int n_base = (wid >> 2) * 32;

    FragC acc[2][2];
#pragma unroll
    for (int mt = 0; mt < 2; mt++)
#pragma unroll
        for (int nt = 0; nt < 2; nt++) wmma::fill_fragment(acc[mt][nt], 0.0f);

    float4 areg[2], breg[2];
    auto LOAD = [&](int c) {
#pragma unroll
        for (int u = 0; u < 2; u++) {
            areg[u] = *(const float4*)(A + (m0 + sr + u*64)*DD + c*32 + sk4);
            breg[u] = *(const float4*)(W + (size_t)(n0 + sr + u*64)*DD + c*32 + sk4);
        }
    };
    auto STORE = [&](int buf) {
        __nv_bfloat16* Ah = dsm + buf*WG_BUF;
        __nv_bfloat16* Al = Ah + 5120;
        __nv_bfloat16* Bh = Ah + 10240;
        __nv_bfloat16* Bl = Ah + 15360;
#pragma unroll
        for (int u = 0; u < 2; u++) {
            int off = (sr + u*64)*40 + sk4;
            bf_split_store4(Ah + off, Al + off, areg[u]);
            bf_split_store4(Bh + off, Bl + off, breg[u]);
        }
    };
    auto COMPUTE = [&](int buf) {
        __nv_bfloat16* Ah = dsm + buf*WG_BUF;
        __nv_bfloat16* Al = Ah + 5120;
        __nv_bfloat16* Bh = Ah + 10240;
        __nv_bfloat16* Bl = Ah + 15360;
#pragma unroll
        for (int ks = 0; ks < 2; ks++) {
            FragA  af[2];
            FragBc bhf[2], blf[2];
#pragma unroll
            for (int mt = 0; mt < 2; mt++)
                wmma::load_matrix_sync(af[mt], Ah + (m_base + mt*16)*40 + ks*16, 40);
#pragma unroll
            for (int nt = 0; nt < 2; nt++) {
                wmma::load_matrix_sync(bhf[nt], Bh + (n_base + nt*16)*40 + ks*16, 40);
                wmma::load_matrix_sync(blf[nt], Bl + (n_base + nt*16)*40 + ks*16, 40);
            }
#pragma unroll
            for (int mt = 0; mt < 2; mt++)
#pragma unroll
                for (int nt = 0; nt < 2; nt++) {
                    wmma::mma_sync(acc[mt][nt], af[mt], bhf[nt], acc[mt][nt]);
                    wmma::mma_sync(acc[mt][nt], af[mt], blf[nt], acc[mt][nt]);
                }
#pragma unroll
            for (int mt = 0; mt < 2; mt++)
                wmma::load_matrix_sync(af[mt], Al + (m_base + mt*16)*40 + ks*16, 40);
#pragma unroll
            for (int mt = 0; mt < 2; mt++)
#pragma unroll
                for (int nt = 0; nt < 2; nt++)
                    wmma::mma_sync(acc[mt][nt], af[mt], bhf[nt], acc[mt][nt]);
        }
    };

    LOAD(0);
    STORE(0);
    __syncthreads();
    for (int c = 0; c < 8; c++) {
        const int cur = c & 1;
        if (c < 7) LOAD(c + 1);
        COMPUTE(cur);
        if (c < 7) STORE(cur ^ 1);
        __syncthreads();
    }

#pragma unroll
    for (int mt = 0; mt < 2; mt++) {
        size_t roff = (m0 + m_base + mt*16) * DD;
#pragma unroll
        for (int nt = 0; nt < 2; nt++) {
            size_t off = roff + n0 + n_base + nt*16;
            if (resid) {
                FragC r;
                wmma::load_matrix_sync(r, resid + off, DD, wmma::mem_row_major);
#pragma unroll
                for (int e = 0; e < r.num_elements; e++) acc[mt][nt].x[e] += r.x[e];
            }
            wmma::store_matrix_sync(outp + off, acc[mt][nt], DD, wmma::mem_row_major);
        }
    }
}

// ---------------------------------------------------------------------------
// K4: mix — per (b,h): C[i, td] = sum_j attn[b,h,i,j] * v[b,j,td'],
//     td' = (t, h*32+d), td = t*32+d within this block's 128-wide td tile.
// attn = matrix_a (row_major, k=j); V staged [j][td] = matrix_b row_major.
// grid (32 td, 2 i, 64 bh), 512 thr (16 warps of 32x32); double-buffered.
// ---------------------------------------------------------------------------
#define MX_BUF 18944   // Ph 5120 + Pl 5120 + Vh 4352 + Vl 4352

__global__ void __launch_bounds__(512) mixgemm_kernel() {
    extern __shared__ __nv_bfloat16 dsm[];   // 2 * MX_BUF

    const int tid = threadIdx.x, wid = tid >> 5;
    const int bh = blockIdx.z, b = bh >> 3, h = bh & 7;
    const int td0 = blockIdx.x * 128;
    const int i0 = blockIdx.y * 128;
    const int pr = tid >> 3, pk4 = (tid & 7) * 4;        // attn staging
    const int vjj = tid >> 5, vtd = (tid & 31) * 4;      // v staging
    const int m_base = (wid & 3) * 32;          // i
    const int n_base = (wid >> 2) * 32;         // td

    const float* Vb = g_v + (size_t)b * NN * TT * DD;
    const float* Pb = g_attn + (size_t)bh * NN * NN;

    FragC acc[2][2];
#pragma unroll
    for (int mt = 0; mt < 2; mt++)
#pragma unroll
        for (int nt = 0; nt < 2; nt++) wmma::fill_fragment(acc[mt][nt], 0.0f);

    float4 vreg[2], preg[2];
    auto LOAD = [&](int c) {
        int tdg = td0 + vtd;
        int ti = tdg >> 5, d = tdg & 31;
#pragma unroll
        for (int u = 0; u < 2; u++) {
            vreg[u] = *(const float4*)(Vb + ((size_t)(c*32 + vjj + u*16)*TT + ti)*DD + h*32 + d);
            preg[u] = *(const float4*)(Pb + (size_t)(i0 + pr + u*64)*NN + c*32 + pk4);
        }
    };
    auto STORE = [&](int buf) {
        __nv_bfloat16* Ph = dsm + buf*MX_BUF;
        __nv_bfloat16* Pl = Ph + 5120;
        __nv_bfloat16* Vh = Ph + 10240;
        __nv_bfloat16* Vl = Ph + 14592;
#pragma unroll
        for (int u = 0; u < 2; u++) {
            int poff = (pr + u*64)*40 + pk4;
            bf_split_store4(Ph + poff, Pl + poff, preg[u]);
            int voff = (vjj + u*16)*136 + vtd;
            bf_split_store4(Vh + voff, Vl + voff, vreg[u]);
        }
    };
    auto COMPUTE = [&](int buf) {
        __nv_bfloat16* Ph = dsm + buf*MX_BUF;
        __nv_bfloat16* Pl = Ph + 5120;
        __nv_bfloat16* Vh = Ph + 10240;
        __nv_bfloat16* Vl = Ph + 14592;
#pragma unroll
        for (int ks = 0; ks < 2; ks++) {
            FragA  af[2];
            FragBr bhf[2], blf[2];
#pragma unroll
            for (int mt = 0; mt < 2; mt++)
                wmma::load_matrix_sync(af[mt], Ph + (m_base + mt*16)*40 + ks*16, 40);
#pragma unroll
            for (int nt = 0; nt < 2; nt++) {
                wmma::load_matrix_sync(bhf[nt], Vh + ks*16*136 + n_base + nt*16, 136);
                wmma::load_matrix_sync(blf[nt], Vl + ks*16*136 + n_base + nt*16, 136);
            }
#pragma unroll
            for (int mt = 0; mt < 2; mt++)
#pragma unroll
                for (int nt = 0; nt < 2; nt++) {
                    wmma::mma_sync(acc[mt][nt], af[mt], bhf[nt], acc[mt][nt]);
                    wmma::mma_sync(acc[mt][nt], af[mt], blf[nt], acc[mt][nt]);
                }
#pragma unroll
            for (int mt = 0; mt < 2; mt++)
                wmma::load_matrix_sync(af[mt], Pl + (m_base + mt*16)*40 + ks*16, 40);
#pragma unroll
            for (int mt = 0; mt < 2; mt++)
#pragma unroll
                for (int nt = 0; nt < 2; nt++)
                    wmma::mma_sync(acc[mt][nt], af[mt], bhf[nt], acc[mt][nt]);
        }
    };

    LOAD(0);
    STORE(0);
    __syncthreads();
    for (int c = 0; c < 8; c++) {
        const int cur = c & 1;
        if (c < 7) LOAD(c + 1);
        COMPUTE(cur);
        if (c < 7) STORE(cur ^ 1);
        __syncthreads();
    }

#pragma unroll
    for (int mt = 0; mt < 2; mt++) {
        int irow0 = i0 + m_base + mt*16;
#pragma unroll
        for (int nt = 0; nt < 2; nt++) {
            int tdg0 = td0 + n_base + nt*16;
            int ti = tdg0 >> 5, d0 = tdg0 & 31;
            float* p = g_mixed + ((size_t)(b*NN + irow0)*TT + ti)*DD + h*32 + d0;
            wmma::store_matrix_sync(p, acc[mt][nt], TT*DD, wmma::mem_row_major);
        }
    }
}

// ---------------------------------------------------------------------------
extern "C" void kernel_launch(void* const* d_in, const int* in_sizes, int n_in,
                              void* d_out, int out_size) {
    const float* h_val = (const float*)d_in[0];
    const float* z_map = (const float*)d_in[1];
    const float* adj   = (const float*)d_in[2];
    const float* Wq    = (const float*)d_in[3];
    const float* Wk    = (const float*)d_in[4];
    const float* Wv    = (const float*)d_in[5];
    const float* Wo    = (const float*)d_in[6];

    float* out       = (float*)d_out;
    float* attn_mean = out + (size_t)BATCH*NN*TT*DD;
    float* raw_mean  = attn_mean + (size_t)BATCH*NN*NN;

    const int attn_smem = (64*257 + 256 + 256 + 8*256 + 8*256) * (int)sizeof(float);
    const int wg_smem   = 2 * WG_BUF * (int)sizeof(__nv_bfloat16);   // 81920
    const int mx_smem   = 2 * MX_BUF * (int)sizeof(__nv_bfloat16);   // 75776
    cudaFuncSetAttribute(attn_kernel, cudaFuncAttributeMaxDynamicSharedMemorySize, attn_smem);
    cudaFuncSetAttribute(wgemm_kernel, cudaFuncAttributeMaxDynamicSharedMemorySize, wg_smem);
    cudaFuncSetAttribute(mixgemm_kernel, cudaFuncAttributeMaxDynamicSharedMemorySize, mx_smem);

    dim3 tgrid(8, 8, 2), tblk(32, 8);
    transpose_w_kernel<<<tgrid, tblk>>>(Wq, Wk);
    dim3 qkgrid(32, 2);
    gemm_qk_kernel<<<qkgrid, 256>>>(z_map);
    attn_kernel<<<BN, 256, attn_smem>>>(adj, attn_mean, raw_mean);
    dim3 wg((int)(M_BIG/128), 2);
    wgemm_kernel<<<wg, 512, wg_smem>>>(h_val, Wv, nullptr, nullptr, 0);
    dim3 gmix(32, 2, BATCH*HH);
    mixgemm_kernel<<<gmix, 512, mx_smem>>>();
    wgemm_kernel<<<wg, 512, wg_smem>>>(nullptr, Wo, out, h_val, 1);
}

// round 12
// speedup vs baseline: 1.9336x; 1.6720x over previous
#include <cuda_runtime.h>
#include <cuda_bf16.h>
#include <cuda_fp16.h>
#include <mma.h>
#include <math.h>
#include <stdint.h>

using namespace nvcuda;

// Problem constants: B=8, N=256, T=128, D=256, H=8, hd=32, TOPK=32
#define BATCH 8
#define NN    256
#define TT    128
#define DD    256
#define HH    8
#define HD    32
#define TOPK  32

#define BN    (BATCH*NN)            // 2048
#define M_BIG ((size_t)BATCH*NN*TT) // 262144

// Scratch (accessed ONLY from device code — never passed as kernel args)
__device__ float g_q[BN*DD];
__device__ float g_k[BN*DD];
__device__ float g_wt[2*DD*DD];                    // transposed Wq,Wk
__device__ float g_attn[(size_t)BATCH*HH*NN*NN];   // 16 MB
__device__ float g_v[(size_t)BATCH*NN*TT*DD];      // 256 MB
__device__ float g_mixed[(size_t)BATCH*NN*TT*DD];  // 256 MB

typedef wmma::fragment<wmma::matrix_a, 16, 16, 16, __half, wmma::row_major> HFragA;
typedef wmma::fragment<wmma::matrix_b, 16, 16, 16, __half, wmma::col_major> HFragBc;
typedef wmma::fragment<wmma::matrix_b, 16, 16, 16, __half, wmma::row_major> HFragBr;
typedef wmma::fragment<wmma::accumulator, 16, 16, 16, float> FragC;

// ---------------------------------------------------------------------------
// helpers
// ---------------------------------------------------------------------------
__device__ __forceinline__ void cp16(void* dst, const void* src) {
    unsigned d = (unsigned)__cvta_generic_to_shared(dst);
    asm volatile("cp.async.cg.shared.global [%0], [%1], 16;\n" :: "r"(d), "l"(src));
}
__device__ __forceinline__ void cp_commit() { asm volatile("cp.async.commit_group;\n"); }
__device__ __forceinline__ void cp_wait1()  { asm volatile("cp.async.wait_group 1;\n"); }
__device__ __forceinline__ void cp_wait0()  { asm volatile("cp.async.wait_group 0;\n"); }

// fp32 -> fp16 (rn), plain element stores
__device__ __forceinline__ void h_store4(__half* p, float4 v) {
    p[0] = __float2half_rn(v.x);
    p[1] = __float2half_rn(v.y);
    p[2] = __float2half_rn(v.z);
    p[3] = __float2half_rn(v.w);
}

// ---------------------------------------------------------------------------
// K0: transpose Wq, Wk  -> g_wt.  grid (8,8,2), block (32,8)
// ---------------------------------------------------------------------------
__global__ void transpose_w_kernel(const float* __restrict__ Wq, const float* __restrict__ Wk) {
    __shared__ float t[32][33];
    const int w = blockIdx.z;
    const float* W = (w == 0) ? Wq : Wk;
    float* out = g_wt + (size_t)w * DD * DD;
    const int n0 = blockIdx.x * 32, k0 = blockIdx.y * 32;
    const int tx = threadIdx.x, ty = threadIdx.y;
#pragma unroll
    for (int i = 0; i < 4; i++)
        t[ty + 8*i][tx] = W[(size_t)(n0 + ty + 8*i)*DD + k0 + tx];
    __syncthreads();
#pragma unroll
    for (int i = 0; i < 4; i++)
        out[(size_t)(k0 + ty + 8*i)*DD + n0 + tx] = t[tx][ty + 8*i];
}

// ---------------------------------------------------------------------------
// SIMT GEMM macros (qk only)
// ---------------------------------------------------------------------------
#define GEMM_DECL \
    __shared__ float As[2][16][68];  \
    __shared__ float Bs[2][16][260]; \
    const int tid = threadIdx.x;     \
    const int tx = tid & 31, ty = tid >> 5; \
    const int ar = tid >> 2;         \
    const int ak = (tid & 3) << 2;   \
    float acc[8][8];                 \
    _Pragma("unroll") for (int r = 0; r < 8; r++) \
    _Pragma("unroll") for (int c = 0; c < 8; c++) acc[r][c] = 0.f;

#define GEMM_COMPUTE(buf) \
    _Pragma("unroll") \
    for (int kk = 0; kk < 16; kk++) { \
        float a[8], bb[8]; \
        *(float4*)&a[0]  = *(const float4*)&As[buf][kk][ty*8]; \
        *(float4*)&a[4]  = *(const float4*)&As[buf][kk][ty*8 + 4]; \
        *(float4*)&bb[0] = *(const float4*)&Bs[buf][kk][tx*8]; \
        *(float4*)&bb[4] = *(const float4*)&Bs[buf][kk][tx*8 + 4]; \
        _Pragma("unroll") for (int r = 0; r < 8; r++) \
        _Pragma("unroll") for (int c = 0; c < 8; c++) acc[r][c] += a[r]*bb[c]; \
    }

// ---------------------------------------------------------------------------
// K1: q/k projection GEMM.  grid (32, 2): y=0 -> q, y=1 -> k
// ---------------------------------------------------------------------------
__global__ void __launch_bounds__(256) gemm_qk_kernel(const float* __restrict__ Z) {
    GEMM_DECL
    const int wsel = blockIdx.y;
    const float* WT = g_wt + (size_t)wsel * DD * DD;
    float* out = wsel ? g_k : g_q;
    const size_t m0 = (size_t)blockIdx.x * 64;

#pragma unroll
    for (int u = 0; u < 4; u++) {
        int f = tid + u*256; int jj = f >> 6; int cc = (f & 63) << 2;
        cp16(&Bs[0][jj][cc], WT + (size_t)jj*DD + cc);
    }
    cp_commit();
    float4 av = *(const float4*)(Z + (m0 + ar)*DD + ak);
    As[0][ak+0][ar] = av.x; As[0][ak+1][ar] = av.y;
    As[0][ak+2][ar] = av.z; As[0][ak+3][ar] = av.w;

    for (int k = 0; k < 16; k++) {
        const int cur = k & 1;
        if (k < 15) {
            av = *(const float4*)(Z + (m0 + ar)*DD + (k+1)*16 + ak);
#pragma unroll
            for (int u = 0; u < 4; u++) {
                int f = tid + u*256; int jj = f >> 6; int cc = (f & 63) << 2;
                cp16(&Bs[cur^1][jj][cc], WT + (size_t)((k+1)*16 + jj)*DD + cc);
            }
            cp_commit(); cp_wait1();
        } else cp_wait0();
        __syncthreads();
        GEMM_COMPUTE(cur)
        __syncthreads();
        if (k < 15) {
            As[cur^1][ak+0][ar] = av.x; As[cur^1][ak+1][ar] = av.y;
            As[cur^1][ak+2][ar] = av.z; As[cur^1][ak+3][ar] = av.w;
        }
    }
#pragma unroll
    for (int r = 0; r < 8; r++) {
        size_t row = m0 + ty*8 + r;
#pragma unroll
        for (int c = 0; c < 8; c += 4) {
            float4 o = make_float4(acc[r][c], acc[r][c+1], acc[r][c+2], acc[r][c+3]);
            *(float4*)(out + row*DD + tx*8 + c) = o;
        }
    }
}

// ---------------------------------------------------------------------------
// K2: attention — warp h handles head h of row (b,i).
// ---------------------------------------------------------------------------
#define SWAP_DESC(a, b) { float _hi = fmaxf(a, b); b = fminf(a, b); a = _hi; }

__global__ void __launch_bounds__(256) attn_kernel(const float* __restrict__ adj,
                                                   float* __restrict__ out_attn_mean,
                                                   float* __restrict__ out_raw_mean) {
    extern __shared__ float sm[];
    float* kss   = sm;
    float* logbs = kss + 64*257;
    float* qsh   = logbs + 256;
    float* asum  = qsh + 256;
    float* rsum  = asum + 8*256;

    const int bi = blockIdx.x, b = bi >> 8, i = bi & 255;
    const int tid = threadIdx.x, lane = tid & 31, h = tid >> 5;
    const float scale = 0.17677669529663687f;

    logbs[tid] = logf(fmaxf(adj[(size_t)bi*NN + tid], 1e-12f));
    qsh[tid]   = g_q[(size_t)bi*DD + tid];
    __syncthreads();

    float qreg[32];
#pragma unroll
    for (int e = 0; e < 32; e++) qreg[e] = qsh[h*HD + e];

    float sreg[8];
    for (int jt = 0; jt < 4; jt++) {
        if (jt) __syncthreads();
        const float* ksrc = g_k + ((size_t)(b*NN) + jt*64) * DD;
#pragma unroll
        for (int u = 0; u < 16; u++) {
            int f = tid + u*256;
            int r = f >> 6, c = (f & 63) << 2;
            float4 kv = *(const float4*)(ksrc + (size_t)f*4);
            kss[r*257 + c + 0] = kv.x; kss[r*257 + c + 1] = kv.y;
            kss[r*257 + c + 2] = kv.z; kss[r*257 + c + 3] = kv.w;
        }
        __syncthreads();
#pragma unroll
        for (int g = 0; g < 2; g++) {
            int jl = g*32 + lane;
            const float* kp = &kss[jl*257 + h*HD];
            float s = 0.f;
#pragma unroll
            for (int e = 0; e < 32; e++) s += qreg[e] * kp[e];
            sreg[jt*2 + g] = s * scale + logbs[jt*64 + jl];
        }
    }

    float m = sreg[0];
#pragma unroll
    for (int x = 1; x < 8; x++) m = fmaxf(m, sreg[x]);
#pragma unroll
    for (int o = 16; o; o >>= 1) m = fmaxf(m, __shfl_xor_sync(0xffffffffu, m, o));
    float preg[8], tsum = 0.f;
#pragma unroll
    for (int x = 0; x < 8; x++) { preg[x] = expf(sreg[x] - m); tsum += preg[x]; }
#pragma unroll
    for (int o = 16; o; o >>= 1) tsum += __shfl_xor_sync(0xffffffffu, tsum, o);

    float v0 = sreg[0], v1 = sreg[1], v2 = sreg[2], v3 = sreg[3];
    float v4 = sreg[4], v5 = sreg[5], v6 = sreg[6], v7 = sreg[7];
    SWAP_DESC(v0,v1) SWAP_DESC(v2,v3) SWAP_DESC(v4,v5) SWAP_DESC(v6,v7)
    SWAP_DESC(v0,v2) SWAP_DESC(v1,v3) SWAP_DESC(v4,v6) SWAP_DESC(v5,v7)
    SWAP_DESC(v1,v2) SWAP_DESC(v5,v6)
    SWAP_DESC(v0,v4) SWAP_DESC(v1,v5) SWAP_DESC(v2,v6) SWAP_DESC(v3,v7)
    SWAP_DESC(v2,v4) SWAP_DESC(v3,v5)
    SWAP_DESC(v1,v2) SWAP_DESC(v3,v4) SWAP_DESC(v5,v6)

    float kth = 0.f;
#pragma unroll 1
    for (int it = 0; it < TOPK; it++) {
        float mm = v0;
#pragma unroll
        for (int o = 16; o; o >>= 1) mm = fmaxf(mm, __shfl_xor_sync(0xffffffffu, mm, o));
        if (it == TOPK-1) { kth = mm; break; }
        unsigned bal = __ballot_sync(0xffffffffu, v0 == mm);
        if (lane == (__ffs(bal) - 1)) {
            v0 = v1; v1 = v2; v2 = v3; v3 = v4; v4 = v5; v5 = v6; v6 = v7;
            v7 = -3.402823466e38f;
        }
    }

    float pa[8], ts2 = 0.f;
#pragma unroll
    for (int x = 0; x < 8; x++) { pa[x] = (sreg[x] >= kth) ? preg[x] : 0.f; ts2 += pa[x]; }
#pragma unroll
    for (int o = 16; o; o >>= 1) ts2 += __shfl_xor_sync(0xffffffffu, ts2, o);

    const float inv2 = 1.f / ts2, inv1 = 1.f / tsum;
    float* arow = g_attn + ((size_t)(b*HH + h)*NN + i)*NN;
#pragma unroll
    for (int x = 0; x < 8; x++) {
        int j = (x >> 1)*64 + (x & 1)*32 + lane;
        float a = pa[x] * inv2;
        arow[j] = a;
        asum[h*256 + j] = a;
        rsum[h*256 + j] = preg[x] * inv1;
    }
    __syncthreads();
    float sa = 0.f, sr = 0.f;
#pragma unroll
    for (int hh = 0; hh < 8; hh++) { sa += asum[hh*256 + tid]; sr += rsum[hh*256 + tid]; }
    out_attn_mean[(size_t)bi*NN + tid] = sa * 0.125f;
    out_raw_mean[(size_t)bi*NN + tid]  = sr * 0.125f;
}

// ---------------------------------------------------------------------------
// K3/K5: single-pass fp16 WMMA GEMM vs weights, 512 threads (16 warps, 32x32),
// double-buffered staging.
// mode 0:  g_v[m,n]  = sum_k Aext[m,k]*W[n,k]           (Aext = h_val)
// mode 1:  outExt[m,n] = resid[m,n] + sum_k g_mixed[m,k]*W[n,k]
// grid (2048, 2); tile 128x128x32.
// ---------------------------------------------------------------------------
#define WG_BUF 10240   // half elems per buffer: 2 planes x 128 rows x 40

__global__ void __launch_bounds__(512) wgemm_kernel(const float* __restrict__ Aext,
                                                    const float* __restrict__ W,
                                                    float* __restrict__ outExt,
                                                    const float* __restrict__ residExt,
                                                    int mode) {
    const float* A      = mode ? (const float*)g_mixed : Aext;
    float*       outp   = mode ? outExt : (float*)g_v;
    const float* resid  = mode ? residExt : nullptr;

    extern __shared__ __half dsm[];   // 2 * WG_BUF

    const int tid = threadIdx.x, wid = tid >> 5;
    const size_t m0 = (size_t)blockIdx.x * 128;
    const int n0 = blockIdx.y * 128;
    const int sr = tid >> 3, sk4 = (tid & 7) * 4;
    const int m_base = (wid & 3) * 32;
    const int n_base = (wid >> 2) * 32;

    FragC acc[2][2];
#pragma unroll
    for (int mt = 0; mt < 2; mt++)
#pragma unroll
        for (int nt = 0; nt < 2; nt++) wmma::fill_fragment(acc[mt][nt], 0.0f);

    float4 areg[2], breg[2];
    auto LOAD = [&](int c) {
#pragma unroll
        for (int u = 0; u < 2; u++) {
            areg[u] = *(const float4*)(A + (m0 + sr + u*64)*DD + c*32 + sk4);
            breg[u] = *(const float4*)(W + (size_t)(n0 + sr + u*64)*DD + c*32 + sk4);
        }
    };
    auto STORE = [&](int buf) {
        __half* Ah = dsm + buf*WG_BUF;
        __half* Bh = Ah + 5120;
#pragma unroll
        for (int u = 0; u < 2; u++) {
            int off = (sr + u*64)*40 + sk4;
            h_store4(Ah + off, areg[u]);
            h_store4(Bh + off, breg[u]);
        }
    };
    auto COMPUTE = [&](int buf) {
        __half* Ah = dsm + buf*WG_BUF;
        __half* Bh = Ah + 5120;
#pragma unroll
        for (int ks = 0; ks < 2; ks++) {
            HFragA  af[2];
            HFragBc bf[2];
#pragma unroll
            for (int mt = 0; mt < 2; mt++)
                wmma::load_matrix_sync(af[mt], Ah + (m_base + mt*16)*40 + ks*16, 40);
#pragma unroll
            for (int nt = 0; nt < 2; nt++)
                wmma::load_matrix_sync(bf[nt], Bh + (n_base + nt*16)*40 + ks*16, 40);
#pragma unroll
            for (int mt = 0; mt < 2; mt++)
#pragma unroll
                for (int nt = 0; nt < 2; nt++)
                    wmma::mma_sync(acc[mt][nt], af[mt], bf[nt], acc[mt][nt]);
        }
    };

    LOAD(0);
    STORE(0);
    __syncthreads();
    for (int c = 0; c < 8; c++) {
        const int cur = c & 1;
        if (c < 7) LOAD(c + 1);
        COMPUTE(cur);
        if (c < 7) STORE(cur ^ 1);
        __syncthreads();
    }

#pragma unroll
    for (int mt = 0; mt < 2; mt++) {
        size_t roff = (m0 + m_base + mt*16) * DD;
#pragma unroll
        for (int nt = 0; nt < 2; nt++) {
            size_t off = roff + n0 + n_base + nt*16;
            if (resid) {
                FragC r;
                wmma::load_matrix_sync(r, resid + off, DD, wmma::mem_row_major);
#pragma unroll
                for (int e = 0; e < r.num_elements; e++) acc[mt][nt].x[e] += r.x[e];
            }
            wmma::store_matrix_sync(outp + off, acc[mt][nt], DD, wmma::mem_row_major);
        }
    }
}

// ---------------------------------------------------------------------------
// K4: mix — per (b,h): C[i, td] = sum_j attn[b,h,i,j] * v[b,j,td'],
//     td' = (t, h*32+d), td = t*32+d within this block's 128-wide td tile.
// attn = matrix_a (row_major, k=j); V staged [j][td] = matrix_b row_major.
// grid (32 td, 2 i, 64 bh), 512 thr (16 warps of 32x32); double-buffered.
// ---------------------------------------------------------------------------
#define MX_BUF 9472   // Ph 5120 + Vh 4352

__global__ void __launch_bounds__(512) mixgemm_kernel() {
    extern __shared__ __half dsm[];   // 2 * MX_BUF

    const int tid = threadIdx.x, wid = tid >> 5;
    const int bh = blockIdx.z, b = bh >> 3, h = bh & 7;
    const int td0 = blockIdx.x * 128;
    const int i0 = blockIdx.y * 128;
    const int pr = tid >> 3, pk4 = (tid & 7) * 4;        // attn staging
    const int vjj = tid >> 5, vtd = (tid & 31) * 4;      // v staging
    const int m_base = (wid & 3) * 32;          // i
    const int n_base = (wid >> 2) * 32;         // td

    const float* Vb = g_v + (size_t)b * NN * TT * DD;
    const float* Pb = g_attn + (size_t)bh * NN * NN;

    FragC acc[2][2];
#pragma unroll
    for (int mt = 0; mt < 2; mt++)
#pragma unroll
        for (int nt = 0; nt < 2; nt++) wmma::fill_fragment(acc[mt][nt], 0.0f);

    float4 vreg[2], preg[2];
    auto LOAD = [&](int c) {
        int tdg = td0 + vtd;
        int ti = tdg >> 5, d = tdg & 31;
#pragma unroll
        for (int u = 0; u < 2; u++) {
            vreg[u] = *(const float4*)(Vb + ((size_t)(c*32 + vjj + u*16)*TT + ti)*DD + h*32 + d);
            preg[u] = *(const float4*)(Pb + (size_t)(i0 + pr + u*64)*NN + c*32 + pk4);
        }
    };
    auto STORE = [&](int buf) {
        __half* Ph = dsm + buf*MX_BUF;
        __half* Vh = Ph + 5120;
#pragma unroll
        for (int u = 0; u < 2; u++) {
            int poff = (pr + u*64)*40 + pk4;
            h_store4(Ph + poff, preg[u]);
            int voff = (vjj + u*16)*136 + vtd;
            h_store4(Vh + voff, vreg[u]);
        }
    };
    auto COMPUTE = [&](int buf) {
        __half* Ph = dsm + buf*MX_BUF;
        __half* Vh = Ph + 5120;
#pragma unroll
        for (int ks = 0; ks < 2; ks++) {
            HFragA  af[2];
            HFragBr bf[2];
#pragma unroll
            for (int mt = 0; mt < 2; mt++)
                wmma::load_matrix_sync(af[mt], Ph + (m_base + mt*16)*40 + ks*16, 40);
#pragma unroll
            for (int nt = 0; nt < 2; nt++)
                wmma::load_matrix_sync(bf[nt], Vh + ks*16*136 + n_base + nt*16, 136);
#pragma unroll
            for (int mt = 0; mt < 2; mt++)
#pragma unroll
                for (int nt = 0; nt < 2; nt++)
                    wmma::mma_sync(acc[mt][nt], af[mt], bf[nt], acc[mt][nt]);
        }
    };

    LOAD(0);
    STORE(0);
    __syncthreads();
    for (int c = 0; c < 8; c++) {
        const int cur = c & 1;
        if (c < 7) LOAD(c + 1);
        COMPUTE(cur);
        if (c < 7) STORE(cur ^ 1);
        __syncthreads();
    }

#pragma unroll
    for (int mt = 0; mt < 2; mt++) {
        int irow0 = i0 + m_base + mt*16;
#pragma unroll
        for (int nt = 0; nt < 2; nt++) {
            int tdg0 = td0 + n_base + nt*16;
            int ti = tdg0 >> 5, d0 = tdg0 & 31;
            float* p = g_mixed + ((size_t)(b*NN + irow0)*TT + ti)*DD + h*32 + d0;
            wmma::store_matrix_sync(p, acc[mt][nt], TT*DD, wmma::mem_row_major);
        }
    }
}

// ---------------------------------------------------------------------------
extern "C" void kernel_launch(void* const* d_in, const int* in_sizes, int n_in,
                              void* d_out, int out_size) {
    const float* h_val = (const float*)d_in[0];
    const float* z_map = (const float*)d_in[1];
    const float* adj   = (const float*)d_in[2];
    const float* Wq    = (const float*)d_in[3];
    const float* Wk    = (const float*)d_in[4];
    const float* Wv    = (const float*)d_in[5];
    const float* Wo    = (const float*)d_in[6];

    float* out       = (float*)d_out;
    float* attn_mean = out + (size_t)BATCH*NN*TT*DD;
    float* raw_mean  = attn_mean + (size_t)BATCH*NN*NN;

    const int attn_smem = (64*257 + 256 + 256 + 8*256 + 8*256) * (int)sizeof(float);
    const int wg_smem   = 2 * WG_BUF * (int)sizeof(__half);   // 40960
    const int mx_smem   = 2 * MX_BUF * (int)sizeof(__half);   // 37888
    cudaFuncSetAttribute(attn_kernel, cudaFuncAttributeMaxDynamicSharedMemorySize, attn_smem);
    cudaFuncSetAttribute(wgemm_kernel, cudaFuncAttributeMaxDynamicSharedMemorySize, wg_smem);
    cudaFuncSetAttribute(mixgemm_kernel, cudaFuncAttributeMaxDynamicSharedMemorySize, mx_smem);

    dim3 tgrid(8, 8, 2), tblk(32, 8);
    transpose_w_kernel<<<tgrid, tblk>>>(Wq, Wk);
    dim3 qkgrid(32, 2);
    gemm_qk_kernel<<<qkgrid, 256>>>(z_map);
    attn_kernel<<<BN, 256, attn_smem>>>(adj, attn_mean, raw_mean);
    dim3 wg((int)(M_BIG/128), 2);
    wgemm_kernel<<<wg, 512, wg_smem>>>(h_val, Wv, nullptr, nullptr, 0);
    dim3 gmix(32, 2, BATCH*HH);
    mixgemm_kernel<<<gmix, 512, mx_smem>>>();
    wgemm_kernel<<<wg, 512, wg_smem>>>(nullptr, Wo, out, h_val, 1);
}

// round 13
// speedup vs baseline: 2.1640x; 1.1192x over previous
#include <cuda_runtime.h>
#include <cuda_fp16.h>
#include <mma.h>
#include <math.h>
#include <stdint.h>

using namespace nvcuda;

// Problem constants: B=8, N=256, T=128, D=256, H=8, hd=32, TOPK=32
#define BATCH 8
#define NN    256
#define TT    128
#define DD    256
#define HH    8
#define HD    32
#define TOPK  32

#define BN    (BATCH*NN)            // 2048
#define M_BIG ((size_t)BATCH*NN*TT) // 262144

// Scratch (accessed ONLY from device code — never passed as kernel args)
__device__ float g_q[BN*DD];
__device__ float g_k[BN*DD];
__device__ float g_wt[2*DD*DD];                         // transposed Wq,Wk
__device__ __half g_w_h[2*DD*DD];                       // Wv, Wo fp16 [w][n][k]
__device__ __half g_attn_h[(size_t)BATCH*HH*NN*NN];     // 8 MB
__device__ __half g_v_h[M_BIG*DD];                      // 128 MB [b,j,t,d]
__device__ __half g_mix_h[M_BIG*DD];                    // 128 MB [m][k]

typedef wmma::fragment<wmma::matrix_a, 16, 16, 16, __half, wmma::row_major> HFragA;
typedef wmma::fragment<wmma::matrix_b, 16, 16, 16, __half, wmma::col_major> HFragBc;
typedef wmma::fragment<wmma::matrix_b, 16, 16, 16, __half, wmma::row_major> HFragBr;
typedef wmma::fragment<wmma::accumulator, 16, 16, 16, float> FragC;

// ---------------------------------------------------------------------------
// helpers
// ---------------------------------------------------------------------------
__device__ __forceinline__ void cp16(void* dst, const void* src) {
    unsigned d = (unsigned)__cvta_generic_to_shared(dst);
    asm volatile("cp.async.cg.shared.global [%0], [%1], 16;\n" :: "r"(d), "l"(src));
}
__device__ __forceinline__ void cp_commit() { asm volatile("cp.async.commit_group;\n"); }
__device__ __forceinline__ void cp_wait1()  { asm volatile("cp.async.wait_group 1;\n"); }
__device__ __forceinline__ void cp_wait0()  { asm volatile("cp.async.wait_group 0;\n"); }

__device__ __forceinline__ void h4_store(__half* p, float4 v) {
    __half2 a; a.x = __float2half_rn(v.x); a.y = __float2half_rn(v.y);
    __half2 b; b.x = __float2half_rn(v.z); b.y = __float2half_rn(v.w);
    *(__half2*)(p)     = a;
    *(__half2*)(p + 2) = b;
}

// ---------------------------------------------------------------------------
// K0a: transpose Wq, Wk  -> g_wt.  grid (8,8,2), block (32,8)
// ---------------------------------------------------------------------------
__global__ void transpose_w_kernel(const float* __restrict__ Wq, const float* __restrict__ Wk) {
    __shared__ float t[32][33];
    const int w = blockIdx.z;
    const float* W = (w == 0) ? Wq : Wk;
    float* out = g_wt + (size_t)w * DD * DD;
    const int n0 = blockIdx.x * 32, k0 = blockIdx.y * 32;
    const int tx = threadIdx.x, ty = threadIdx.y;
#pragma unroll
    for (int i = 0; i < 4; i++)
        t[ty + 8*i][tx] = W[(size_t)(n0 + ty + 8*i)*DD + k0 + tx];
    __syncthreads();
#pragma unroll
    for (int i = 0; i < 4; i++)
        out[(size_t)(k0 + ty + 8*i)*DD + n0 + tx] = t[tx][ty + 8*i];
}

// K0b: Wv, Wo -> fp16.  grid (64, 2) x 256
__global__ void convert_w_kernel(const float* __restrict__ Wv, const float* __restrict__ Wo) {
    const int w = blockIdx.y;
    const float* W = w ? Wo : Wv;
    size_t f = ((size_t)blockIdx.x*256 + threadIdx.x) * 4;
    float4 v = *(const float4*)(W + f);
    h4_store(g_w_h + (size_t)w*DD*DD + f, v);
}

// ---------------------------------------------------------------------------
// SIMT GEMM macros (qk only)
// ---------------------------------------------------------------------------
#define GEMM_DECL \
    __shared__ float As[2][16][68];  \
    __shared__ float Bs[2][16][260]; \
    const int tid = threadIdx.x;     \
    const int tx = tid & 31, ty = tid >> 5; \
    const int ar = tid >> 2;         \
    const int ak = (tid & 3) << 2;   \
    float acc[8][8];                 \
    _Pragma("unroll") for (int r = 0; r < 8; r++) \
    _Pragma("unroll") for (int c = 0; c < 8; c++) acc[r][c] = 0.f;

#define GEMM_COMPUTE(buf) \
    _Pragma("unroll") \
    for (int kk = 0; kk < 16; kk++) { \
        float a[8], bb[8]; \
        *(float4*)&a[0]  = *(const float4*)&As[buf][kk][ty*8]; \
        *(float4*)&a[4]  = *(const float4*)&As[buf][kk][ty*8 + 4]; \
        *(float4*)&bb[0] = *(const float4*)&Bs[buf][kk][tx*8]; \
        *(float4*)&bb[4] = *(const float4*)&Bs[buf][kk][tx*8 + 4]; \
        _Pragma("unroll") for (int r = 0; r < 8; r++) \
        _Pragma("unroll") for (int c = 0; c < 8; c++) acc[r][c] += a[r]*bb[c]; \
    }

// ---------------------------------------------------------------------------
// K1: q/k projection GEMM.  grid (32, 2): y=0 -> q, y=1 -> k
// ---------------------------------------------------------------------------
__global__ void __launch_bounds__(256) gemm_qk_kernel(const float* __restrict__ Z) {
    GEMM_DECL
    const int wsel = blockIdx.y;
    const float* WT = g_wt + (size_t)wsel * DD * DD;
    float* out = wsel ? g_k : g_q;
    const size_t m0 = (size_t)blockIdx.x * 64;

#pragma unroll
    for (int u = 0; u < 4; u++) {
        int f = tid + u*256; int jj = f >> 6; int cc = (f & 63) << 2;
        cp16(&Bs[0][jj][cc], WT + (size_t)jj*DD + cc);
    }
    cp_commit();
    float4 av = *(const float4*)(Z + (m0 + ar)*DD + ak);
    As[0][ak+0][ar] = av.x; As[0][ak+1][ar] = av.y;
    As[0][ak+2][ar] = av.z; As[0][ak+3][ar] = av.w;

    for (int k = 0; k < 16; k++) {
        const int cur = k & 1;
        if (k < 15) {
            av = *(const float4*)(Z + (m0 + ar)*DD + (k+1)*16 + ak);
#pragma unroll
            for (int u = 0; u < 4; u++) {
                int f = tid + u*256; int jj = f >> 6; int cc = (f & 63) << 2;
                cp16(&Bs[cur^1][jj][cc], WT + (size_t)((k+1)*16 + jj)*DD + cc);
            }
            cp_commit(); cp_wait1();
        } else cp_wait0();
        __syncthreads();
        GEMM_COMPUTE(cur)
        __syncthreads();
        if (k < 15) {
            As[cur^1][ak+0][ar] = av.x; As[cur^1][ak+1][ar] = av.y;
            As[cur^1][ak+2][ar] = av.z; As[cur^1][ak+3][ar] = av.w;
        }
    }
#pragma unroll
    for (int r = 0; r < 8; r++) {
        size_t row = m0 + ty*8 + r;
#pragma unroll
        for (int c = 0; c < 8; c += 4) {
            float4 o = make_float4(acc[r][c], acc[r][c+1], acc[r][c+2], acc[r][c+3]);
            *(float4*)(out + row*DD + tx*8 + c) = o;
        }
    }
}

// ---------------------------------------------------------------------------
// K2: attention — warp h handles head h of row (b,i). Emits fp16 attn.
// ---------------------------------------------------------------------------
#define SWAP_DESC(a, b) { float _hi = fmaxf(a, b); b = fminf(a, b); a = _hi; }

__global__ void __launch_bounds__(256) attn_kernel(const float* __restrict__ adj,
                                                   float* __restrict__ out_attn_mean,
                                                   float* __restrict__ out_raw_mean) {
    extern __shared__ float sm[];
    float* kss   = sm;
    float* logbs = kss + 64*257;
    float* qsh   = logbs + 256;
    float* asum  = qsh + 256;
    float* rsum  = asum + 8*256;

    const int bi = blockIdx.x, b = bi >> 8, i = bi & 255;
    const int tid = threadIdx.x, lane = tid & 31, h = tid >> 5;
    const float scale = 0.17677669529663687f;

    logbs[tid] = logf(fmaxf(adj[(size_t)bi*NN + tid], 1e-12f));
    qsh[tid]   = g_q[(size_t)bi*DD + tid];
    __syncthreads();

    float qreg[32];
#pragma unroll
    for (int e = 0; e < 32; e++) qreg[e] = qsh[h*HD + e];

    float sreg[8];
    for (int jt = 0; jt < 4; jt++) {
        if (jt) __syncthreads();
        const float* ksrc = g_k + ((size_t)(b*NN) + jt*64) * DD;
#pragma unroll
        for (int u = 0; u < 16; u++) {
            int f = tid + u*256;
            int r = f >> 6, c = (f & 63) << 2;
            float4 kv = *(const float4*)(ksrc + (size_t)f*4);
            kss[r*257 + c + 0] = kv.x; kss[r*257 + c + 1] = kv.y;
            kss[r*257 + c + 2] = kv.z; kss[r*257 + c + 3] = kv.w;
        }
        __syncthreads();
#pragma unroll
        for (int g = 0; g < 2; g++) {
            int jl = g*32 + lane;
            const float* kp = &kss[jl*257 + h*HD];
            float s = 0.f;
#pragma unroll
            for (int e = 0; e < 32; e++) s += qreg[e] * kp[e];
            sreg[jt*2 + g] = s * scale + logbs[jt*64 + jl];
        }
    }

    float m = sreg[0];
#pragma unroll
    for (int x = 1; x < 8; x++) m = fmaxf(m, sreg[x]);
#pragma unroll
    for (int o = 16; o; o >>= 1) m = fmaxf(m, __shfl_xor_sync(0xffffffffu, m, o));
    float preg[8], tsum = 0.f;
#pragma unroll
    for (int x = 0; x < 8; x++) { preg[x] = expf(sreg[x] - m); tsum += preg[x]; }
#pragma unroll
    for (int o = 16; o; o >>= 1) tsum += __shfl_xor_sync(0xffffffffu, tsum, o);

    float v0 = sreg[0], v1 = sreg[1], v2 = sreg[2], v3 = sreg[3];
    float v4 = sreg[4], v5 = sreg[5], v6 = sreg[6], v7 = sreg[7];
    SWAP_DESC(v0,v1) SWAP_DESC(v2,v3) SWAP_DESC(v4,v5) SWAP_DESC(v6,v7)
    SWAP_DESC(v0,v2) SWAP_DESC(v1,v3) SWAP_DESC(v4,v6) SWAP_DESC(v5,v7)
    SWAP_DESC(v1,v2) SWAP_DESC(v5,v6)
    SWAP_DESC(v0,v4) SWAP_DESC(v1,v5) SWAP_DESC(v2,v6) SWAP_DESC(v3,v7)
    SWAP_DESC(v2,v4) SWAP_DESC(v3,v5)
    SWAP_DESC(v1,v2) SWAP_DESC(v3,v4) SWAP_DESC(v5,v6)

    float kth = 0.f;
#pragma unroll 1
    for (int it = 0; it < TOPK; it++) {
        float mm = v0;
#pragma unroll
        for (int o = 16; o; o >>= 1) mm = fmaxf(mm, __shfl_xor_sync(0xffffffffu, mm, o));
        if (it == TOPK-1) { kth = mm; break; }
        unsigned bal = __ballot_sync(0xffffffffu, v0 == mm);
        if (lane == (__ffs(bal) - 1)) {
            v0 = v1; v1 = v2; v2 = v3; v3 = v4; v4 = v5; v5 = v6; v6 = v7;
            v7 = -3.402823466e38f;
        }
    }

    float pa[8], ts2 = 0.f;
#pragma unroll
    for (int x = 0; x < 8; x++) { pa[x] = (sreg[x] >= kth) ? preg[x] : 0.f; ts2 += pa[x]; }
#pragma unroll
    for (int o = 16; o; o >>= 1) ts2 += __shfl_xor_sync(0xffffffffu, ts2, o);

    const float inv2 = 1.f / ts2, inv1 = 1.f / tsum;
    const size_t arow = ((size_t)(b*HH + h)*NN + i)*NN;
#pragma unroll
    for (int x = 0; x < 8; x++) {
        int j = (x >> 1)*64 + (x & 1)*32 + lane;
        float a = pa[x] * inv2;
        g_attn_h[arow + j] = __float2half_rn(a);
        asum[h*256 + j] = a;
        rsum[h*256 + j] = preg[x] * inv1;
    }
    __syncthreads();
    float sa = 0.f, sr = 0.f;
#pragma unroll
    for (int hh = 0; hh < 8; hh++) { sa += asum[hh*256 + tid]; sr += rsum[hh*256 + tid]; }
    out_attn_mean[(size_t)bi*NN + tid] = sa * 0.125f;
    out_raw_mean[(size_t)bi*NN + tid]  = sr * 0.125f;
}

// ---------------------------------------------------------------------------
// K3/K5: fp16 WMMA GEMM vs weights. 512 thr (16 warps of 32x32).
// mode 0:  g_v_h[m,n] (fp16) = sum_k h_val[m,k]*Wv[n,k]   (A fp32->staged)
// mode 1:  outExt[m,n] = resid[m,n] + sum_k g_mix_h[m,k]*Wo[n,k]  (A cp.async)
// B always cp.async from g_w_h.  grid (2048, 2); tile 128x128x32.
// ---------------------------------------------------------------------------
#define WG_BUF 10240   // half elems per buffer: A(128x40) + B(128x40)

__global__ void __launch_bounds__(512) wgemm_kernel(const float* __restrict__ Aext,
                                                    float* __restrict__ outExt,
                                                    const float* __restrict__ residExt,
                                                    int mode) {
    const __half* Wh = g_w_h + (size_t)mode*DD*DD;

    extern __shared__ __half dsm[];   // mainloop 2*WG_BUF halves; epilogue fp32 scratch

    const int tid = threadIdx.x, wid = tid >> 5;
    const size_t m0 = (size_t)blockIdx.x * 128;
    const int n0 = blockIdx.y * 128;
    const int sr = tid >> 3, sk4 = (tid & 7) * 4;   // mode0 A staging
    const int frow = tid >> 2, fcc = (tid & 3) * 8; // cp.async fill
    const int m_base = (wid & 3) * 32;
    const int n_base = (wid >> 2) * 32;

    FragC acc[2][2];
#pragma unroll
    for (int mt = 0; mt < 2; mt++)
#pragma unroll
        for (int nt = 0; nt < 2; nt++) wmma::fill_fragment(acc[mt][nt], 0.0f);

    auto FILLB = [&](int buf, int c) {
        cp16(dsm + buf*WG_BUF + 5120 + frow*40 + fcc,
             Wh + (size_t)(n0 + frow)*DD + c*32 + fcc);
    };
    auto FILLA = [&](int buf, int c) {
        cp16(dsm + buf*WG_BUF + frow*40 + fcc,
             g_mix_h + (m0 + frow)*DD + c*32 + fcc);
    };
    float4 areg[2];
    auto LOADA = [&](int c) {
#pragma unroll
        for (int u = 0; u < 2; u++)
            areg[u] = *(const float4*)(Aext + (m0 + sr + u*64)*DD + c*32 + sk4);
    };
    auto STOREA = [&](int buf) {
#pragma unroll
        for (int u = 0; u < 2; u++) {
            __half* p = dsm + buf*WG_BUF + (sr + u*64)*40 + sk4;
            h4_store(p, areg[u]);
        }
    };
    auto COMPUTE = [&](int buf) {
        __half* Ah = dsm + buf*WG_BUF;
        __half* Bh = Ah + 5120;
#pragma unroll
        for (int ks = 0; ks < 2; ks++) {
            HFragA  af[2];
            HFragBc bf[2];
#pragma unroll
            for (int mt = 0; mt < 2; mt++)
                wmma::load_matrix_sync(af[mt], Ah + (m_base + mt*16)*40 + ks*16, 40);
#pragma unroll
            for (int nt = 0; nt < 2; nt++)
                wmma::load_matrix_sync(bf[nt], Bh + (n_base + nt*16)*40 + ks*16, 40);
#pragma unroll
            for (int mt = 0; mt < 2; mt++)
#pragma unroll
                for (int nt = 0; nt < 2; nt++)
                    wmma::mma_sync(acc[mt][nt], af[mt], bf[nt], acc[mt][nt]);
        }
    };

    if (mode == 0) {
        LOADA(0); FILLB(0, 0); cp_commit(); STOREA(0);
        for (int c = 0; c < 8; c++) {
            const int cur = c & 1;
            if (c < 7) { LOADA(c + 1); FILLB(cur ^ 1, c + 1); cp_commit(); cp_wait1(); }
            else cp_wait0();
            __syncthreads();
            COMPUTE(cur);
            if (c < 7) STOREA(cur ^ 1);
            __syncthreads();
        }
        // epilogue: stage fp32 tile, emit fp16 g_v_h
        float* cs = (float*)dsm;   // 128 x 132
#pragma unroll
        for (int mt = 0; mt < 2; mt++)
#pragma unroll
            for (int nt = 0; nt < 2; nt++)
                wmma::store_matrix_sync(cs + (m_base + mt*16)*132 + n_base + nt*16,
                                        acc[mt][nt], 132, wmma::mem_row_major);
        __syncthreads();
#pragma unroll
        for (int u = 0; u < 8; u++) {
            int f = u*512 + tid;
            int r = f >> 5, c4 = (f & 31) * 4;
            float4 v = *(const float4*)(cs + r*132 + c4);
            h4_store(g_v_h + (m0 + r)*DD + n0 + c4, v);
        }
    } else {
        FILLA(0, 0); FILLB(0, 0); cp_commit();
        for (int c = 0; c < 8; c++) {
            const int cur = c & 1;
            if (c < 7) { FILLA(cur ^ 1, c + 1); FILLB(cur ^ 1, c + 1); cp_commit(); cp_wait1(); }
            else cp_wait0();
            __syncthreads();
            COMPUTE(cur);
            __syncthreads();
        }
#pragma unroll
        for (int mt = 0; mt < 2; mt++) {
            size_t roff = (m0 + m_base + mt*16) * DD;
#pragma unroll
            for (int nt = 0; nt < 2; nt++) {
                size_t off = roff + n0 + n_base + nt*16;
                FragC r;
                wmma::load_matrix_sync(r, residExt + off, DD, wmma::mem_row_major);
#pragma unroll
                for (int e = 0; e < r.num_elements; e++) acc[mt][nt].x[e] += r.x[e];
                wmma::store_matrix_sync(outExt + off, acc[mt][nt], DD, wmma::mem_row_major);
            }
        }
    }
}

// ---------------------------------------------------------------------------
// K4: mix — per (b,h): C[i, td] = sum_j attn[b,h,i,j] * v[b,j,td'].
// Both operands fp16 via cp.async; epilogue emits fp16 g_mix_h.
// grid (32 td, 2 i, 64 bh), 512 thr; tile 128(i)x128(td)x32(j).
// ---------------------------------------------------------------------------
#define MX_BUF 9472   // P(128x40) + V(32x136)

__global__ void __launch_bounds__(512) mixgemm_kernel() {
    extern __shared__ __half dsm[];   // mainloop 2*MX_BUF; epilogue fp32 scratch

    const int tid = threadIdx.x, wid = tid >> 5;
    const int bh = blockIdx.z, b = bh >> 3, h = bh & 7;
    const int td0 = blockIdx.x * 128;
    const int i0 = blockIdx.y * 128;
    const int prow = tid >> 2, pcc = (tid & 3) * 8;
    const int vj = tid >> 4, vcc = (tid & 15) * 8;
    const int m_base = (wid & 3) * 32;          // i
    const int n_base = (wid >> 2) * 32;         // td

    const __half* Pb = g_attn_h + (size_t)bh * NN * NN;
    const __half* Vb = g_v_h + (size_t)b * NN * TT * DD;

    FragC acc[2][2];
#pragma unroll
    for (int mt = 0; mt < 2; mt++)
#pragma unroll
        for (int nt = 0; nt < 2; nt++) wmma::fill_fragment(acc[mt][nt], 0.0f);

    auto FILL = [&](int buf, int c) {
        __half* base = dsm + buf*MX_BUF;
        cp16(base + prow*40 + pcc, Pb + (size_t)(i0 + prow)*NN + c*32 + pcc);
        int tdg = td0 + vcc;
        int ti = tdg >> 5, d = tdg & 31;
        cp16(base + 5120 + vj*136 + vcc,
             Vb + ((size_t)(c*32 + vj)*TT + ti)*DD + h*32 + d);
        cp_commit();
    };
    auto COMPUTE = [&](int buf) {
        __half* Ph = dsm + buf*MX_BUF;
        __half* Vh = Ph + 5120;
#pragma unroll
        for (int ks = 0; ks < 2; ks++) {
            HFragA  af[2];
            HFragBr bf[2];
#pragma unroll
            for (int mt = 0; mt < 2; mt++)
                wmma::load_matrix_sync(af[mt], Ph + (m_base + mt*16)*40 + ks*16, 40);
#pragma unroll
            for (int nt = 0; nt < 2; nt++)
                wmma::load_matrix_sync(bf[nt], Vh + ks*16*136 + n_base + nt*16, 136);
#pragma unroll
            for (int mt = 0; mt < 2; mt++)
#pragma unroll
                for (int nt = 0; nt < 2; nt++)
                    wmma::mma_sync(acc[mt][nt], af[mt], bf[nt], acc[mt][nt]);
        }
    };

    FILL(0, 0);
    for (int c = 0; c < 8; c++) {
        const int cur = c & 1;
        if (c < 7) { FILL(cur ^ 1, c + 1); cp_wait1(); }
        else cp_wait0();
        __syncthreads();
        COMPUTE(cur);
        __syncthreads();
    }

    // epilogue: stage fp32 tile, emit fp16 g_mix_h
    float* cs = (float*)dsm;   // 128 x 132
#pragma unroll
    for (int mt = 0; mt < 2; mt++)
#pragma unroll
        for (int nt = 0; nt < 2; nt++)
            wmma::store_matrix_sync(cs + (m_base + mt*16)*132 + n_base + nt*16,
                                    acc[mt][nt], 132, wmma::mem_row_major);
    __syncthreads();
#pragma unroll
    for (int u = 0; u < 8; u++) {
        int f = u*512 + tid;
        int r = f >> 5, c4 = (f & 31) * 4;
        float4 v = *(const float4*)(cs + r*132 + c4);
        int tdg = td0 + c4;
        int ti = tdg >> 5, d = tdg & 31;
        h4_store(g_mix_h + ((size_t)(b*NN + i0 + r)*TT + ti)*DD + h*32 + d, v);
    }
}

// ---------------------------------------------------------------------------
extern "C" void kernel_launch(void* const* d_in, const int* in_sizes, int n_in,
                              void* d_out, int out_size) {
    const float* h_val = (const float*)d_in[0];
    const float* z_map = (const float*)d_in[1];
    const float* adj   = (const float*)d_in[2];
    const float* Wq    = (const float*)d_in[3];
    const float* Wk    = (const float*)d_in[4];
    const float* Wv    = (const float*)d_in[5];
    const float* Wo    = (const float*)d_in[6];

    float* out       = (float*)d_out;
    float* attn_mean = out + (size_t)BATCH*NN*TT*DD;
    float* raw_mean  = attn_mean + (size_t)BATCH*NN*NN;

    const int attn_smem = (64*257 + 256 + 256 + 8*256 + 8*256) * (int)sizeof(float);
    const int gemm_smem = 128 * 132 * (int)sizeof(float);   // 67584 >= mainloop needs
    cudaFuncSetAttribute(attn_kernel, cudaFuncAttributeMaxDynamicSharedMemorySize, attn_smem);
    cudaFuncSetAttribute(wgemm_kernel, cudaFuncAttributeMaxDynamicSharedMemorySize, gemm_smem);
    cudaFuncSetAttribute(mixgemm_kernel, cudaFuncAttributeMaxDynamicSharedMemorySize, gemm_smem);

    dim3 tgrid(8, 8, 2), tblk(32, 8);
    transpose_w_kernel<<<tgrid, tblk>>>(Wq, Wk);
    dim3 cwgrid(64, 2);
    convert_w_kernel<<<cwgrid, 256>>>(Wv, Wo);
    dim3 qkgrid(32, 2);
    gemm_qk_kernel<<<qkgrid, 256>>>(z_map);
    attn_kernel<<<BN, 256, attn_smem>>>(adj, attn_mean, raw_mean);
    dim3 wg((int)(M_BIG/128), 2);
    wgemm_kernel<<<wg, 512, gemm_smem>>>(h_val, nullptr, nullptr, 0);
    dim3 gmix(32, 2, BATCH*HH);
    mixgemm_kernel<<<gmix, 512, gemm_smem>>>();
    wgemm_kernel<<<wg, 512, gemm_smem>>>(nullptr, out, h_val, 1);
}

// round 14
// speedup vs baseline: 2.3707x; 1.0955x over previous
#include <cuda_runtime.h>
#include <cuda_fp16.h>
#include <mma.h>
#include <math.h>
#include <stdint.h>

using namespace nvcuda;

// Problem constants: B=8, N=256, T=128, D=256, H=8, hd=32, TOPK=32
#define BATCH 8
#define NN    256
#define TT    128
#define DD    256
#define HH    8
#define HD    32
#define TOPK  32

#define BN    (BATCH*NN)            // 2048
#define M_BIG ((size_t)BATCH*NN*TT) // 262144

// Scratch (accessed ONLY from device code — never passed as kernel args)
__device__ float g_q[BN*DD];
__device__ float g_k[BN*DD];
__device__ float g_wt[2*DD*DD];                         // transposed Wq,Wk
__device__ __half g_w_h[2*DD*DD];                       // Wv, Wo fp16 [w][n][k]
__device__ __half g_attn_h[(size_t)BATCH*HH*NN*NN];     // 8 MB
__device__ __half g_v_h[M_BIG*DD];                      // 128 MB [b,j,t,d]
__device__ __half g_mix_h[M_BIG*DD];                    // 128 MB [m][k]

typedef wmma::fragment<wmma::matrix_a, 16, 16, 16, __half, wmma::row_major> HFragA;
typedef wmma::fragment<wmma::matrix_b, 16, 16, 16, __half, wmma::col_major> HFragBc;
typedef wmma::fragment<wmma::matrix_b, 16, 16, 16, __half, wmma::row_major> HFragBr;
typedef wmma::fragment<wmma::accumulator, 16, 16, 16, float> FragC;

// ---------------------------------------------------------------------------
// helpers
// ---------------------------------------------------------------------------
__device__ __forceinline__ void cp16(void* dst, const void* src) {
    unsigned d = (unsigned)__cvta_generic_to_shared(dst);
    asm volatile("cp.async.cg.shared.global [%0], [%1], 16;\n" :: "r"(d), "l"(src));
}
__device__ __forceinline__ void cp_commit() { asm volatile("cp.async.commit_group;\n"); }
__device__ __forceinline__ void cp_wait1()  { asm volatile("cp.async.wait_group 1;\n"); }
__device__ __forceinline__ void cp_wait0()  { asm volatile("cp.async.wait_group 0;\n"); }

__device__ __forceinline__ void h4_store(__half* p, float4 v) {
    __half2 a; a.x = __float2half_rn(v.x); a.y = __float2half_rn(v.y);
    __half2 b; b.x = __float2half_rn(v.z); b.y = __float2half_rn(v.w);
    *(__half2*)(p)     = a;
    *(__half2*)(p + 2) = b;
}

// ---------------------------------------------------------------------------
// K0a: transpose Wq, Wk  -> g_wt.  grid (8,8,2), block (32,8)
// ---------------------------------------------------------------------------
__global__ void transpose_w_kernel(const float* __restrict__ Wq, const float* __restrict__ Wk) {
    __shared__ float t[32][33];
    const int w = blockIdx.z;
    const float* W = (w == 0) ? Wq : Wk;
    float* out = g_wt + (size_t)w * DD * DD;
    const int n0 = blockIdx.x * 32, k0 = blockIdx.y * 32;
    const int tx = threadIdx.x, ty = threadIdx.y;
#pragma unroll
    for (int i = 0; i < 4; i++)
        t[ty + 8*i][tx] = W[(size_t)(n0 + ty + 8*i)*DD + k0 + tx];
    __syncthreads();
#pragma unroll
    for (int i = 0; i < 4; i++)
        out[(size_t)(k0 + ty + 8*i)*DD + n0 + tx] = t[tx][ty + 8*i];
}

// K0b: Wv, Wo -> fp16.  grid (64, 2) x 256
__global__ void convert_w_kernel(const float* __restrict__ Wv, const float* __restrict__ Wo) {
    const int w = blockIdx.y;
    const float* W = w ? Wo : Wv;
    size_t f = ((size_t)blockIdx.x*256 + threadIdx.x) * 4;
    float4 v = *(const float4*)(W + f);
    h4_store(g_w_h + (size_t)w*DD*DD + f, v);
}

// ---------------------------------------------------------------------------
// SIMT GEMM macros (qk only)
// ---------------------------------------------------------------------------
#define GEMM_DECL \
    __shared__ float As[2][16][68];  \
    __shared__ float Bs[2][16][260]; \
    const int tid = threadIdx.x;     \
    const int tx = tid & 31, ty = tid >> 5; \
    const int ar = tid >> 2;         \
    const int ak = (tid & 3) << 2;   \
    float acc[8][8];                 \
    _Pragma("unroll") for (int r = 0; r < 8; r++) \
    _Pragma("unroll") for (int c = 0; c < 8; c++) acc[r][c] = 0.f;

#define GEMM_COMPUTE(buf) \
    _Pragma("unroll") \
    for (int kk = 0; kk < 16; kk++) { \
        float a[8], bb[8]; \
        *(float4*)&a[0]  = *(const float4*)&As[buf][kk][ty*8]; \
        *(float4*)&a[4]  = *(const float4*)&As[buf][kk][ty*8 + 4]; \
        *(float4*)&bb[0] = *(const float4*)&Bs[buf][kk][tx*8]; \
        *(float4*)&bb[4] = *(const float4*)&Bs[buf][kk][tx*8 + 4]; \
        _Pragma("unroll") for (int r = 0; r < 8; r++) \
        _Pragma("unroll") for (int c = 0; c < 8; c++) acc[r][c] += a[r]*bb[c]; \
    }

// ---------------------------------------------------------------------------
// K1: q/k projection GEMM.  grid (32, 2): y=0 -> q, y=1 -> k
// ---------------------------------------------------------------------------
__global__ void __launch_bounds__(256) gemm_qk_kernel(const float* __restrict__ Z) {
    GEMM_DECL
    const int wsel = blockIdx.y;
    const float* WT = g_wt + (size_t)wsel * DD * DD;
    float* out = wsel ? g_k : g_q;
    const size_t m0 = (size_t)blockIdx.x * 64;

#pragma unroll
    for (int u = 0; u < 4; u++) {
        int f = tid + u*256; int jj = f >> 6; int cc = (f & 63) << 2;
        cp16(&Bs[0][jj][cc], WT + (size_t)jj*DD + cc);
    }
    cp_commit();
    float4 av = *(const float4*)(Z + (m0 + ar)*DD + ak);
    As[0][ak+0][ar] = av.x; As[0][ak+1][ar] = av.y;
    As[0][ak+2][ar] = av.z; As[0][ak+3][ar] = av.w;

    for (int k = 0; k < 16; k++) {
        const int cur = k & 1;
        if (k < 15) {
            av = *(const float4*)(Z + (m0 + ar)*DD + (k+1)*16 + ak);
#pragma unroll
            for (int u = 0; u < 4; u++) {
                int f = tid + u*256; int jj = f >> 6; int cc = (f & 63) << 2;
                cp16(&Bs[cur^1][jj][cc], WT + (size_t)((k+1)*16 + jj)*DD + cc);
            }
            cp_commit(); cp_wait1();
        } else cp_wait0();
        __syncthreads();
        GEMM_COMPUTE(cur)
        __syncthreads();
        if (k < 15) {
            As[cur^1][ak+0][ar] = av.x; As[cur^1][ak+1][ar] = av.y;
            As[cur^1][ak+2][ar] = av.z; As[cur^1][ak+3][ar] = av.w;
        }
    }
#pragma unroll
    for (int r = 0; r < 8; r++) {
        size_t row = m0 + ty*8 + r;
#pragma unroll
        for (int c = 0; c < 8; c += 4) {
            float4 o = make_float4(acc[r][c], acc[r][c+1], acc[r][c+2], acc[r][c+3]);
            *(float4*)(out + row*DD + tx*8 + c) = o;
        }
    }
}

// ---------------------------------------------------------------------------
// K2: attention — warp h handles head h; block covers TWO query rows (2x
// register blocking: one kss LDS feeds both rows' FMAs).  grid 1024 x 256.
// ---------------------------------------------------------------------------
#define SWAP_DESC(a, b) { float _hi = fmaxf(a, b); b = fminf(a, b); a = _hi; }

__global__ void __launch_bounds__(256) attn_kernel(const float* __restrict__ adj,
                                                   float* __restrict__ out_attn_mean,
                                                   float* __restrict__ out_raw_mean) {
    extern __shared__ float sm[];
    float* kss   = sm;                     // 64*257
    float* logbs = kss + 64*257;           // 2*256
    float* qsh   = logbs + 512;            // 2*256
    float* asum  = qsh + 512;              // 2*8*256
    float* rsum  = asum + 4096;            // 2*8*256

    const int bi0 = blockIdx.x * 2;        // two consecutive rows, same batch
    const int b   = bi0 >> 8;
    const int tid = threadIdx.x, lane = tid & 31, h = tid >> 5;
    const float scale = 0.17677669529663687f;

#pragma unroll
    for (int r = 0; r < 2; r++) {
        logbs[r*256 + tid] = logf(fmaxf(adj[(size_t)(bi0 + r)*NN + tid], 1e-12f));
        qsh[r*256 + tid]   = g_q[(size_t)(bi0 + r)*DD + tid];
    }
    __syncthreads();

    float qreg[2][32];
#pragma unroll
    for (int r = 0; r < 2; r++)
#pragma unroll
        for (int e = 0; e < 32; e++) qreg[r][e] = qsh[r*256 + h*HD + e];

    float sreg[2][8];
    for (int jt = 0; jt < 4; jt++) {
        if (jt) __syncthreads();
        const float* ksrc = g_k + ((size_t)(b*NN) + jt*64) * DD;
#pragma unroll
        for (int u = 0; u < 16; u++) {
            int f = tid + u*256;
            int r = f >> 6, c = (f & 63) << 2;
            float4 kv = *(const float4*)(ksrc + (size_t)f*4);
            kss[r*257 + c + 0] = kv.x; kss[r*257 + c + 1] = kv.y;
            kss[r*257 + c + 2] = kv.z; kss[r*257 + c + 3] = kv.w;
        }
        __syncthreads();
#pragma unroll
        for (int g = 0; g < 2; g++) {
            int jl = g*32 + lane;
            const float* kp = &kss[jl*257 + h*HD];
            float s0 = 0.f, s1 = 0.f;
#pragma unroll
            for (int e = 0; e < 32; e++) {
                float kv = kp[e];
                s0 += qreg[0][e] * kv;
                s1 += qreg[1][e] * kv;
            }
            float lb0 = logbs[jt*64 + jl];
            float lb1 = logbs[256 + jt*64 + jl];
            sreg[0][jt*2 + g] = s0 * scale + lb0;
            sreg[1][jt*2 + g] = s1 * scale + lb1;
        }
    }

#pragma unroll 1
    for (int r = 0; r < 2; r++) {
        float m = sreg[r][0];
#pragma unroll
        for (int x = 1; x < 8; x++) m = fmaxf(m, sreg[r][x]);
#pragma unroll
        for (int o = 16; o; o >>= 1) m = fmaxf(m, __shfl_xor_sync(0xffffffffu, m, o));
        float preg[8], tsum = 0.f;
#pragma unroll
        for (int x = 0; x < 8; x++) { preg[x] = expf(sreg[r][x] - m); tsum += preg[x]; }
#pragma unroll
        for (int o = 16; o; o >>= 1) tsum += __shfl_xor_sync(0xffffffffu, tsum, o);

        float v0 = sreg[r][0], v1 = sreg[r][1], v2 = sreg[r][2], v3 = sreg[r][3];
        float v4 = sreg[r][4], v5 = sreg[r][5], v6 = sreg[r][6], v7 = sreg[r][7];
        SWAP_DESC(v0,v1) SWAP_DESC(v2,v3) SWAP_DESC(v4,v5) SWAP_DESC(v6,v7)
        SWAP_DESC(v0,v2) SWAP_DESC(v1,v3) SWAP_DESC(v4,v6) SWAP_DESC(v5,v7)
        SWAP_DESC(v1,v2) SWAP_DESC(v5,v6)
        SWAP_DESC(v0,v4) SWAP_DESC(v1,v5) SWAP_DESC(v2,v6) SWAP_DESC(v3,v7)
        SWAP_DESC(v2,v4) SWAP_DESC(v3,v5)
        SWAP_DESC(v1,v2) SWAP_DESC(v3,v4) SWAP_DESC(v5,v6)

        float kth = 0.f;
#pragma unroll 1
        for (int it = 0; it < TOPK; it++) {
            float mm = v0;
#pragma unroll
            for (int o = 16; o; o >>= 1) mm = fmaxf(mm, __shfl_xor_sync(0xffffffffu, mm, o));
            if (it == TOPK-1) { kth = mm; break; }
            unsigned bal = __ballot_sync(0xffffffffu, v0 == mm);
            if (lane == (__ffs(bal) - 1)) {
                v0 = v1; v1 = v2; v2 = v3; v3 = v4; v4 = v5; v5 = v6; v6 = v7;
                v7 = -3.402823466e38f;
            }
        }

        float pa[8], ts2 = 0.f;
#pragma unroll
        for (int x = 0; x < 8; x++) { pa[x] = (sreg[r][x] >= kth) ? preg[x] : 0.f; ts2 += pa[x]; }
#pragma unroll
        for (int o = 16; o; o >>= 1) ts2 += __shfl_xor_sync(0xffffffffu, ts2, o);

        const float inv2 = 1.f / ts2, inv1 = 1.f / tsum;
        const size_t arow = ((size_t)(b*HH + h)*NN + ((bi0 + r) & 255))*NN;
#pragma unroll
        for (int x = 0; x < 8; x++) {
            int j = (x >> 1)*64 + (x & 1)*32 + lane;
            float a = pa[x] * inv2;
            g_attn_h[arow + j] = __float2half_rn(a);
            asum[r*2048 + h*256 + j] = a;
            rsum[r*2048 + h*256 + j] = preg[x] * inv1;
        }
    }
    __syncthreads();
#pragma unroll
    for (int r = 0; r < 2; r++) {
        float sa = 0.f, sr = 0.f;
#pragma unroll
        for (int hh = 0; hh < 8; hh++) {
            sa += asum[r*2048 + hh*256 + tid];
            sr += rsum[r*2048 + hh*256 + tid];
        }
        out_attn_mean[(size_t)(bi0 + r)*NN + tid] = sa * 0.125f;
        out_raw_mean[(size_t)(bi0 + r)*NN + tid]  = sr * 0.125f;
    }
}

// ---------------------------------------------------------------------------
// K3/K5: fp16 WMMA GEMM vs weights. 512 thr (16 warps of 32x32).
// grid (2 n-tiles, 2048 m-tiles)  — n-major so same-m CTAs co-resident (A in L2).
// mode 0:  g_v_h[m,n] (fp16) = sum_k h_val[m,k]*Wv[n,k]   (A fp32->staged)
// mode 1:  outExt[m,n] = resid[m,n] + sum_k g_mix_h[m,k]*Wo[n,k]  (A cp.async)
// ---------------------------------------------------------------------------
#define WG_BUF 10240   // half elems per buffer: A(128x40) + B(128x40)

__global__ void __launch_bounds__(512) wgemm_kernel(const float* __restrict__ Aext,
                                                    float* __restrict__ outExt,
                                                    const float* __restrict__ residExt,
                                                    int mode) {
    const __half* Wh = g_w_h + (size_t)mode*DD*DD;

    extern __shared__ __half dsm[];

    const int tid = threadIdx.x, wid = tid >> 5;
    const size_t m0 = (size_t)blockIdx.y * 128;
    const int n0 = blockIdx.x * 128;
    const int sr = tid >> 3, sk4 = (tid & 7) * 4;
    const int frow = tid >> 2, fcc = (tid & 3) * 8;
    const int m_base = (wid & 3) * 32;
    const int n_base = (wid >> 2) * 32;

    FragC acc[2][2];
#pragma unroll
    for (int mt = 0; mt < 2; mt++)
#pragma unroll
        for (int nt = 0; nt < 2; nt++) wmma::fill_fragment(acc[mt][nt], 0.0f);

    auto FILLB = [&](int buf, int c) {
        cp16(dsm + buf*WG_BUF + 5120 + frow*40 + fcc,
             Wh + (size_t)(n0 + frow)*DD + c*32 + fcc);
    };
    auto FILLA = [&](int buf, int c) {
        cp16(dsm + buf*WG_BUF + frow*40 + fcc,
             g_mix_h + (m0 + frow)*DD + c*32 + fcc);
    };
    float4 areg[2];
    auto LOADA = [&](int c) {
#pragma unroll
        for (int u = 0; u < 2; u++)
            areg[u] = *(const float4*)(Aext + (m0 + sr + u*64)*DD + c*32 + sk4);
    };
    auto STOREA = [&](int buf) {
#pragma unroll
        for (int u = 0; u < 2; u++) {
            __half* p = dsm + buf*WG_BUF + (sr + u*64)*40 + sk4;
            h4_store(p, areg[u]);
        }
    };
    auto COMPUTE = [&](int buf) {
        __half* Ah = dsm + buf*WG_BUF;
        __half* Bh = Ah + 5120;
#pragma unroll
        for (int ks = 0; ks < 2; ks++) {
            HFragA  af[2];
            HFragBc bf[2];
#pragma unroll
            for (int mt = 0; mt < 2; mt++)
                wmma::load_matrix_sync(af[mt], Ah + (m_base + mt*16)*40 + ks*16, 40);
#pragma unroll
            for (int nt = 0; nt < 2; nt++)
                wmma::load_matrix_sync(bf[nt], Bh + (n_base + nt*16)*40 + ks*16, 40);
#pragma unroll
            for (int mt = 0; mt < 2; mt++)
#pragma unroll
                for (int nt = 0; nt < 2; nt++)
                    wmma::mma_sync(acc[mt][nt], af[mt], bf[nt], acc[mt][nt]);
        }
    };

    if (mode == 0) {
        LOADA(0); FILLB(0, 0); cp_commit(); STOREA(0);
        for (int c = 0; c < 8; c++) {
            const int cur = c & 1;
            if (c < 7) { LOADA(c + 1); FILLB(cur ^ 1, c + 1); cp_commit(); cp_wait1(); }
            else cp_wait0();
            __syncthreads();
            COMPUTE(cur);
            if (c < 7) STOREA(cur ^ 1);
            __syncthreads();
        }
        float* cs = (float*)dsm;   // 128 x 132
#pragma unroll
        for (int mt = 0; mt < 2; mt++)
#pragma unroll
            for (int nt = 0; nt < 2; nt++)
                wmma::store_matrix_sync(cs + (m_base + mt*16)*132 + n_base + nt*16,
                                        acc[mt][nt], 132, wmma::mem_row_major);
        __syncthreads();
#pragma unroll
        for (int u = 0; u < 8; u++) {
            int f = u*512 + tid;
            int r = f >> 5, c4 = (f & 31) * 4;
            float4 v = *(const float4*)(cs + r*132 + c4);
            h4_store(g_v_h + (m0 + r)*DD + n0 + c4, v);
        }
    } else {
        FILLA(0, 0); FILLB(0, 0); cp_commit();
        for (int c = 0; c < 8; c++) {
            const int cur = c & 1;
            if (c < 7) { FILLA(cur ^ 1, c + 1); FILLB(cur ^ 1, c + 1); cp_commit(); cp_wait1(); }
            else cp_wait0();
            __syncthreads();
            COMPUTE(cur);
            __syncthreads();
        }
#pragma unroll
        for (int mt = 0; mt < 2; mt++) {
            size_t roff = (m0 + m_base + mt*16) * DD;
#pragma unroll
            for (int nt = 0; nt < 2; nt++) {
                size_t off = roff + n0 + n_base + nt*16;
                FragC r;
                wmma::load_matrix_sync(r, residExt + off, DD, wmma::mem_row_major);
#pragma unroll
                for (int e = 0; e < r.num_elements; e++) acc[mt][nt].x[e] += r.x[e];
                wmma::store_matrix_sync(outExt + off, acc[mt][nt], DD, wmma::mem_row_major);
            }
        }
    }
}

// ---------------------------------------------------------------------------
// K4: mix — per (b,h): C[i, td] = sum_j attn[b,h,i,j] * v[b,j,td'].
// Both operands fp16 via cp.async; epilogue emits fp16 g_mix_h.
// grid (32 td, 2 i, 64 bh), 512 thr; tile 128(i)x128(td)x32(j).
// ---------------------------------------------------------------------------
#define MX_BUF 9472   // P(128x40) + V(32x136)

__global__ void __launch_bounds__(512) mixgemm_kernel() {
    extern __shared__ __half dsm[];

    const int tid = threadIdx.x, wid = tid >> 5;
    const int bh = blockIdx.z, b = bh >> 3, h = bh & 7;
    const int td0 = blockIdx.x * 128;
    const int i0 = blockIdx.y * 128;
    const int prow = tid >> 2, pcc = (tid & 3) * 8;
    const int vj = tid >> 4, vcc = (tid & 15) * 8;
    const int m_base = (wid & 3) * 32;          // i
    const int n_base = (wid >> 2) * 32;         // td

    const __half* Pb = g_attn_h + (size_t)bh * NN * NN;
    const __half* Vb = g_v_h + (size_t)b * NN * TT * DD;

    FragC acc[2][2];
#pragma unroll
    for (int mt = 0; mt < 2; mt++)
#pragma unroll
        for (int nt = 0; nt < 2; nt++) wmma::fill_fragment(acc[mt][nt], 0.0f);

    auto FILL = [&](int buf, int c) {
        __half* base = dsm + buf*MX_BUF;
        cp16(base + prow*40 + pcc, Pb + (size_t)(i0 + prow)*NN + c*32 + pcc);
        int tdg = td0 + vcc;
        int ti = tdg >> 5, d = tdg & 31;
        cp16(base + 5120 + vj*136 + vcc,
             Vb + ((size_t)(c*32 + vj)*TT + ti)*DD + h*32 + d);
        cp_commit();
    };
    auto COMPUTE = [&](int buf) {
        __half* Ph = dsm + buf*MX_BUF;
        __half* Vh = Ph + 5120;
#pragma unroll
        for (int ks = 0; ks < 2; ks++) {
            HFragA  af[2];
            HFragBr bf[2];
#pragma unroll
            for (int mt = 0; mt < 2; mt++)
                wmma::load_matrix_sync(af[mt], Ph + (m_base + mt*16)*40 + ks*16, 40);
#pragma unroll
            for (int nt = 0; nt < 2; nt++)
                wmma::load_matrix_sync(bf[nt], Vh + ks*16*136 + n_base + nt*16, 136);
#pragma unroll
            for (int mt = 0; mt < 2; mt++)
#pragma unroll
                for (int nt = 0; nt < 2; nt++)
                    wmma::mma_sync(acc[mt][nt], af[mt], bf[nt], acc[mt][nt]);
        }
    };

    FILL(0, 0);
    for (int c = 0; c < 8; c++) {
        const int cur = c & 1;
        if (c < 7) { FILL(cur ^ 1, c + 1); cp_wait1(); }
        else cp_wait0();
        __syncthreads();
        COMPUTE(cur);
        __syncthreads();
    }

    float* cs = (float*)dsm;   // 128 x 132
#pragma unroll
    for (int mt = 0; mt < 2; mt++)
#pragma unroll
        for (int nt = 0; nt < 2; nt++)
            wmma::store_matrix_sync(cs + (m_base + mt*16)*132 + n_base + nt*16,
                                    acc[mt][nt], 132, wmma::mem_row_major);
    __syncthreads();
#pragma unroll
    for (int u = 0; u < 8; u++) {
        int f = u*512 + tid;
        int r = f >> 5, c4 = (f & 31) * 4;
        float4 v = *(const float4*)(cs + r*132 + c4);
        int tdg = td0 + c4;
        int ti = tdg >> 5, d = tdg & 31;
        h4_store(g_mix_h + ((size_t)(b*NN + i0 + r)*TT + ti)*DD + h*32 + d, v);
    }
}

// ---------------------------------------------------------------------------
extern "C" void kernel_launch(void* const* d_in, const int* in_sizes, int n_in,
                              void* d_out, int out_size) {
    const float* h_val = (const float*)d_in[0];
    const float* z_map = (const float*)d_in[1];
    const float* adj   = (const float*)d_in[2];
    const float* Wq    = (const float*)d_in[3];
    const float* Wk    = (const float*)d_in[4];
    const float* Wv    = (const float*)d_in[5];
    const float* Wo    = (const float*)d_in[6];

    float* out       = (float*)d_out;
    float* attn_mean = out + (size_t)BATCH*NN*TT*DD;
    float* raw_mean  = attn_mean + (size_t)BATCH*NN*NN;

    const int attn_smem = (64*257 + 512 + 512 + 2*8*256 + 2*8*256) * (int)sizeof(float);
    const int gemm_smem = 128 * 132 * (int)sizeof(float);   // 67584
    cudaFuncSetAttribute(attn_kernel, cudaFuncAttributeMaxDynamicSharedMemorySize, attn_smem);
    cudaFuncSetAttribute(wgemm_kernel, cudaFuncAttributeMaxDynamicSharedMemorySize, gemm_smem);
    cudaFuncSetAttribute(mixgemm_kernel, cudaFuncAttributeMaxDynamicSharedMemorySize, gemm_smem);

    dim3 tgrid(8, 8, 2), tblk(32, 8);
    transpose_w_kernel<<<tgrid, tblk>>>(Wq, Wk);
    dim3 cwgrid(64, 2);
    convert_w_kernel<<<cwgrid, 256>>>(Wv, Wo);
    dim3 qkgrid(32, 2);
    gemm_qk_kernel<<<qkgrid, 256>>>(z_map);
    attn_kernel<<<BN/2, 256, attn_smem>>>(adj, attn_mean, raw_mean);
    dim3 wg(2, (int)(M_BIG/128));
    wgemm_kernel<<<wg, 512, gemm_smem>>>(h_val, nullptr, nullptr, 0);
    dim3 gmix(32, 2, BATCH*HH);
    mixgemm_kernel<<<gmix, 512, gemm_smem>>>();
    wgemm_kernel<<<wg, 512, gemm_smem>>>(nullptr, out, h_val, 1);
}

// round 15
// speedup vs baseline: 2.6401x; 1.1136x over previous
#include <cuda_runtime.h>
#include <cuda_fp16.h>
#include <mma.h>
#include <math.h>
#include <stdint.h>

using namespace nvcuda;

// Problem constants: B=8, N=256, T=128, D=256, H=8, hd=32, TOPK=32
#define BATCH 8
#define NN    256
#define TT    128
#define DD    256
#define HH    8
#define HD    32
#define TOPK  32

#define BN    (BATCH*NN)            // 2048
#define M_BIG ((size_t)BATCH*NN*TT) // 262144

// Scratch (accessed ONLY from device code — never passed as kernel args)
__device__ float g_q[BN*DD];
__device__ float g_k[BN*DD];
__device__ float g_wt[2*DD*DD];                         // transposed Wq,Wk
__device__ __half g_w_h[2*DD*DD];                       // Wv, Wo fp16 [w][n][k]
__device__ __half g_attn_h[(size_t)BATCH*HH*NN*NN];     // 8 MB
__device__ __half g_v_h[M_BIG*DD];                      // 128 MB [b,j,t,d]
__device__ __half g_mix_h[M_BIG*DD];                    // 128 MB [m][k]

typedef wmma::fragment<wmma::matrix_a, 16, 16, 16, __half, wmma::row_major> HFragA;
typedef wmma::fragment<wmma::matrix_b, 16, 16, 16, __half, wmma::col_major> HFragBc;
typedef wmma::fragment<wmma::matrix_b, 16, 16, 16, __half, wmma::row_major> HFragBr;
typedef wmma::fragment<wmma::accumulator, 16, 16, 16, float> FragC;

// ---------------------------------------------------------------------------
// helpers
// ---------------------------------------------------------------------------
__device__ __forceinline__ void cp16(void* dst, const void* src) {
    unsigned d = (unsigned)__cvta_generic_to_shared(dst);
    asm volatile("cp.async.cg.shared.global [%0], [%1], 16;\n" :: "r"(d), "l"(src));
}
__device__ __forceinline__ void cp_commit() { asm volatile("cp.async.commit_group;\n"); }
__device__ __forceinline__ void cp_wait1()  { asm volatile("cp.async.wait_group 1;\n"); }
__device__ __forceinline__ void cp_wait0()  { asm volatile("cp.async.wait_group 0;\n"); }

__device__ __forceinline__ void h4_store(__half* p, float4 v) {
    __half2 a; a.x = __float2half_rn(v.x); a.y = __float2half_rn(v.y);
    __half2 b; b.x = __float2half_rn(v.z); b.y = __float2half_rn(v.w);
    *(__half2*)(p)     = a;
    *(__half2*)(p + 2) = b;
}

// ---------------------------------------------------------------------------
// K0a: transpose Wq, Wk  -> g_wt.  grid (8,8,2), block (32,8)
// ---------------------------------------------------------------------------
__global__ void transpose_w_kernel(const float* __restrict__ Wq, const float* __restrict__ Wk) {
    __shared__ float t[32][33];
    const int w = blockIdx.z;
    const float* W = (w == 0) ? Wq : Wk;
    float* out = g_wt + (size_t)w * DD * DD;
    const int n0 = blockIdx.x * 32, k0 = blockIdx.y * 32;
    const int tx = threadIdx.x, ty = threadIdx.y;
#pragma unroll
    for (int i = 0; i < 4; i++)
        t[ty + 8*i][tx] = W[(size_t)(n0 + ty + 8*i)*DD + k0 + tx];
    __syncthreads();
#pragma unroll
    for (int i = 0; i < 4; i++)
        out[(size_t)(k0 + ty + 8*i)*DD + n0 + tx] = t[tx][ty + 8*i];
}

// K0b: Wv, Wo -> fp16.  grid (64, 2) x 256
__global__ void convert_w_kernel(const float* __restrict__ Wv, const float* __restrict__ Wo) {
    const int w = blockIdx.y;
    const float* W = w ? Wo : Wv;
    size_t f = ((size_t)blockIdx.x*256 + threadIdx.x) * 4;
    float4 v = *(const float4*)(W + f);
    h4_store(g_w_h + (size_t)w*DD*DD + f, v);
}

// ---------------------------------------------------------------------------
// SIMT GEMM macros (qk only)
// ---------------------------------------------------------------------------
#define GEMM_DECL \
    __shared__ float As[2][16][68];  \
    __shared__ float Bs[2][16][260]; \
    const int tid = threadIdx.x;     \
    const int tx = tid & 31, ty = tid >> 5; \
    const int ar = tid >> 2;         \
    const int ak = (tid & 3) << 2;   \
    float acc[8][8];                 \
    _Pragma("unroll") for (int r = 0; r < 8; r++) \
    _Pragma("unroll") for (int c = 0; c < 8; c++) acc[r][c] = 0.f;

#define GEMM_COMPUTE(buf) \
    _Pragma("unroll") \
    for (int kk = 0; kk < 16; kk++) { \
        float a[8], bb[8]; \
        *(float4*)&a[0]  = *(const float4*)&As[buf][kk][ty*8]; \
        *(float4*)&a[4]  = *(const float4*)&As[buf][kk][ty*8 + 4]; \
        *(float4*)&bb[0] = *(const float4*)&Bs[buf][kk][tx*8]; \
        *(float4*)&bb[4] = *(const float4*)&Bs[buf][kk][tx*8 + 4]; \
        _Pragma("unroll") for (int r = 0; r < 8; r++) \
        _Pragma("unroll") for (int c = 0; c < 8; c++) acc[r][c] += a[r]*bb[c]; \
    }

// ---------------------------------------------------------------------------
// K1: q/k projection GEMM.  grid (32, 2): y=0 -> q, y=1 -> k
// ---------------------------------------------------------------------------
__global__ void __launch_bounds__(256) gemm_qk_kernel(const float* __restrict__ Z) {
    GEMM_DECL
    const int wsel = blockIdx.y;
    const float* WT = g_wt + (size_t)wsel * DD * DD;
    float* out = wsel ? g_k : g_q;
    const size_t m0 = (size_t)blockIdx.x * 64;

#pragma unroll
    for (int u = 0; u < 4; u++) {
        int f = tid + u*256; int jj = f >> 6; int cc = (f & 63) << 2;
        cp16(&Bs[0][jj][cc], WT + (size_t)jj*DD + cc);
    }
    cp_commit();
    float4 av = *(const float4*)(Z + (m0 + ar)*DD + ak);
    As[0][ak+0][ar] = av.x; As[0][ak+1][ar] = av.y;
    As[0][ak+2][ar] = av.z; As[0][ak+3][ar] = av.w;

    for (int k = 0; k < 16; k++) {
        const int cur = k & 1;
        if (k < 15) {
            av = *(const float4*)(Z + (m0 + ar)*DD + (k+1)*16 + ak);
#pragma unroll
            for (int u = 0; u < 4; u++) {
                int f = tid + u*256; int jj = f >> 6; int cc = (f & 63) << 2;
                cp16(&Bs[cur^1][jj][cc], WT + (size_t)((k+1)*16 + jj)*DD + cc);
            }
            cp_commit(); cp_wait1();
        } else cp_wait0();
        __syncthreads();
        GEMM_COMPUTE(cur)
        __syncthreads();
        if (k < 15) {
            As[cur^1][ak+0][ar] = av.x; As[cur^1][ak+1][ar] = av.y;
            As[cur^1][ak+2][ar] = av.z; As[cur^1][ak+3][ar] = av.w;
        }
    }
#pragma unroll
    for (int r = 0; r < 8; r++) {
        size_t row = m0 + ty*8 + r;
#pragma unroll
        for (int c = 0; c < 8; c += 4) {
            float4 o = make_float4(acc[r][c], acc[r][c+1], acc[r][c+2], acc[r][c+3]);
            *(float4*)(out + row*DD + tx*8 + c) = o;
        }
    }
}

// ---------------------------------------------------------------------------
// K2: attention — 512 threads, warp = (row, head): 16 warps each own one
// (query-row, head) pair so the serial softmax/top-k path halves.
// Block covers TWO query rows.  grid 1024 x 512.
// ---------------------------------------------------------------------------
#define SWAP_DESC(a, b) { float _hi = fmaxf(a, b); b = fminf(a, b); a = _hi; }

__global__ void __launch_bounds__(512) attn_kernel(const float* __restrict__ adj,
                                                   float* __restrict__ out_attn_mean,
                                                   float* __restrict__ out_raw_mean) {
    extern __shared__ float sm[];
    float* kss   = sm;                     // 64*257
    float* logbs = kss + 64*257;           // 2*256
    float* qsh   = logbs + 512;            // 2*256
    float* asum  = qsh + 512;              // 2*8*256
    float* rsum  = asum + 4096;            // 2*8*256

    const int bi0 = blockIdx.x * 2;        // two consecutive rows, same batch
    const int b   = bi0 >> 8;
    const int tid = threadIdx.x, lane = tid & 31, w = tid >> 5;
    const int r = w >> 3, h = w & 7;       // warp's (row, head)
    const float scale = 0.17677669529663687f;

    {
        int r2 = tid >> 8, col = tid & 255;
        logbs[tid] = logf(fmaxf(adj[(size_t)(bi0 + r2)*NN + col], 1e-12f));
        qsh[tid]   = g_q[(size_t)(bi0 + r2)*DD + col];
    }
    __syncthreads();

    float qreg[32];
#pragma unroll
    for (int e = 0; e < 32; e++) qreg[e] = qsh[r*256 + h*HD + e];

    float sreg[8];
    for (int jt = 0; jt < 4; jt++) {
        if (jt) __syncthreads();
        const float* ksrc = g_k + ((size_t)(b*NN) + jt*64) * DD;
#pragma unroll
        for (int u = 0; u < 8; u++) {
            int f = tid + u*512;
            int rr = f >> 6, c = (f & 63) << 2;
            float4 kv = *(const float4*)(ksrc + (size_t)f*4);
            kss[rr*257 + c + 0] = kv.x; kss[rr*257 + c + 1] = kv.y;
            kss[rr*257 + c + 2] = kv.z; kss[rr*257 + c + 3] = kv.w;
        }
        __syncthreads();
#pragma unroll
        for (int g = 0; g < 2; g++) {
            int jl = g*32 + lane;
            const float* kp = &kss[jl*257 + h*HD];
            float s = 0.f;
#pragma unroll
            for (int e = 0; e < 32; e++) s += qreg[e] * kp[e];
            sreg[jt*2 + g] = s * scale + logbs[r*256 + jt*64 + jl];
        }
    }

    float m = sreg[0];
#pragma unroll
    for (int x = 1; x < 8; x++) m = fmaxf(m, sreg[x]);
#pragma unroll
    for (int o = 16; o; o >>= 1) m = fmaxf(m, __shfl_xor_sync(0xffffffffu, m, o));
    float preg[8], tsum = 0.f;
#pragma unroll
    for (int x = 0; x < 8; x++) { preg[x] = expf(sreg[x] - m); tsum += preg[x]; }
#pragma unroll
    for (int o = 16; o; o >>= 1) tsum += __shfl_xor_sync(0xffffffffu, tsum, o);

    float v0 = sreg[0], v1 = sreg[1], v2 = sreg[2], v3 = sreg[3];
    float v4 = sreg[4], v5 = sreg[5], v6 = sreg[6], v7 = sreg[7];
    SWAP_DESC(v0,v1) SWAP_DESC(v2,v3) SWAP_DESC(v4,v5) SWAP_DESC(v6,v7)
    SWAP_DESC(v0,v2) SWAP_DESC(v1,v3) SWAP_DESC(v4,v6) SWAP_DESC(v5,v7)
    SWAP_DESC(v1,v2) SWAP_DESC(v5,v6)
    SWAP_DESC(v0,v4) SWAP_DESC(v1,v5) SWAP_DESC(v2,v6) SWAP_DESC(v3,v7)
    SWAP_DESC(v2,v4) SWAP_DESC(v3,v5)
    SWAP_DESC(v1,v2) SWAP_DESC(v3,v4) SWAP_DESC(v5,v6)

    float kth = 0.f;
#pragma unroll 1
    for (int it = 0; it < TOPK; it++) {
        float mm = v0;
#pragma unroll
        for (int o = 16; o; o >>= 1) mm = fmaxf(mm, __shfl_xor_sync(0xffffffffu, mm, o));
        if (it == TOPK-1) { kth = mm; break; }
        unsigned bal = __ballot_sync(0xffffffffu, v0 == mm);
        if (lane == (__ffs(bal) - 1)) {
            v0 = v1; v1 = v2; v2 = v3; v3 = v4; v4 = v5; v5 = v6; v6 = v7;
            v7 = -3.402823466e38f;
        }
    }

    float pa[8], ts2 = 0.f;
#pragma unroll
    for (int x = 0; x < 8; x++) { pa[x] = (sreg[x] >= kth) ? preg[x] : 0.f; ts2 += pa[x]; }
#pragma unroll
    for (int o = 16; o; o >>= 1) ts2 += __shfl_xor_sync(0xffffffffu, ts2, o);

    const float inv2 = 1.f / ts2, inv1 = 1.f / tsum;
    const size_t arow = ((size_t)(b*HH + h)*NN + ((bi0 + r) & 255))*NN;
#pragma unroll
    for (int x = 0; x < 8; x++) {
        int j = (x >> 1)*64 + (x & 1)*32 + lane;
        float a = pa[x] * inv2;
        g_attn_h[arow + j] = __float2half_rn(a);
        asum[r*2048 + h*256 + j] = a;
        rsum[r*2048 + h*256 + j] = preg[x] * inv1;
    }
    __syncthreads();
    {
        int r2 = tid >> 8, col = tid & 255;
        float sa = 0.f, sr2 = 0.f;
#pragma unroll
        for (int hh = 0; hh < 8; hh++) {
            sa  += asum[r2*2048 + hh*256 + col];
            sr2 += rsum[r2*2048 + hh*256 + col];
        }
        out_attn_mean[(size_t)(bi0 + r2)*NN + col] = sa * 0.125f;
        out_raw_mean[(size_t)(bi0 + r2)*NN + col]  = sr2 * 0.125f;
    }
}

// ---------------------------------------------------------------------------
// K3/K5: fp16 WMMA GEMM vs weights. 512 thr (16 warps of 32x32), 2 CTAs/SM.
// grid (2 n-tiles, 2048 m-tiles) — n-major so same-m CTAs co-resident.
// mode 0:  g_v_h[m,n] (fp16) = sum_k h_val[m,k]*Wv[n,k]   (A fp32->staged)
// mode 1:  outExt[m,n] = resid[m,n] + sum_k g_mix_h[m,k]*Wo[n,k]  (A cp.async)
// ---------------------------------------------------------------------------
#define WG_BUF 10240   // half elems per buffer: A(128x40) + B(128x40)

__global__ void __launch_bounds__(512, 2) wgemm_kernel(const float* __restrict__ Aext,
                                                       float* __restrict__ outExt,
                                                       const float* __restrict__ residExt,
                                                       int mode) {
    const __half* Wh = g_w_h + (size_t)mode*DD*DD;

    extern __shared__ __half dsm[];

    const int tid = threadIdx.x, wid = tid >> 5;
    const size_t m0 = (size_t)blockIdx.y * 128;
    const int n0 = blockIdx.x * 128;
    const int sr = tid >> 3, sk4 = (tid & 7) * 4;
    const int frow = tid >> 2, fcc = (tid & 3) * 8;
    const int m_base = (wid & 3) * 32;
    const int n_base = (wid >> 2) * 32;

    FragC acc[2][2];
#pragma unroll
    for (int mt = 0; mt < 2; mt++)
#pragma unroll
        for (int nt = 0; nt < 2; nt++) wmma::fill_fragment(acc[mt][nt], 0.0f);

    auto FILLB = [&](int buf, int c) {
        cp16(dsm + buf*WG_BUF + 5120 + frow*40 + fcc,
             Wh + (size_t)(n0 + frow)*DD + c*32 + fcc);
    };
    auto FILLA = [&](int buf, int c) {
        cp16(dsm + buf*WG_BUF + frow*40 + fcc,
             g_mix_h + (m0 + frow)*DD + c*32 + fcc);
    };
    float4 areg[2];
    auto LOADA = [&](int c) {
#pragma unroll
        for (int u = 0; u < 2; u++)
            areg[u] = *(const float4*)(Aext + (m0 + sr + u*64)*DD + c*32 + sk4);
    };
    auto STOREA = [&](int buf) {
#pragma unroll
        for (int u = 0; u < 2; u++) {
            __half* p = dsm + buf*WG_BUF + (sr + u*64)*40 + sk4;
            h4_store(p, areg[u]);
        }
    };
    auto COMPUTE = [&](int buf) {
        __half* Ah = dsm + buf*WG_BUF;
        __half* Bh = Ah + 5120;
#pragma unroll
        for (int ks = 0; ks < 2; ks++) {
            HFragA  af[2];
            HFragBc bf[2];
#pragma unroll
            for (int mt = 0; mt < 2; mt++)
                wmma::load_matrix_sync(af[mt], Ah + (m_base + mt*16)*40 + ks*16, 40);
#pragma unroll
            for (int nt = 0; nt < 2; nt++)
                wmma::load_matrix_sync(bf[nt], Bh + (n_base + nt*16)*40 + ks*16, 40);
#pragma unroll
            for (int mt = 0; mt < 2; mt++)
#pragma unroll
                for (int nt = 0; nt < 2; nt++)
                    wmma::mma_sync(acc[mt][nt], af[mt], bf[nt], acc[mt][nt]);
        }
    };

    if (mode == 0) {
        LOADA(0); FILLB(0, 0); cp_commit(); STOREA(0);
        for (int c = 0; c < 8; c++) {
            const int cur = c & 1;
            if (c < 7) { LOADA(c + 1); FILLB(cur ^ 1, c + 1); cp_commit(); cp_wait1(); }
            else cp_wait0();
            __syncthreads();
            COMPUTE(cur);
            if (c < 7) STOREA(cur ^ 1);
            __syncthreads();
        }
        float* cs = (float*)dsm;   // 128 x 132
#pragma unroll
        for (int mt = 0; mt < 2; mt++)
#pragma unroll
            for (int nt = 0; nt < 2; nt++)
                wmma::store_matrix_sync(cs + (m_base + mt*16)*132 + n_base + nt*16,
                                        acc[mt][nt], 132, wmma::mem_row_major);
        __syncthreads();
#pragma unroll
        for (int u = 0; u < 8; u++) {
            int f = u*512 + tid;
            int r = f >> 5, c4 = (f & 31) * 4;
            float4 v = *(const float4*)(cs + r*132 + c4);
            h4_store(g_v_h + (m0 + r)*DD + n0 + c4, v);
        }
    } else {
        FILLA(0, 0); FILLB(0, 0); cp_commit();
        for (int c = 0; c < 8; c++) {
            const int cur = c & 1;
            if (c < 7) { FILLA(cur ^ 1, c + 1); FILLB(cur ^ 1, c + 1); cp_commit(); cp_wait1(); }
            else cp_wait0();
            __syncthreads();
            COMPUTE(cur);
            __syncthreads();
        }
#pragma unroll
        for (int mt = 0; mt < 2; mt++) {
            size_t roff = (m0 + m_base + mt*16) * DD;
#pragma unroll
            for (int nt = 0; nt < 2; nt++) {
                size_t off = roff + n0 + n_base + nt*16;
                FragC r;
                wmma::load_matrix_sync(r, residExt + off, DD, wmma::mem_row_major);
#pragma unroll
                for (int e = 0; e < r.num_elements; e++) acc[mt][nt].x[e] += r.x[e];
                wmma::store_matrix_sync(outExt + off, acc[mt][nt], DD, wmma::mem_row_major);
            }
        }
    }
}

// ---------------------------------------------------------------------------
// K4: mix — per (b,h): C[i, td] = sum_j attn[b,h,i,j] * v[b,j,td'].
// Both operands fp16 via cp.async; epilogue emits fp16 g_mix_h.  2 CTAs/SM.
// grid (32 td, 2 i, 64 bh), 512 thr; tile 128(i)x128(td)x32(j).
// ---------------------------------------------------------------------------
#define MX_BUF 9472   // P(128x40) + V(32x136)

__global__ void __launch_bounds__(512, 2) mixgemm_kernel() {
    extern __shared__ __half dsm[];

    const int tid = threadIdx.x, wid = tid >> 5;
    const int bh = blockIdx.z, b = bh >> 3, h = bh & 7;
    const int td0 = blockIdx.x * 128;
    const int i0 = blockIdx.y * 128;
    const int prow = tid >> 2, pcc = (tid & 3) * 8;
    const int vj = tid >> 4, vcc = (tid & 15) * 8;
    const int m_base = (wid & 3) * 32;          // i
    const int n_base = (wid >> 2) * 32;         // td

    const __half* Pb = g_attn_h + (size_t)bh * NN * NN;
    const __half* Vb = g_v_h + (size_t)b * NN * TT * DD;

    FragC acc[2][2];
#pragma unroll
    for (int mt = 0; mt < 2; mt++)
#pragma unroll
        for (int nt = 0; nt < 2; nt++) wmma::fill_fragment(acc[mt][nt], 0.0f);

    auto FILL = [&](int buf, int c) {
        __half* base = dsm + buf*MX_BUF;
        cp16(base + prow*40 + pcc, Pb + (size_t)(i0 + prow)*NN + c*32 + pcc);
        int tdg = td0 + vcc;
        int ti = tdg >> 5, d = tdg & 31;
        cp16(base + 5120 + vj*136 + vcc,
             Vb + ((size_t)(c*32 + vj)*TT + ti)*DD + h*32 + d);
        cp_commit();
    };
    auto COMPUTE = [&](int buf) {
        __half* Ph = dsm + buf*MX_BUF;
        __half* Vh = Ph + 5120;
#pragma unroll
        for (int ks = 0; ks < 2; ks++) {
            HFragA  af[2];
            HFragBr bf[2];
#pragma unroll
            for (int mt = 0; mt < 2; mt++)
                wmma::load_matrix_sync(af[mt], Ph + (m_base + mt*16)*40 + ks*16, 40);
#pragma unroll
            for (int nt = 0; nt < 2; nt++)
                wmma::load_matrix_sync(bf[nt], Vh + ks*16*136 + n_base + nt*16, 136);
#pragma unroll
            for (int mt = 0; mt < 2; mt++)
#pragma unroll
                for (int nt = 0; nt < 2; nt++)
                    wmma::mma_sync(acc[mt][nt], af[mt], bf[nt], acc[mt][nt]);
        }
    };

    FILL(0, 0);
    for (int c = 0; c < 8; c++) {
        const int cur = c & 1;
        if (c < 7) { FILL(cur ^ 1, c + 1); cp_wait1(); }
        else cp_wait0();
        __syncthreads();
        COMPUTE(cur);
        __syncthreads();
    }

    float* cs = (float*)dsm;   // 128 x 132
#pragma unroll
    for (int mt = 0; mt < 2; mt++)
#pragma unroll
        for (int nt = 0; nt < 2; nt++)
            wmma::store_matrix_sync(cs + (m_base + mt*16)*132 + n_base + nt*16,
                                    acc[mt][nt], 132, wmma::mem_row_major);
    __syncthreads();
#pragma unroll
    for (int u = 0; u < 8; u++) {
        int f = u*512 + tid;
        int r = f >> 5, c4 = (f & 31) * 4;
        float4 v = *(const float4*)(cs + r*132 + c4);
        int tdg = td0 + c4;
        int ti = tdg >> 5, d = tdg & 31;
        h4_store(g_mix_h + ((size_t)(b*NN + i0 + r)*TT + ti)*DD + h*32 + d, v);
    }
}

// ---------------------------------------------------------------------------
extern "C" void kernel_launch(void* const* d_in, const int* in_sizes, int n_in,
                              void* d_out, int out_size) {
    const float* h_val = (const float*)d_in[0];
    const float* z_map = (const float*)d_in[1];
    const float* adj   = (const float*)d_in[2];
    const float* Wq    = (const float*)d_in[3];
    const float* Wk    = (const float*)d_in[4];
    const float* Wv    = (const float*)d_in[5];
    const float* Wo    = (const float*)d_in[6];

    float* out       = (float*)d_out;
    float* attn_mean = out + (size_t)BATCH*NN*TT*DD;
    float* raw_mean  = attn_mean + (size_t)BATCH*NN*NN;

    const int attn_smem = (64*257 + 512 + 512 + 2*8*256 + 2*8*256) * (int)sizeof(float);
    const int gemm_smem = 128 * 132 * (int)sizeof(float);   // 67584
    cudaFuncSetAttribute(attn_kernel, cudaFuncAttributeMaxDynamicSharedMemorySize, attn_smem);
    cudaFuncSetAttribute(wgemm_kernel, cudaFuncAttributeMaxDynamicSharedMemorySize, gemm_smem);
    cudaFuncSetAttribute(mixgemm_kernel, cudaFuncAttributeMaxDynamicSharedMemorySize, gemm_smem);

    dim3 tgrid(8, 8, 2), tblk(32, 8);
    transpose_w_kernel<<<tgrid, tblk>>>(Wq, Wk);
    dim3 cwgrid(64, 2);
    convert_w_kernel<<<cwgrid, 256>>>(Wv, Wo);
    dim3 qkgrid(32, 2);
    gemm_qk_kernel<<<qkgrid, 256>>>(z_map);
    attn_kernel<<<BN/2, 512, attn_smem>>>(adj, attn_mean, raw_mean);
    dim3 wg(2, (int)(M_BIG/128));
    wgemm_kernel<<<wg, 512, gemm_smem>>>(h_val, nullptr, nullptr, 0);
    dim3 gmix(32, 2, BATCH*HH);
    mixgemm_kernel<<<gmix, 512, gemm_smem>>>();
    wgemm_kernel<<<wg, 512, gemm_smem>>>(nullptr, out, h_val, 1);
}

// round 16
// speedup vs baseline: 3.0741x; 1.1644x over previous
#include <cuda_runtime.h>
#include <cuda_fp16.h>
#include <mma.h>
#include <math.h>
#include <stdint.h>

using namespace nvcuda;

// Problem constants: B=8, N=256, T=128, D=256, H=8, hd=32, TOPK=32
#define BATCH 8
#define NN    256
#define TT    128
#define DD    256
#define HH    8
#define HD    32
#define TOPK  32

#define BN    (BATCH*NN)            // 2048
#define M_BIG ((size_t)BATCH*NN*TT) // 262144

// Scratch (accessed ONLY from device code — never passed as kernel args)
__device__ float g_q[BN*DD];
__device__ float g_k[BN*DD];
__device__ float g_wt[2*DD*DD];                         // transposed Wq,Wk
__device__ __half g_w_h[2*DD*DD];                       // Wv, Wo fp16 [w][n][k]
__device__ __half g_attn_h[(size_t)BATCH*HH*NN*NN];     // 8 MB
__device__ __half g_v_h[M_BIG*DD];                      // 128 MB [b,j,t,d]
__device__ __half g_mix_h[M_BIG*DD];                    // 128 MB [m][k]

typedef wmma::fragment<wmma::matrix_a, 16, 16, 16, __half, wmma::row_major> HFragA;
typedef wmma::fragment<wmma::matrix_b, 16, 16, 16, __half, wmma::col_major> HFragBc;
typedef wmma::fragment<wmma::matrix_b, 16, 16, 16, __half, wmma::row_major> HFragBr;
typedef wmma::fragment<wmma::accumulator, 16, 16, 16, float> FragC;

// ---------------------------------------------------------------------------
// helpers
// ---------------------------------------------------------------------------
__device__ __forceinline__ void cp16(void* dst, const void* src) {
    unsigned d = (unsigned)__cvta_generic_to_shared(dst);
    asm volatile("cp.async.cg.shared.global [%0], [%1], 16;\n" :: "r"(d), "l"(src));
}
__device__ __forceinline__ void cp_commit() { asm volatile("cp.async.commit_group;\n"); }
__device__ __forceinline__ void cp_wait1()  { asm volatile("cp.async.wait_group 1;\n"); }
__device__ __forceinline__ void cp_wait0()  { asm volatile("cp.async.wait_group 0;\n"); }

__device__ __forceinline__ void h4_store(__half* p, float4 v) {
    __half2 a; a.x = __float2half_rn(v.x); a.y = __float2half_rn(v.y);
    __half2 b; b.x = __float2half_rn(v.z); b.y = __float2half_rn(v.w);
    *(__half2*)(p)     = a;
    *(__half2*)(p + 2) = b;
}

// ---------------------------------------------------------------------------
// K0a: transpose Wq, Wk  -> g_wt.  grid (8,8,2), block (32,8)
// ---------------------------------------------------------------------------
__global__ void transpose_w_kernel(const float* __restrict__ Wq, const float* __restrict__ Wk) {
    __shared__ float t[32][33];
    const int w = blockIdx.z;
    const float* W = (w == 0) ? Wq : Wk;
    float* out = g_wt + (size_t)w * DD * DD;
    const int n0 = blockIdx.x * 32, k0 = blockIdx.y * 32;
    const int tx = threadIdx.x, ty = threadIdx.y;
#pragma unroll
    for (int i = 0; i < 4; i++)
        t[ty + 8*i][tx] = W[(size_t)(n0 + ty + 8*i)*DD + k0 + tx];
    __syncthreads();
#pragma unroll
    for (int i = 0; i < 4; i++)
        out[(size_t)(k0 + ty + 8*i)*DD + n0 + tx] = t[tx][ty + 8*i];
}

// K0b: Wv, Wo -> fp16.  grid (64, 2) x 256
__global__ void convert_w_kernel(const float* __restrict__ Wv, const float* __restrict__ Wo) {
    const int w = blockIdx.y;
    const float* W = w ? Wo : Wv;
    size_t f = ((size_t)blockIdx.x*256 + threadIdx.x) * 4;
    float4 v = *(const float4*)(W + f);
    h4_store(g_w_h + (size_t)w*DD*DD + f, v);
}

// ---------------------------------------------------------------------------
// K1: q/k projection GEMM, N-split for occupancy.
// grid (32 m-tiles, 4): y>>1 selects q/k, y&1 selects 128-col half.
// Tile 64(m) x 128(n) x 16(k); 256 thr; per-thread acc 4x8.
// ---------------------------------------------------------------------------
__global__ void __launch_bounds__(256) gemm_qk_kernel(const float* __restrict__ Z) {
    __shared__ float As[2][16][68];
    __shared__ float Bs[2][16][132];
    const int tid = threadIdx.x;
    const int tx = tid & 15, ty = tid >> 4;
    const int ar = tid >> 2;
    const int ak = (tid & 3) << 2;

    const int wsel = blockIdx.y >> 1;
    const int n0 = (blockIdx.y & 1) * 128;
    const float* WT = g_wt + (size_t)wsel * DD * DD;
    float* out = wsel ? g_k : g_q;
    const size_t m0 = (size_t)blockIdx.x * 64;

    float acc[4][8];
#pragma unroll
    for (int r = 0; r < 4; r++)
#pragma unroll
        for (int c = 0; c < 8; c++) acc[r][c] = 0.f;

#pragma unroll
    for (int u = 0; u < 2; u++) {
        int f = tid + u*256; int jj = f >> 5; int cc = (f & 31) << 2;
        cp16(&Bs[0][jj][cc], WT + (size_t)jj*DD + n0 + cc);
    }
    cp_commit();
    float4 av = *(const float4*)(Z + (m0 + ar)*DD + ak);
    As[0][ak+0][ar] = av.x; As[0][ak+1][ar] = av.y;
    As[0][ak+2][ar] = av.z; As[0][ak+3][ar] = av.w;

    for (int k = 0; k < 16; k++) {
        const int cur = k & 1;
        if (k < 15) {
            av = *(const float4*)(Z + (m0 + ar)*DD + (k+1)*16 + ak);
#pragma unroll
            for (int u = 0; u < 2; u++) {
                int f = tid + u*256; int jj = f >> 5; int cc = (f & 31) << 2;
                cp16(&Bs[cur^1][jj][cc], WT + (size_t)((k+1)*16 + jj)*DD + n0 + cc);
            }
            cp_commit(); cp_wait1();
        } else cp_wait0();
        __syncthreads();
#pragma unroll
        for (int kk = 0; kk < 16; kk++) {
            float a[4], bb[8];
            *(float4*)&a[0]  = *(const float4*)&As[cur][kk][ty*4];
            *(float4*)&bb[0] = *(const float4*)&Bs[cur][kk][tx*8];
            *(float4*)&bb[4] = *(const float4*)&Bs[cur][kk][tx*8 + 4];
#pragma unroll
            for (int r = 0; r < 4; r++)
#pragma unroll
                for (int c = 0; c < 8; c++) acc[r][c] += a[r]*bb[c];
        }
        __syncthreads();
        if (k < 15) {
            As[cur^1][ak+0][ar] = av.x; As[cur^1][ak+1][ar] = av.y;
            As[cur^1][ak+2][ar] = av.z; As[cur^1][ak+3][ar] = av.w;
        }
    }
#pragma unroll
    for (int r = 0; r < 4; r++) {
        size_t row = m0 + ty*4 + r;
#pragma unroll
        for (int c = 0; c < 8; c += 4) {
            float4 o = make_float4(acc[r][c], acc[r][c+1], acc[r][c+2], acc[r][c+3]);
            *(float4*)(out + row*DD + n0 + tx*8 + c) = o;
        }
    }
}

// ---------------------------------------------------------------------------
// K2: attention — 512 threads, warp = (row, head).  grid 1024 x 512.
// ---------------------------------------------------------------------------
#define SWAP_DESC(a, b) { float _hi = fmaxf(a, b); b = fminf(a, b); a = _hi; }

__global__ void __launch_bounds__(512) attn_kernel(const float* __restrict__ adj,
                                                   float* __restrict__ out_attn_mean,
                                                   float* __restrict__ out_raw_mean) {
    extern __shared__ float sm[];
    float* kss   = sm;                     // 64*257
    float* logbs = kss + 64*257;           // 2*256
    float* qsh   = logbs + 512;            // 2*256
    float* asum  = qsh + 512;              // 2*8*256
    float* rsum  = asum + 4096;            // 2*8*256

    const int bi0 = blockIdx.x * 2;
    const int b   = bi0 >> 8;
    const int tid = threadIdx.x, lane = tid & 31, w = tid >> 5;
    const int r = w >> 3, h = w & 7;
    const float scale = 0.17677669529663687f;

    {
        int r2 = tid >> 8, col = tid & 255;
        logbs[tid] = logf(fmaxf(adj[(size_t)(bi0 + r2)*NN + col], 1e-12f));
        qsh[tid]   = g_q[(size_t)(bi0 + r2)*DD + col];
    }
    __syncthreads();

    float qreg[32];
#pragma unroll
    for (int e = 0; e < 32; e++) qreg[e] = qsh[r*256 + h*HD + e];

    float sreg[8];
    for (int jt = 0; jt < 4; jt++) {
        if (jt) __syncthreads();
        const float* ksrc = g_k + ((size_t)(b*NN) + jt*64) * DD;
#pragma unroll
        for (int u = 0; u < 8; u++) {
            int f = tid + u*512;
            int rr = f >> 6, c = (f & 63) << 2;
            float4 kv = *(const float4*)(ksrc + (size_t)f*4);
            kss[rr*257 + c + 0] = kv.x; kss[rr*257 + c + 1] = kv.y;
            kss[rr*257 + c + 2] = kv.z; kss[rr*257 + c + 3] = kv.w;
        }
        __syncthreads();
#pragma unroll
        for (int g = 0; g < 2; g++) {
            int jl = g*32 + lane;
            const float* kp = &kss[jl*257 + h*HD];
            float s = 0.f;
#pragma unroll
            for (int e = 0; e < 32; e++) s += qreg[e] * kp[e];
            sreg[jt*2 + g] = s * scale + logbs[r*256 + jt*64 + jl];
        }
    }

    float m = sreg[0];
#pragma unroll
    for (int x = 1; x < 8; x++) m = fmaxf(m, sreg[x]);
#pragma unroll
    for (int o = 16; o; o >>= 1) m = fmaxf(m, __shfl_xor_sync(0xffffffffu, m, o));
    float preg[8], tsum = 0.f;
#pragma unroll
    for (int x = 0; x < 8; x++) { preg[x] = expf(sreg[x] - m); tsum += preg[x]; }
#pragma unroll
    for (int o = 16; o; o >>= 1) tsum += __shfl_xor_sync(0xffffffffu, tsum, o);

    float v0 = sreg[0], v1 = sreg[1], v2 = sreg[2], v3 = sreg[3];
    float v4 = sreg[4], v5 = sreg[5], v6 = sreg[6], v7 = sreg[7];
    SWAP_DESC(v0,v1) SWAP_DESC(v2,v3) SWAP_DESC(v4,v5) SWAP_DESC(v6,v7)
    SWAP_DESC(v0,v2) SWAP_DESC(v1,v3) SWAP_DESC(v4,v6) SWAP_DESC(v5,v7)
    SWAP_DESC(v1,v2) SWAP_DESC(v5,v6)
    SWAP_DESC(v0,v4) SWAP_DESC(v1,v5) SWAP_DESC(v2,v6) SWAP_DESC(v3,v7)
    SWAP_DESC(v2,v4) SWAP_DESC(v3,v5)
    SWAP_DESC(v1,v2) SWAP_DESC(v3,v4) SWAP_DESC(v5,v6)

    float kth = 0.f;
#pragma unroll 1
    for (int it = 0; it < TOPK; it++) {
        float mm = v0;
#pragma unroll
        for (int o = 16; o; o >>= 1) mm = fmaxf(mm, __shfl_xor_sync(0xffffffffu, mm, o));
        if (it == TOPK-1) { kth = mm; break; }
        unsigned bal = __ballot_sync(0xffffffffu, v0 == mm);
        if (lane == (__ffs(bal) - 1)) {
            v0 = v1; v1 = v2; v2 = v3; v3 = v4; v4 = v5; v5 = v6; v6 = v7;
            v7 = -3.402823466e38f;
        }
    }

    float pa[8], ts2 = 0.f;
#pragma unroll
    for (int x = 0; x < 8; x++) { pa[x] = (sreg[x] >= kth) ? preg[x] : 0.f; ts2 += pa[x]; }
#pragma unroll
    for (int o = 16; o; o >>= 1) ts2 += __shfl_xor_sync(0xffffffffu, ts2, o);

    const float inv2 = 1.f / ts2, inv1 = 1.f / tsum;
    const size_t arow = ((size_t)(b*HH + h)*NN + ((bi0 + r) & 255))*NN;
#pragma unroll
    for (int x = 0; x < 8; x++) {
        int j = (x >> 1)*64 + (x & 1)*32 + lane;
        float a = pa[x] * inv2;
        g_attn_h[arow + j] = __float2half_rn(a);
        asum[r*2048 + h*256 + j] = a;
        rsum[r*2048 + h*256 + j] = preg[x] * inv1;
    }
    __syncthreads();
    {
        int r2 = tid >> 8, col = tid & 255;
        float sa = 0.f, sr2 = 0.f;
#pragma unroll
        for (int hh = 0; hh < 8; hh++) {
            sa  += asum[r2*2048 + hh*256 + col];
            sr2 += rsum[r2*2048 + hh*256 + col];
        }
        out_attn_mean[(size_t)(bi0 + r2)*NN + col] = sa * 0.125f;
        out_raw_mean[(size_t)(bi0 + r2)*NN + col]  = sr2 * 0.125f;
    }
}

// ---------------------------------------------------------------------------
// K3/K5: fp16 WMMA GEMM vs weights. 512 thr (16 warps of 32x32), 2 CTAs/SM.
// BK=64 (4 K-chunks), rows padded to 72 halves.
// grid (2 n-tiles, 2048 m-tiles) — n-major so same-m CTAs co-resident.
// mode 0:  g_v_h[m,n] (fp16) = sum_k h_val[m,k]*Wv[n,k]   (A fp32->staged)
// mode 1:  outExt[m,n] = resid[m,n] + sum_k g_mix_h[m,k]*Wo[n,k]  (A cp.async)
// ---------------------------------------------------------------------------
#define WG_BUF 18432   // half elems per buffer: A(128x72) + B(128x72)

__global__ void __launch_bounds__(512, 2) wgemm_kernel(const float* __restrict__ Aext,
                                                       float* __restrict__ outExt,
                                                       const float* __restrict__ residExt,
                                                       int mode) {
    const __half* Wh = g_w_h + (size_t)mode*DD*DD;

    extern __shared__ __half dsm[];

    const int tid = threadIdx.x, wid = tid >> 5;
    const size_t m0 = (size_t)blockIdx.y * 128;
    const int n0 = blockIdx.x * 128;
    const int m_base = (wid & 3) * 32;
    const int n_base = (wid >> 2) * 32;

    FragC acc[2][2];
#pragma unroll
    for (int mt = 0; mt < 2; mt++)
#pragma unroll
        for (int nt = 0; nt < 2; nt++) wmma::fill_fragment(acc[mt][nt], 0.0f);

    auto FILLB = [&](int buf, int c) {
#pragma unroll
        for (int p = 0; p < 2; p++) {
            int f = tid + p*512;
            int row = f >> 3, cc = (f & 7) * 8;
            cp16(dsm + buf*WG_BUF + 9216 + row*72 + cc,
                 Wh + (size_t)(n0 + row)*DD + c*64 + cc);
        }
    };
    auto FILLA = [&](int buf, int c) {
#pragma unroll
        for (int p = 0; p < 2; p++) {
            int f = tid + p*512;
            int row = f >> 3, cc = (f & 7) * 8;
            cp16(dsm + buf*WG_BUF + row*72 + cc,
                 g_mix_h + (m0 + row)*DD + c*64 + cc);
        }
    };
    float4 areg[4];
    const int arow = tid >> 4, acol = (tid & 15) * 4;
    auto LOADA = [&](int c) {
#pragma unroll
        for (int p = 0; p < 4; p++)
            areg[p] = *(const float4*)(Aext + (m0 + arow + p*32)*DD + c*64 + acol);
    };
    auto STOREA = [&](int buf) {
#pragma unroll
        for (int p = 0; p < 4; p++)
            h4_store(dsm + buf*WG_BUF + (arow + p*32)*72 + acol, areg[p]);
    };
    auto COMPUTE = [&](int buf) {
        __half* Ah = dsm + buf*WG_BUF;
        __half* Bh = Ah + 9216;
#pragma unroll
        for (int ks = 0; ks < 4; ks++) {
            HFragA  af[2];
            HFragBc bf[2];
#pragma unroll
            for (int mt = 0; mt < 2; mt++)
                wmma::load_matrix_sync(af[mt], Ah + (m_base + mt*16)*72 + ks*16, 72);
#pragma unroll
            for (int nt = 0; nt < 2; nt++)
                wmma::load_matrix_sync(bf[nt], Bh + (n_base + nt*16)*72 + ks*16, 72);
#pragma unroll
            for (int mt = 0; mt < 2; mt++)
#pragma unroll
                for (int nt = 0; nt < 2; nt++)
                    wmma::mma_sync(acc[mt][nt], af[mt], bf[nt], acc[mt][nt]);
        }
    };

    if (mode == 0) {
        LOADA(0); FILLB(0, 0); cp_commit(); STOREA(0);
        for (int c = 0; c < 4; c++) {
            const int cur = c & 1;
            if (c < 3) { LOADA(c + 1); FILLB(cur ^ 1, c + 1); cp_commit(); cp_wait1(); }
            else cp_wait0();
            __syncthreads();
            COMPUTE(cur);
            if (c < 3) STOREA(cur ^ 1);
            __syncthreads();
        }
        float* cs = (float*)dsm;   // 128 x 132
#pragma unroll
        for (int mt = 0; mt < 2; mt++)
#pragma unroll
            for (int nt = 0; nt < 2; nt++)
                wmma::store_matrix_sync(cs + (m_base + mt*16)*132 + n_base + nt*16,
                                        acc[mt][nt], 132, wmma::mem_row_major);
        __syncthreads();
#pragma unroll
        for (int u = 0; u < 8; u++) {
            int f = u*512 + tid;
            int r = f >> 5, c4 = (f & 31) * 4;
            float4 v = *(const float4*)(cs + r*132 + c4);
            h4_store(g_v_h + (m0 + r)*DD + n0 + c4, v);
        }
    } else {
        FILLA(0, 0); FILLB(0, 0); cp_commit();
        for (int c = 0; c < 4; c++) {
            const int cur = c & 1;
            if (c < 3) { FILLA(cur ^ 1, c + 1); FILLB(cur ^ 1, c + 1); cp_commit(); cp_wait1(); }
            else cp_wait0();
            __syncthreads();
            COMPUTE(cur);
            __syncthreads();
        }
#pragma unroll
        for (int mt = 0; mt < 2; mt++) {
            size_t roff = (m0 + m_base + mt*16) * DD;
#pragma unroll
            for (int nt = 0; nt < 2; nt++) {
                size_t off = roff + n0 + n_base + nt*16;
                FragC r;
                wmma::load_matrix_sync(r, residExt + off, DD, wmma::mem_row_major);
#pragma unroll
                for (int e = 0; e < r.num_elements; e++) acc[mt][nt].x[e] += r.x[e];
                wmma::store_matrix_sync(outExt + off, acc[mt][nt], DD, wmma::mem_row_major);
            }
        }
    }
}

// ---------------------------------------------------------------------------
// K4: mix — per (b,h): C[i, td] = sum_j attn[b,h,i,j] * v[b,j,td'].
// BK(j)=64, fp16 operands via cp.async; epilogue emits fp16 g_mix_h. 2 CTAs/SM.
// grid (32 td, 2 i, 64 bh), 512 thr; tile 128(i)x128(td)x64(j).
// ---------------------------------------------------------------------------
#define MX_BUF 17920   // P(128x72) + V(64x136)

__global__ void __launch_bounds__(512, 2) mixgemm_kernel() {
    extern __shared__ __half dsm[];

    const int tid = threadIdx.x, wid = tid >> 5;
    const int bh = blockIdx.z, b = bh >> 3, h = bh & 7;
    const int td0 = blockIdx.x * 128;
    const int i0 = blockIdx.y * 128;
    const int m_base = (wid & 3) * 32;          // i
    const int n_base = (wid >> 2) * 32;         // td

    const __half* Pb = g_attn_h + (size_t)bh * NN * NN;
    const __half* Vb = g_v_h + (size_t)b * NN * TT * DD;

    FragC acc[2][2];
#pragma unroll
    for (int mt = 0; mt < 2; mt++)
#pragma unroll
        for (int nt = 0; nt < 2; nt++) wmma::fill_fragment(acc[mt][nt], 0.0f);

    auto FILL = [&](int buf, int c) {
        __half* base = dsm + buf*MX_BUF;
#pragma unroll
        for (int p = 0; p < 2; p++) {
            int f = tid + p*512;
            int prow = f >> 3, pcc = (f & 7) * 8;
            cp16(base + prow*72 + pcc, Pb + (size_t)(i0 + prow)*NN + c*64 + pcc);
            int vj = f >> 4, vcc = (f & 15) * 8;
            int tdg = td0 + vcc;
            int ti = tdg >> 5, d = tdg & 31;
            cp16(base + 9216 + vj*136 + vcc,
                 Vb + ((size_t)(c*64 + vj)*TT + ti)*DD + h*32 + d);
        }
        cp_commit();
    };
    auto COMPUTE = [&](int buf) {
        __half* Ph = dsm + buf*MX_BUF;
        __half* Vh = Ph + 9216;
#pragma unroll
        for (int ks = 0; ks < 4; ks++) {
            HFragA  af[2];
            HFragBr bf[2];
#pragma unroll
            for (int mt = 0; mt < 2; mt++)
                wmma::load_matrix_sync(af[mt], Ph + (m_base + mt*16)*72 + ks*16, 72);
#pragma unroll
            for (int nt = 0; nt < 2; nt++)
                wmma::load_matrix_sync(bf[nt], Vh + ks*16*136 + n_base + nt*16, 136);
#pragma unroll
            for (int mt = 0; mt < 2; mt++)
#pragma unroll
                for (int nt = 0; nt < 2; nt++)
                    wmma::mma_sync(acc[mt][nt], af[mt], bf[nt], acc[mt][nt]);
        }
    };

    FILL(0, 0);
    for (int c = 0; c < 4; c++) {
        const int cur = c & 1;
        if (c < 3) { FILL(cur ^ 1, c + 1); cp_wait1(); }
        else cp_wait0();
        __syncthreads();
        COMPUTE(cur);
        __syncthreads();
    }

    float* cs = (float*)dsm;   // 128 x 132
#pragma unroll
    for (int mt = 0; mt < 2; mt++)
#pragma unroll
        for (int nt = 0; nt < 2; nt++)
            wmma::store_matrix_sync(cs + (m_base + mt*16)*132 + n_base + nt*16,
                                    acc[mt][nt], 132, wmma::mem_row_major);
    __syncthreads();
#pragma unroll
    for (int u = 0; u < 8; u++) {
        int f = u*512 + tid;
        int r = f >> 5, c4 = (f & 31) * 4;
        float4 v = *(const float4*)(cs + r*132 + c4);
        int tdg = td0 + c4;
        int ti = tdg >> 5, d = tdg & 31;
        h4_store(g_mix_h + ((size_t)(b*NN + i0 + r)*TT + ti)*DD + h*32 + d, v);
    }
}

// ---------------------------------------------------------------------------
extern "C" void kernel_launch(void* const* d_in, const int* in_sizes, int n_in,
                              void* d_out, int out_size) {
    const float* h_val = (const float*)d_in[0];
    const float* z_map = (const float*)d_in[1];
    const float* adj   = (const float*)d_in[2];
    const float* Wq    = (const float*)d_in[3];
    const float* Wk    = (const float*)d_in[4];
    const float* Wv    = (const float*)d_in[5];
    const float* Wo    = (const float*)d_in[6];

    float* out       = (float*)d_out;
    float* attn_mean = out + (size_t)BATCH*NN*TT*DD;
    float* raw_mean  = attn_mean + (size_t)BATCH*NN*NN;

    const int attn_smem = (64*257 + 512 + 512 + 2*8*256 + 2*8*256) * (int)sizeof(float);
    const int wg_smem   = 2 * WG_BUF * (int)sizeof(__half);   // 73728
    const int mx_smem   = 2 * MX_BUF * (int)sizeof(__half);   // 71680
    cudaFuncSetAttribute(attn_kernel, cudaFuncAttributeMaxDynamicSharedMemorySize, attn_smem);
    cudaFuncSetAttribute(wgemm_kernel, cudaFuncAttributeMaxDynamicSharedMemorySize, wg_smem);
    cudaFuncSetAttribute(mixgemm_kernel, cudaFuncAttributeMaxDynamicSharedMemorySize, mx_smem);

    dim3 tgrid(8, 8, 2), tblk(32, 8);
    transpose_w_kernel<<<tgrid, tblk>>>(Wq, Wk);
    dim3 cwgrid(64, 2);
    convert_w_kernel<<<cwgrid, 256>>>(Wv, Wo);
    dim3 qkgrid(32, 4);
    gemm_qk_kernel<<<qkgrid, 256>>>(z_map);
    attn_kernel<<<BN/2, 512, attn_smem>>>(adj, attn_mean, raw_mean);
    dim3 wg(2, (int)(M_BIG/128));
    wgemm_kernel<<<wg, 512, wg_smem>>>(h_val, nullptr, nullptr, 0);
    dim3 gmix(32, 2, BATCH*HH);
    mixgemm_kernel<<<gmix, 512, mx_smem>>>();
    wgemm_kernel<<<wg, 512, wg_smem>>>(nullptr, out, h_val, 1);
}

// round 17
// speedup vs baseline: 3.0806x; 1.0021x over previous
#include <cuda_runtime.h>
#include <cuda_fp16.h>
#include <mma.h>
#include <math.h>
#include <stdint.h>

using namespace nvcuda;

// Problem constants: B=8, N=256, T=128, D=256, H=8, hd=32, TOPK=32
#define BATCH 8
#define NN    256
#define TT    128
#define DD    256
#define HH    8
#define HD    32
#define TOPK  32

#define BN    (BATCH*NN)            // 2048
#define M_BIG ((size_t)BATCH*NN*TT) // 262144

// Scratch (accessed ONLY from device code — never passed as kernel args)
__device__ float g_q[BN*DD];
__device__ float g_k[BN*DD];
__device__ float g_wt[2*DD*DD];                         // transposed Wq,Wk
__device__ __half g_w_h[2*DD*DD];                       // Wv, Wo fp16 [w][n][k]
__device__ __half g_attn_h[(size_t)BATCH*HH*NN*NN];     // 8 MB
__device__ __half g_v_h[M_BIG*DD];                      // 128 MB [b,j,t,d]
__device__ __half g_mix_h[M_BIG*DD];                    // 128 MB [m][k]

typedef wmma::fragment<wmma::matrix_a, 16, 16, 16, __half, wmma::row_major> HFragA;
typedef wmma::fragment<wmma::matrix_b, 16, 16, 16, __half, wmma::col_major> HFragBc;
typedef wmma::fragment<wmma::matrix_b, 16, 16, 16, __half, wmma::row_major> HFragBr;
typedef wmma::fragment<wmma::accumulator, 16, 16, 16, float> FragC;

// ---------------------------------------------------------------------------
// helpers
// ---------------------------------------------------------------------------
__device__ __forceinline__ void cp16(void* dst, const void* src) {
    unsigned d = (unsigned)__cvta_generic_to_shared(dst);
    asm volatile("cp.async.cg.shared.global [%0], [%1], 16;\n" :: "r"(d), "l"(src));
}
__device__ __forceinline__ void cp_commit() { asm volatile("cp.async.commit_group;\n"); }
__device__ __forceinline__ void cp_wait0()  { asm volatile("cp.async.wait_group 0;\n"); }

__device__ __forceinline__ void h4_store(__half* p, float4 v) {
    __half2 a; a.x = __float2half_rn(v.x); a.y = __float2half_rn(v.y);
    __half2 b; b.x = __float2half_rn(v.z); b.y = __float2half_rn(v.w);
    *(__half2*)(p)     = a;
    *(__half2*)(p + 2) = b;
}

// ---------------------------------------------------------------------------
// K0: prep weights — z<2: transpose Wq/Wk -> g_wt; z>=2: convert Wv/Wo -> fp16.
// grid (8,8,4), block (32,8)
// ---------------------------------------------------------------------------
__global__ void prep_w_kernel(const float* __restrict__ Wq, const float* __restrict__ Wk,
                              const float* __restrict__ Wv, const float* __restrict__ Wo) {
    __shared__ float t[32][33];
    const int w = blockIdx.z;
    const int tx = threadIdx.x, ty = threadIdx.y;
    if (w < 2) {
        const float* W = (w == 0) ? Wq : Wk;
        float* out = g_wt + (size_t)w * DD * DD;
        const int n0 = blockIdx.x * 32, k0 = blockIdx.y * 32;
#pragma unroll
        for (int i = 0; i < 4; i++)
            t[ty + 8*i][tx] = W[(size_t)(n0 + ty + 8*i)*DD + k0 + tx];
        __syncthreads();
#pragma unroll
        for (int i = 0; i < 4; i++)
            out[(size_t)(k0 + ty + 8*i)*DD + n0 + tx] = t[tx][ty + 8*i];
    } else {
        const float* W = (w == 2) ? Wv : Wo;
        int bid = blockIdx.y * 8 + blockIdx.x;
        int tid = ty * 32 + tx;
        size_t f = ((size_t)bid*256 + tid) * 4;
        float4 v = *(const float4*)(W + f);
        h4_store(g_w_h + (size_t)(w - 2)*DD*DD + f, v);
    }
}

// ---------------------------------------------------------------------------
// K1: q/k projection GEMM, N-split for occupancy.
// grid (32 m-tiles, 4): y>>1 selects q/k, y&1 selects 128-col half.
// Tile 64(m) x 128(n) x 16(k); 256 thr; per-thread acc 4x8.
// ---------------------------------------------------------------------------
__global__ void __launch_bounds__(256) gemm_qk_kernel(const float* __restrict__ Z) {
    __shared__ float As[2][16][68];
    __shared__ float Bs[2][16][132];
    const int tid = threadIdx.x;
    const int tx = tid & 15, ty = tid >> 4;
    const int ar = tid >> 2;
    const int ak = (tid & 3) << 2;

    const int wsel = blockIdx.y >> 1;
    const int n0 = (blockIdx.y & 1) * 128;
    const float* WT = g_wt + (size_t)wsel * DD * DD;
    float* out = wsel ? g_k : g_q;
    const size_t m0 = (size_t)blockIdx.x * 64;

    float acc[4][8];
#pragma unroll
    for (int r = 0; r < 4; r++)
#pragma unroll
        for (int c = 0; c < 8; c++) acc[r][c] = 0.f;

#pragma unroll
    for (int u = 0; u < 2; u++) {
        int f = tid + u*256; int jj = f >> 5; int cc = (f & 31) << 2;
        cp16(&Bs[0][jj][cc], WT + (size_t)jj*DD + n0 + cc);
    }
    cp_commit();
    float4 av = *(const float4*)(Z + (m0 + ar)*DD + ak);
    As[0][ak+0][ar] = av.x; As[0][ak+1][ar] = av.y;
    As[0][ak+2][ar] = av.z; As[0][ak+3][ar] = av.w;

    for (int k = 0; k < 16; k++) {
        const int cur = k & 1;
        cp_wait0();
        __syncthreads();
        if (k < 15) {
            av = *(const float4*)(Z + (m0 + ar)*DD + (k+1)*16 + ak);
#pragma unroll
            for (int u = 0; u < 2; u++) {
                int f = tid + u*256; int jj = f >> 5; int cc = (f & 31) << 2;
                cp16(&Bs[cur^1][jj][cc], WT + (size_t)((k+1)*16 + jj)*DD + n0 + cc);
            }
            cp_commit();
        }
#pragma unroll
        for (int kk = 0; kk < 16; kk++) {
            float a[4], bb[8];
            *(float4*)&a[0]  = *(const float4*)&As[cur][kk][ty*4];
            *(float4*)&bb[0] = *(const float4*)&Bs[cur][kk][tx*8];
            *(float4*)&bb[4] = *(const float4*)&Bs[cur][kk][tx*8 + 4];
#pragma unroll
            for (int r = 0; r < 4; r++)
#pragma unroll
                for (int c = 0; c < 8; c++) acc[r][c] += a[r]*bb[c];
        }
        if (k < 15) {
            As[cur^1][ak+0][ar] = av.x; As[cur^1][ak+1][ar] = av.y;
            As[cur^1][ak+2][ar] = av.z; As[cur^1][ak+3][ar] = av.w;
        }
    }
#pragma unroll
    for (int r = 0; r < 4; r++) {
        size_t row = m0 + ty*4 + r;
#pragma unroll
        for (int c = 0; c < 8; c += 4) {
            float4 o = make_float4(acc[r][c], acc[r][c+1], acc[r][c+2], acc[r][c+3]);
            *(float4*)(out + row*DD + n0 + tx*8 + c) = o;
        }
    }
}

// ---------------------------------------------------------------------------
// K2: attention — 512 threads, warp = (row, head).  grid 1024 x 512.
// ---------------------------------------------------------------------------
#define SWAP_DESC(a, b) { float _hi = fmaxf(a, b); b = fminf(a, b); a = _hi; }

__global__ void __launch_bounds__(512) attn_kernel(const float* __restrict__ adj,
                                                   float* __restrict__ out_attn_mean,
                                                   float* __restrict__ out_raw_mean) {
    extern __shared__ float sm[];
    float* kss   = sm;                     // 64*257
    float* logbs = kss + 64*257;           // 2*256
    float* qsh   = logbs + 512;            // 2*256
    float* asum  = qsh + 512;              // 2*8*256
    float* rsum  = asum + 4096;            // 2*8*256

    const int bi0 = blockIdx.x * 2;
    const int b   = bi0 >> 8;
    const int tid = threadIdx.x, lane = tid & 31, w = tid >> 5;
    const int r = w >> 3, h = w & 7;
    const float scale = 0.17677669529663687f;

    {
        int r2 = tid >> 8, col = tid & 255;
        logbs[tid] = logf(fmaxf(adj[(size_t)(bi0 + r2)*NN + col], 1e-12f));
        qsh[tid]   = g_q[(size_t)(bi0 + r2)*DD + col];
    }
    __syncthreads();

    float qreg[32];
#pragma unroll
    for (int e = 0; e < 32; e++) qreg[e] = qsh[r*256 + h*HD + e];

    float sreg[8];
    for (int jt = 0; jt < 4; jt++) {
        if (jt) __syncthreads();
        const float* ksrc = g_k + ((size_t)(b*NN) + jt*64) * DD;
#pragma unroll
        for (int u = 0; u < 8; u++) {
            int f = tid + u*512;
            int rr = f >> 6, c = (f & 63) << 2;
            float4 kv = *(const float4*)(ksrc + (size_t)f*4);
            kss[rr*257 + c + 0] = kv.x; kss[rr*257 + c + 1] = kv.y;
            kss[rr*257 + c + 2] = kv.z; kss[rr*257 + c + 3] = kv.w;
        }
        __syncthreads();
#pragma unroll
        for (int g = 0; g < 2; g++) {
            int jl = g*32 + lane;
            const float* kp = &kss[jl*257 + h*HD];
            float s = 0.f;
#pragma unroll
            for (int e = 0; e < 32; e++) s += qreg[e] * kp[e];
            sreg[jt*2 + g] = s * scale + logbs[r*256 + jt*64 + jl];
        }
    }

    float m = sreg[0];
#pragma unroll
    for (int x = 1; x < 8; x++) m = fmaxf(m, sreg[x]);
#pragma unroll
    for (int o = 16; o; o >>= 1) m = fmaxf(m, __shfl_xor_sync(0xffffffffu, m, o));
    float preg[8], tsum = 0.f;
#pragma unroll
    for (int x = 0; x < 8; x++) { preg[x] = expf(sreg[x] - m); tsum += preg[x]; }
#pragma unroll
    for (int o = 16; o; o >>= 1) tsum += __shfl_xor_sync(0xffffffffu, tsum, o);

    float v0 = sreg[0], v1 = sreg[1], v2 = sreg[2], v3 = sreg[3];
    float v4 = sreg[4], v5 = sreg[5], v6 = sreg[6], v7 = sreg[7];
    SWAP_DESC(v0,v1) SWAP_DESC(v2,v3) SWAP_DESC(v4,v5) SWAP_DESC(v6,v7)
    SWAP_DESC(v0,v2) SWAP_DESC(v1,v3) SWAP_DESC(v4,v6) SWAP_DESC(v5,v7)
    SWAP_DESC(v1,v2) SWAP_DESC(v5,v6)
    SWAP_DESC(v0,v4) SWAP_DESC(v1,v5) SWAP_DESC(v2,v6) SWAP_DESC(v3,v7)
    SWAP_DESC(v2,v4) SWAP_DESC(v3,v5)
    SWAP_DESC(v1,v2) SWAP_DESC(v3,v4) SWAP_DESC(v5,v6)

    float kth = 0.f;
#pragma unroll 1
    for (int it = 0; it < TOPK; it++) {
        float mm = v0;
#pragma unroll
        for (int o = 16; o; o >>= 1) mm = fmaxf(mm, __shfl_xor_sync(0xffffffffu, mm, o));
        if (it == TOPK-1) { kth = mm; break; }
        unsigned bal = __ballot_sync(0xffffffffu, v0 == mm);
        if (lane == (__ffs(bal) - 1)) {
            v0 = v1; v1 = v2; v2 = v3; v3 = v4; v4 = v5; v5 = v6; v6 = v7;
            v7 = -3.402823466e38f;
        }
    }

    float pa[8], ts2 = 0.f;
#pragma unroll
    for (int x = 0; x < 8; x++) { pa[x] = (sreg[x] >= kth) ? preg[x] : 0.f; ts2 += pa[x]; }
#pragma unroll
    for (int o = 16; o; o >>= 1) ts2 += __shfl_xor_sync(0xffffffffu, ts2, o);

    const float inv2 = 1.f / ts2, inv1 = 1.f / tsum;
    const size_t arow = ((size_t)(b*HH + h)*NN + ((bi0 + r) & 255))*NN;
#pragma unroll
    for (int x = 0; x < 8; x++) {
        int j = (x >> 1)*64 + (x & 1)*32 + lane;
        float a = pa[x] * inv2;
        g_attn_h[arow + j] = __float2half_rn(a);
        asum[r*2048 + h*256 + j] = a;
        rsum[r*2048 + h*256 + j] = preg[x] * inv1;
    }
    __syncthreads();
    {
        int r2 = tid >> 8, col = tid & 255;
        float sa = 0.f, sr2 = 0.f;
#pragma unroll
        for (int hh = 0; hh < 8; hh++) {
            sa  += asum[r2*2048 + hh*256 + col];
            sr2 += rsum[r2*2048 + hh*256 + col];
        }
        out_attn_mean[(size_t)(bi0 + r2)*NN + col] = sa * 0.125f;
        out_raw_mean[(size_t)(bi0 + r2)*NN + col]  = sr2 * 0.125f;
    }
}

// ---------------------------------------------------------------------------
// K3/K5: fp16 WMMA GEMM vs weights. 512 thr (16 warps of 32x32), 2 CTAs/SM.
// BK=64 (4 K-chunks), rows padded to 72 halves.  Single-sync pipeline:
//   per chunk: wait0 -> sync -> FILL(next) -> COMPUTE(cur) [-> STOREA(next)]
// grid (2 n-tiles, 2048 m-tiles) — n-major so same-m CTAs co-resident.
// mode 0:  g_v_h[m,n] (fp16) = sum_k h_val[m,k]*Wv[n,k]   (A fp32->staged)
// mode 1:  outExt[m,n] = resid[m,n] + sum_k g_mix_h[m,k]*Wo[n,k]  (A cp.async)
// ---------------------------------------------------------------------------
#define WG_BUF 18432   // half elems per buffer: A(128x72) + B(128x72)

__global__ void __launch_bounds__(512, 2) wgemm_kernel(const float* __restrict__ Aext,
                                                       float* __restrict__ outExt,
                                                       const float* __restrict__ residExt,
                                                       int mode) {
    const __half* Wh = g_w_h + (size_t)mode*DD*DD;

    extern __shared__ __half dsm[];

    const int tid = threadIdx.x, wid = tid >> 5;
    const size_t m0 = (size_t)blockIdx.y * 128;
    const int n0 = blockIdx.x * 128;
    const int m_base = (wid & 3) * 32;
    const int n_base = (wid >> 2) * 32;

    FragC acc[2][2];
#pragma unroll
    for (int mt = 0; mt < 2; mt++)
#pragma unroll
        for (int nt = 0; nt < 2; nt++) wmma::fill_fragment(acc[mt][nt], 0.0f);

    auto FILLB = [&](int buf, int c) {
#pragma unroll
        for (int p = 0; p < 2; p++) {
            int f = tid + p*512;
            int row = f >> 3, cc = (f & 7) * 8;
            cp16(dsm + buf*WG_BUF + 9216 + row*72 + cc,
                 Wh + (size_t)(n0 + row)*DD + c*64 + cc);
        }
    };
    auto FILLA = [&](int buf, int c) {
#pragma unroll
        for (int p = 0; p < 2; p++) {
            int f = tid + p*512;
            int row = f >> 3, cc = (f & 7) * 8;
            cp16(dsm + buf*WG_BUF + row*72 + cc,
                 g_mix_h + (m0 + row)*DD + c*64 + cc);
        }
    };
    float4 areg[4];
    const int arow = tid >> 4, acol = (tid & 15) * 4;
    auto LOADA = [&](int c) {
#pragma unroll
        for (int p = 0; p < 4; p++)
            areg[p] = *(const float4*)(Aext + (m0 + arow + p*32)*DD + c*64 + acol);
    };
    auto STOREA = [&](int buf) {
#pragma unroll
        for (int p = 0; p < 4; p++)
            h4_store(dsm + buf*WG_BUF + (arow + p*32)*72 + acol, areg[p]);
    };
    auto COMPUTE = [&](int buf) {
        __half* Ah = dsm + buf*WG_BUF;
        __half* Bh = Ah + 9216;
#pragma unroll
        for (int ks = 0; ks < 4; ks++) {
            HFragA  af[2];
            HFragBc bf[2];
#pragma unroll
            for (int mt = 0; mt < 2; mt++)
                wmma::load_matrix_sync(af[mt], Ah + (m_base + mt*16)*72 + ks*16, 72);
#pragma unroll
            for (int nt = 0; nt < 2; nt++)
                wmma::load_matrix_sync(bf[nt], Bh + (n_base + nt*16)*72 + ks*16, 72);
#pragma unroll
            for (int mt = 0; mt < 2; mt++)
#pragma unroll
                for (int nt = 0; nt < 2; nt++)
                    wmma::mma_sync(acc[mt][nt], af[mt], bf[nt], acc[mt][nt]);
        }
    };

    if (mode == 0) {
        LOADA(0); FILLB(0, 0); cp_commit(); STOREA(0);
        for (int c = 0; c < 4; c++) {
            const int cur = c & 1;
            cp_wait0();
            __syncthreads();
            if (c < 3) { FILLB(cur ^ 1, c + 1); cp_commit(); LOADA(c + 1); }
            COMPUTE(cur);
            if (c < 3) STOREA(cur ^ 1);
        }
        __syncthreads();   // before smem reuse as fp32 scratch
        float* cs = (float*)dsm;   // 128 x 132
#pragma unroll
        for (int mt = 0; mt < 2; mt++)
#pragma unroll
            for (int nt = 0; nt < 2; nt++)
                wmma::store_matrix_sync(cs + (m_base + mt*16)*132 + n_base + nt*16,
                                        acc[mt][nt], 132, wmma::mem_row_major);
        __syncthreads();
#pragma unroll
        for (int u = 0; u < 8; u++) {
            int f = u*512 + tid;
            int r = f >> 5, c4 = (f & 31) * 4;
            float4 v = *(const float4*)(cs + r*132 + c4);
            h4_store(g_v_h + (m0 + r)*DD + n0 + c4, v);
        }
    } else {
        FILLA(0, 0); FILLB(0, 0); cp_commit();
        for (int c = 0; c < 4; c++) {
            const int cur = c & 1;
            cp_wait0();
            __syncthreads();
            if (c < 3) { FILLA(cur ^ 1, c + 1); FILLB(cur ^ 1, c + 1); cp_commit(); }
            COMPUTE(cur);
        }
#pragma unroll
        for (int mt = 0; mt < 2; mt++) {
            size_t roff = (m0 + m_base + mt*16) * DD;
#pragma unroll
            for (int nt = 0; nt < 2; nt++) {
                size_t off = roff + n0 + n_base + nt*16;
                FragC r;
                wmma::load_matrix_sync(r, residExt + off, DD, wmma::mem_row_major);
#pragma unroll
                for (int e = 0; e < r.num_elements; e++) acc[mt][nt].x[e] += r.x[e];
                wmma::store_matrix_sync(outExt + off, acc[mt][nt], DD, wmma::mem_row_major);
            }
        }
    }
}

// ---------------------------------------------------------------------------
// K4: mix — per (b,h): C[i, td] = sum_j attn[b,h,i,j] * v[b,j,td'].
// BK(j)=64, fp16 operands via cp.async; single-sync pipeline; 2 CTAs/SM.
// grid (32 td, 2 i, 64 bh), 512 thr; tile 128(i)x128(td)x64(j).
// ---------------------------------------------------------------------------
#define MX_BUF 17920   // P(128x72) + V(64x136)

__global__ void __launch_bounds__(512, 2) mixgemm_kernel() {
    extern __shared__ __half dsm[];

    const int tid = threadIdx.x, wid = tid >> 5;
    const int bh = blockIdx.z, b = bh >> 3, h = bh & 7;
    const int td0 = blockIdx.x * 128;
    const int i0 = blockIdx.y * 128;
    const int m_base = (wid & 3) * 32;          // i
    const int n_base = (wid >> 2) * 32;         // td

    const __half* Pb = g_attn_h + (size_t)bh * NN * NN;
    const __half* Vb = g_v_h + (size_t)b * NN * TT * DD;

    FragC acc[2][2];
#pragma unroll
    for (int mt = 0; mt < 2; mt++)
#pragma unroll
        for (int nt = 0; nt < 2; nt++) wmma::fill_fragment(acc[mt][nt], 0.0f);

    auto FILL = [&](int buf, int c) {
        __half* base = dsm + buf*MX_BUF;
#pragma unroll
        for (int p = 0; p < 2; p++) {
            int f = tid + p*512;
            int prow = f >> 3, pcc = (f & 7) * 8;
            cp16(base + prow*72 + pcc, Pb + (size_t)(i0 + prow)*NN + c*64 + pcc);
            int vj = f >> 4, vcc = (f & 15) * 8;
            int tdg = td0 + vcc;
            int ti = tdg >> 5, d = tdg & 31;
            cp16(base + 9216 + vj*136 + vcc,
                 Vb + ((size_t)(c*64 + vj)*TT + ti)*DD + h*32 + d);
        }
        cp_commit();
    };
    auto COMPUTE = [&](int buf) {
        __half* Ph = dsm + buf*MX_BUF;
        __half* Vh = Ph + 9216;
#pragma unroll
        for (int ks = 0; ks < 4; ks++) {
            HFragA  af[2];
            HFragBr bf[2];
#pragma unroll
            for (int mt = 0; mt < 2; mt++)
                wmma::load_matrix_sync(af[mt], Ph + (m_base + mt*16)*72 + ks*16, 72);
#pragma unroll
            for (int nt = 0; nt < 2; nt++)
                wmma::load_matrix_sync(bf[nt], Vh + ks*16*136 + n_base + nt*16, 136);
#pragma unroll
            for (int mt = 0; mt < 2; mt++)
#pragma unroll
                for (int nt = 0; nt < 2; nt++)
                    wmma::mma_sync(acc[mt][nt], af[mt], bf[nt], acc[mt][nt]);
        }
    };

    FILL(0, 0);
    for (int c = 0; c < 4; c++) {
        const int cur = c & 1;
        cp_wait0();
        __syncthreads();
        if (c < 3) FILL(cur ^ 1, c + 1);
        COMPUTE(cur);
    }

    __syncthreads();   // before smem reuse as fp32 scratch
    float* cs = (float*)dsm;   // 128 x 132
#pragma unroll
    for (int mt = 0; mt < 2; mt++)
#pragma unroll
        for (int nt = 0; nt < 2; nt++)
            wmma::store_matrix_sync(cs + (m_base + mt*16)*132 + n_base + nt*16,
                                    acc[mt][nt], 132, wmma::mem_row_major);
    __syncthreads();
#pragma unroll
    for (int u = 0; u < 8; u++) {
        int f = u*512 + tid;
        int r = f >> 5, c4 = (f & 31) * 4;
        float4 v = *(const float4*)(cs + r*132 + c4);
        int tdg = td0 + c4;
        int ti = tdg >> 5, d = tdg & 31;
        h4_store(g_mix_h + ((size_t)(b*NN + i0 + r)*TT + ti)*DD + h*32 + d, v);
    }
}

// ---------------------------------------------------------------------------
extern "C" void kernel_launch(void* const* d_in, const int* in_sizes, int n_in,
                              void* d_out, int out_size) {
    const float* h_val = (const float*)d_in[0];
    const float* z_map = (const float*)d_in[1];
    const float* adj   = (const float*)d_in[2];
    const float* Wq    = (const float*)d_in[3];
    const float* Wk    = (const float*)d_in[4];
    const float* Wv    = (const float*)d_in[5];
    const float* Wo    = (const float*)d_in[6];

    float* out       = (float*)d_out;
    float* attn_mean = out + (size_t)BATCH*NN*TT*DD;
    float* raw_mean  = attn_mean + (size_t)BATCH*NN*NN;

    const int attn_smem = (64*257 + 512 + 512 + 2*8*256 + 2*8*256) * (int)sizeof(float);
    const int wg_smem   = 2 * WG_BUF * (int)sizeof(__half);   // 73728
    const int mx_smem   = 2 * MX_BUF * (int)sizeof(__half);   // 71680
    cudaFuncSetAttribute(attn_kernel, cudaFuncAttributeMaxDynamicSharedMemorySize, attn_smem);
    cudaFuncSetAttribute(wgemm_kernel, cudaFuncAttributeMaxDynamicSharedMemorySize, wg_smem);
    cudaFuncSetAttribute(mixgemm_kernel, cudaFuncAttributeMaxDynamicSharedMemorySize, mx_smem);

    dim3 tgrid(8, 8, 4), tblk(32, 8);
    prep_w_kernel<<<tgrid, tblk>>>(Wq, Wk, Wv, Wo);
    dim3 qkgrid(32, 4);
    gemm_qk_kernel<<<qkgrid, 256>>>(z_map);
    attn_kernel<<<BN/2, 512, attn_smem>>>(adj, attn_mean, raw_mean);
    dim3 wg(2, (int)(M_BIG/128));
    wgemm_kernel<<<wg, 512, wg_smem>>>(h_val, nullptr, nullptr, 0);
    dim3 gmix(32, 2, BATCH*HH);
    mixgemm_kernel<<<gmix, 512, mx_smem>>>();
    wgemm_kernel<<<wg, 512, wg_smem>>>(nullptr, out, h_val, 1);
}